// round 3
// baseline (speedup 1.0000x reference)
#include <cuda_runtime.h>
#include <cuda_bf16.h>
#include <math.h>

// Problem constants
#define BB 2
#define NN 2048
#define EE 1024
#define HH 16
#define DD 64
#define HD 1024            // H*D
#define MTOT 4096          // B*N

// ---------------------------------------------------------------------------
// Scratch (static device globals — no allocation allowed)
// ---------------------------------------------------------------------------
__device__ float g_Q[MTOT * HD];   // (B*N, H*D)
__device__ float g_K[MTOT * DD];   // (B*N, D)
__device__ float g_V[MTOT * DD];   // (B*N, D)
__device__ float g_Z[MTOT * HD];   // (B*N, H*D)

// ---------------------------------------------------------------------------
// Double-buffered register-blocked SGEMM body.
// C[M,N] = A[M,K] @ B[K,N] (+ bias). Row-major. Dims divisible by tiles.
// ---------------------------------------------------------------------------
template <int BM, int BN, int BK, int TM, int TN, bool BIAS>
__device__ __forceinline__
void sgemm_body(const float* __restrict__ A, const float* __restrict__ B,
                const float* __restrict__ bias, float* __restrict__ C,
                int M, int N, int K, int row0, int col0)
{
    constexpr int THREADS = (BM / TM) * (BN / TN);
    __shared__ float As[2][BK][BM];   // transposed A tiles
    __shared__ float Bs[2][BK][BN];

    const int tid = threadIdx.x;
    const int tx  = tid % (BN / TN);
    const int ty  = tid / (BN / TN);

    constexpr int A_VECS     = BM * BK / 4 / THREADS;
    constexpr int B_VECS     = BK * BN / 4 / THREADS;
    constexpr int A_ROW_VECS = BK / 4;
    constexpr int B_ROW_VECS = BN / 4;

    float acc[TM][TN];
#pragma unroll
    for (int i = 0; i < TM; i++)
#pragma unroll
        for (int j = 0; j < TN; j++) acc[i][j] = 0.0f;

    // Prologue: load tile 0 into buffer 0
#pragma unroll
    for (int i = 0; i < A_VECS; i++) {
        int idx = tid + i * THREADS;
        int r   = idx / A_ROW_VECS;
        int c   = (idx % A_ROW_VECS) * 4;
        float4 v = *(const float4*)&A[(size_t)(row0 + r) * K + c];
        As[0][c + 0][r] = v.x;
        As[0][c + 1][r] = v.y;
        As[0][c + 2][r] = v.z;
        As[0][c + 3][r] = v.w;
    }
#pragma unroll
    for (int i = 0; i < B_VECS; i++) {
        int idx = tid + i * THREADS;
        int r   = idx / B_ROW_VECS;
        int c   = (idx % B_ROW_VECS) * 4;
        *(float4*)&Bs[0][r][c] = *(const float4*)&B[(size_t)r * N + col0 + c];
    }
    __syncthreads();

    const int NTILES = K / BK;
    for (int kt = 0; kt < NTILES; kt++) {
        const int cur = kt & 1;
        float4 rA[A_VECS], rB[B_VECS];
        if (kt + 1 < NTILES) {
            const int k0 = (kt + 1) * BK;
#pragma unroll
            for (int i = 0; i < A_VECS; i++) {
                int idx = tid + i * THREADS;
                int r   = idx / A_ROW_VECS;
                int c   = (idx % A_ROW_VECS) * 4;
                rA[i] = *(const float4*)&A[(size_t)(row0 + r) * K + k0 + c];
            }
#pragma unroll
            for (int i = 0; i < B_VECS; i++) {
                int idx = tid + i * THREADS;
                int r   = idx / B_ROW_VECS;
                int c   = (idx % B_ROW_VECS) * 4;
                rB[i] = *(const float4*)&B[(size_t)(k0 + r) * N + col0 + c];
            }
        }

#pragma unroll
        for (int kk = 0; kk < BK; kk++) {
            float ra[TM], rb[TN];
#pragma unroll
            for (int i = 0; i < TM; i++) ra[i] = As[cur][kk][ty * TM + i];
#pragma unroll
            for (int j = 0; j < TN; j++) rb[j] = Bs[cur][kk][tx * TN + j];
#pragma unroll
            for (int i = 0; i < TM; i++)
#pragma unroll
                for (int j = 0; j < TN; j++)
                    acc[i][j] = fmaf(ra[i], rb[j], acc[i][j]);
        }

        if (kt + 1 < NTILES) {
            const int nxt = cur ^ 1;
#pragma unroll
            for (int i = 0; i < A_VECS; i++) {
                int idx = tid + i * THREADS;
                int r   = idx / A_ROW_VECS;
                int c   = (idx % A_ROW_VECS) * 4;
                As[nxt][c + 0][r] = rA[i].x;
                As[nxt][c + 1][r] = rA[i].y;
                As[nxt][c + 2][r] = rA[i].z;
                As[nxt][c + 3][r] = rA[i].w;
            }
#pragma unroll
            for (int i = 0; i < B_VECS; i++) {
                int idx = tid + i * THREADS;
                int r   = idx / B_ROW_VECS;
                int c   = (idx % B_ROW_VECS) * 4;
                *(float4*)&Bs[nxt][r][c] = rB[i];
            }
            __syncthreads();
        }
    }

#pragma unroll
    for (int i = 0; i < TM; i++) {
        int row = row0 + ty * TM + i;
#pragma unroll
        for (int j = 0; j < TN; j += 4) {
            int col = col0 + tx * TN + j;
            float4 v;
            v.x = acc[i][j + 0];
            v.y = acc[i][j + 1];
            v.z = acc[i][j + 2];
            v.w = acc[i][j + 3];
            if (BIAS) {
                v.x += bias[col + 0];
                v.y += bias[col + 1];
                v.z += bias[col + 2];
                v.w += bias[col + 3];
            }
            *(float4*)&C[(size_t)row * N + col] = v;
        }
    }
}

// Q projection: (4096,1024) @ (1024,1024)
__global__ __launch_bounds__(256)
void qproj_kernel(const float* __restrict__ X, const float* __restrict__ Wq,
                  float* __restrict__ Q)
{
    sgemm_body<128, 128, 16, 8, 8, false>(X, Wq, nullptr, Q, MTOT, HD, EE,
                                          blockIdx.y * 128, blockIdx.x * 128);
}

// Output projection + bias: (4096,1024) @ (1024,1024) + bo
__global__ __launch_bounds__(256)
void oproj_kernel(const float* __restrict__ Z, const float* __restrict__ Wo,
                  const float* __restrict__ bo, float* __restrict__ out)
{
    sgemm_body<128, 128, 16, 8, 8, true>(Z, Wo, bo, out, MTOT, HD, HD,
                                         blockIdx.y * 128, blockIdx.x * 128);
}

// Fused K and V projections: (4096,1024) @ (1024,64), z=0 -> K, z=1 -> V
__global__ __launch_bounds__(256)
void kvproj_kernel(const float* __restrict__ X, const float* __restrict__ Wk,
                   const float* __restrict__ Wv, float* __restrict__ K,
                   float* __restrict__ V)
{
    const float* Bm = blockIdx.z ? Wv : Wk;
    float* Cm       = blockIdx.z ? V : K;
    sgemm_body<64, 64, 16, 4, 4, false>(X, Bm, nullptr, Cm, MTOT, DD, EE,
                                        blockIdx.y * 64, 0);
}

// ---------------------------------------------------------------------------
// Causal MQA flash attention.
// 1D grid of 512 blocks, heavy-first (descending qt) so the HW block
// scheduler backfills light blocks behind heavy ones (LPT balance).
// 1 thread = 1 query row; q[64], o[64] register-resident.
// ---------------------------------------------------------------------------
#define BR 128   // query rows per block (== blockDim.x)
#define BC 64    // key rows per smem tile
#define NQT (NN / BR)   // 16 query tiles per (b,h)

__global__ __launch_bounds__(BR, 3)
void mqa_attn_kernel(const float* __restrict__ Q,
                     const float* __restrict__ K,
                     const float* __restrict__ V,
                     float* __restrict__ Z)
{
    __shared__ float Ks[BC][DD];
    __shared__ float Vs[BC][DD];

    const int wid = blockIdx.x;
    const int qt  = (NQT - 1) - (wid >> 5);   // heavy tiles dispatched first
    const int bh  = wid & 31;                 // 32 (b,h) pairs
    const int b   = bh >> 4;
    const int h   = bh & 15;
    const int tid = threadIdx.x;
    const int nq  = qt * BR + tid;            // query index within batch

    float q[DD], o[DD];
    const float* Qrow = Q + ((size_t)(b * NN + nq)) * HD + h * DD;
    const float qscale = 0.125f;              // 1/sqrt(64)
#pragma unroll
    for (int d = 0; d < DD; d++) {
        q[d] = Qrow[d] * qscale;
        o[d] = 0.0f;
    }

    float m = -1e30f, l = 0.0f;

    const int klimit = (qt + 1) * BR;         // exclusive key bound
    for (int k0 = 0; k0 < klimit; k0 += BC) {
        // cooperative tile load (contiguous BC*DD floats)
        const float4* Kt = (const float4*)(K + ((size_t)(b * NN + k0)) * DD);
        const float4* Vt = (const float4*)(V + ((size_t)(b * NN + k0)) * DD);
        float4* Ksv = (float4*)&Ks[0][0];
        float4* Vsv = (float4*)&Vs[0][0];
#pragma unroll 2
        for (int i = tid; i < BC * DD / 4; i += BR) {
            Ksv[i] = Kt[i];
            Vsv[i] = Vt[i];
        }
        __syncthreads();

        for (int j0 = 0; j0 < BC; j0 += 8) {
            float s[8];
#pragma unroll
            for (int jj = 0; jj < 8; jj++) {
                const float4* kr = (const float4*)&Ks[j0 + jj][0];
                float a0 = 0.0f, a1 = 0.0f, a2 = 0.0f, a3 = 0.0f;
#pragma unroll
                for (int d4 = 0; d4 < DD / 4; d4++) {
                    float4 kv = kr[d4];
                    a0 = fmaf(q[4 * d4 + 0], kv.x, a0);
                    a1 = fmaf(q[4 * d4 + 1], kv.y, a1);
                    a2 = fmaf(q[4 * d4 + 2], kv.z, a2);
                    a3 = fmaf(q[4 * d4 + 3], kv.w, a3);
                }
                float a = (a0 + a1) + (a2 + a3);
                s[jj] = (k0 + j0 + jj <= nq) ? a : -1e30f;
            }

            float mt = m;
#pragma unroll
            for (int jj = 0; jj < 8; jj++) mt = fmaxf(mt, s[jj]);
            const float scale = __expf(m - mt);
            float p[8];
            float lsum = 0.0f;
#pragma unroll
            for (int jj = 0; jj < 8; jj++) {
                p[jj] = __expf(s[jj] - mt);
                lsum += p[jj];
            }
            l = l * scale + lsum;
            m = mt;

#pragma unroll
            for (int d4 = 0; d4 < DD / 4; d4++) {
                float ox = o[4 * d4 + 0] * scale;
                float oy = o[4 * d4 + 1] * scale;
                float oz = o[4 * d4 + 2] * scale;
                float ow = o[4 * d4 + 3] * scale;
#pragma unroll
                for (int jj = 0; jj < 8; jj++) {
                    float4 vv = ((const float4*)&Vs[j0 + jj][0])[d4];
                    ox = fmaf(p[jj], vv.x, ox);
                    oy = fmaf(p[jj], vv.y, oy);
                    oz = fmaf(p[jj], vv.z, oz);
                    ow = fmaf(p[jj], vv.w, ow);
                }
                o[4 * d4 + 0] = ox;
                o[4 * d4 + 1] = oy;
                o[4 * d4 + 2] = oz;
                o[4 * d4 + 3] = ow;
            }
        }
        __syncthreads();
    }

    const float inv = 1.0f / l;
    float* Zrow = Z + ((size_t)(b * NN + nq)) * HD + h * DD;
#pragma unroll
    for (int d = 0; d < DD; d += 4) {
        float4 v;
        v.x = o[d + 0] * inv;
        v.y = o[d + 1] * inv;
        v.z = o[d + 2] * inv;
        v.w = o[d + 3] * inv;
        *(float4*)&Zrow[d] = v;
    }
}

// ---------------------------------------------------------------------------
// Launch
// ---------------------------------------------------------------------------
extern "C" void kernel_launch(void* const* d_in, const int* in_sizes, int n_in,
                              void* d_out, int out_size)
{
    const float* X  = (const float*)d_in[0];  // (B,N,E)
    const float* Wq = (const float*)d_in[1];  // (E, H*D)
    const float* Wk = (const float*)d_in[2];  // (E, D)
    const float* Wv = (const float*)d_in[3];  // (E, D)
    const float* Wo = (const float*)d_in[4];  // (H*D, H*D)
    const float* bo = (const float*)d_in[5];  // (H*D,)
    float* out = (float*)d_out;               // (B,N,H*D)

    float *pQ, *pK, *pV, *pZ;
    cudaGetSymbolAddress((void**)&pQ, g_Q);
    cudaGetSymbolAddress((void**)&pK, g_K);
    cudaGetSymbolAddress((void**)&pV, g_V);
    cudaGetSymbolAddress((void**)&pZ, g_Z);

    // K / V projections fused: 128 blocks instead of 2x32
    kvproj_kernel<<<dim3(1, MTOT / 64, 2), 256>>>(X, Wk, Wv, pK, pV);

    // Q projection
    qproj_kernel<<<dim3(HD / 128, MTOT / 128), 256>>>(X, Wq, pQ);

    // Causal MQA attention, heavy-first 1D grid
    mqa_attn_kernel<<<NQT * BB * HH, BR>>>(pQ, pK, pV, pZ);

    // Output projection + bias
    oproj_kernel<<<dim3(HD / 128, MTOT / 128), 256>>>(pZ, Wo, bo, out);
}

// round 4
// speedup vs baseline: 1.6069x; 1.6069x over previous
#include <cuda_runtime.h>
#include <cuda_bf16.h>
#include <math.h>

// Problem constants
#define BB 2
#define NN 2048
#define EE 1024
#define HH 16
#define DD 64
#define HD 1024            // H*D
#define MTOT 4096          // B*N

// ---------------------------------------------------------------------------
// Scratch (static device globals — no allocation allowed)
// ---------------------------------------------------------------------------
__device__ float g_Q[MTOT * HD];   // (B*N, H*D)
__device__ float g_K[MTOT * DD];   // (B*N, D)
__device__ float g_V[MTOT * DD];   // (B*N, D)
__device__ float g_Z[MTOT * HD];   // (B*N, H*D)

// ---------------------------------------------------------------------------
// Single-buffered register-blocked SGEMM (R1 known-good version).
// C[M,N] = A[M,K] @ B[K,N] (+ bias). Row-major. Dims divisible by tiles.
// ---------------------------------------------------------------------------
template <int BM, int BN, int BK, int TM, int TN, bool BIAS>
__global__ __launch_bounds__((BM / TM) * (BN / TN))
void sgemm_kernel(const float* __restrict__ A, const float* __restrict__ B,
                  const float* __restrict__ bias, float* __restrict__ C,
                  int M, int N, int K,
                  const float* __restrict__ B2, float* __restrict__ C2)
{
    constexpr int THREADS = (BM / TM) * (BN / TN);
    __shared__ float As[BK][BM];   // transposed A tile
    __shared__ float Bs[BK][BN];

    // Optional second-output dispatch (fused KV): z selects B/C pair.
    if (B2 != nullptr && blockIdx.z) { B = B2; C = C2; }

    const int tid  = threadIdx.x;
    const int tx   = tid % (BN / TN);
    const int ty   = tid / (BN / TN);
    const int row0 = blockIdx.y * BM;
    const int col0 = blockIdx.x * BN;

    float acc[TM][TN];
#pragma unroll
    for (int i = 0; i < TM; i++)
#pragma unroll
        for (int j = 0; j < TN; j++) acc[i][j] = 0.0f;

    constexpr int A_VECS     = BM * BK / 4 / THREADS;
    constexpr int B_VECS     = BK * BN / 4 / THREADS;
    constexpr int A_ROW_VECS = BK / 4;
    constexpr int B_ROW_VECS = BN / 4;

    for (int k0 = 0; k0 < K; k0 += BK) {
#pragma unroll
        for (int i = 0; i < A_VECS; i++) {
            int idx = tid + i * THREADS;
            int r   = idx / A_ROW_VECS;
            int c   = (idx % A_ROW_VECS) * 4;
            float4 v = *(const float4*)&A[(size_t)(row0 + r) * K + k0 + c];
            As[c + 0][r] = v.x;
            As[c + 1][r] = v.y;
            As[c + 2][r] = v.z;
            As[c + 3][r] = v.w;
        }
#pragma unroll
        for (int i = 0; i < B_VECS; i++) {
            int idx = tid + i * THREADS;
            int r   = idx / B_ROW_VECS;
            int c   = (idx % B_ROW_VECS) * 4;
            *(float4*)&Bs[r][c] =
                *(const float4*)&B[(size_t)(k0 + r) * N + col0 + c];
        }
        __syncthreads();

#pragma unroll
        for (int kk = 0; kk < BK; kk++) {
            float ra[TM], rb[TN];
#pragma unroll
            for (int i = 0; i < TM; i++) ra[i] = As[kk][ty * TM + i];
#pragma unroll
            for (int j = 0; j < TN; j++) rb[j] = Bs[kk][tx * TN + j];
#pragma unroll
            for (int i = 0; i < TM; i++)
#pragma unroll
                for (int j = 0; j < TN; j++)
                    acc[i][j] = fmaf(ra[i], rb[j], acc[i][j]);
        }
        __syncthreads();
    }

#pragma unroll
    for (int i = 0; i < TM; i++) {
        int row = row0 + ty * TM + i;
#pragma unroll
        for (int j = 0; j < TN; j += 4) {
            int col = col0 + tx * TN + j;
            float4 v;
            v.x = acc[i][j + 0];
            v.y = acc[i][j + 1];
            v.z = acc[i][j + 2];
            v.w = acc[i][j + 3];
            if (BIAS) {
                v.x += bias[col + 0];
                v.y += bias[col + 1];
                v.z += bias[col + 2];
                v.w += bias[col + 3];
            }
            *(float4*)&C[(size_t)row * N + col] = v;
        }
    }
}

// ---------------------------------------------------------------------------
// Causal MQA flash attention.
// BR=64 queries per block, __launch_bounds__(64,5): 5 blocks/SM (reg cap 204,
// no spill), 10 warps/SM. 1D grid of 1024 blocks dispatched heavy-first
// (descending qt) for LPT balance. 1 thread = 1 query row; q/o in registers.
// ---------------------------------------------------------------------------
#define BR 64    // query rows per block (== blockDim.x)
#define BC 64    // key rows per smem tile
#define NQT (NN / BR)   // 32 query tiles per (b,h)

__global__ __launch_bounds__(BR, 5)
void mqa_attn_kernel(const float* __restrict__ Q,
                     const float* __restrict__ K,
                     const float* __restrict__ V,
                     float* __restrict__ Z)
{
    __shared__ float Ks[BC][DD];
    __shared__ float Vs[BC][DD];

    const int wid = blockIdx.x;
    const int qt  = (NQT - 1) - (wid >> 5);   // heavy tiles dispatched first
    const int bh  = wid & 31;                 // 32 (b,h) pairs
    const int b   = bh >> 4;
    const int h   = bh & 15;
    const int tid = threadIdx.x;
    const int nq  = qt * BR + tid;            // query index within batch

    float q[DD], o[DD];
    const float* Qrow = Q + ((size_t)(b * NN + nq)) * HD + h * DD;
    const float qscale = 0.125f;              // 1/sqrt(64)
#pragma unroll
    for (int d = 0; d < DD; d++) {
        q[d] = Qrow[d] * qscale;
        o[d] = 0.0f;
    }

    float m = -1e30f, l = 0.0f;

    const int klimit = (qt + 1) * BR;         // exclusive key bound
    for (int k0 = 0; k0 < klimit; k0 += BC) {
        // cooperative tile load (contiguous BC*DD floats)
        const float4* Kt = (const float4*)(K + ((size_t)(b * NN + k0)) * DD);
        const float4* Vt = (const float4*)(V + ((size_t)(b * NN + k0)) * DD);
        float4* Ksv = (float4*)&Ks[0][0];
        float4* Vsv = (float4*)&Vs[0][0];
#pragma unroll 4
        for (int i = tid; i < BC * DD / 4; i += BR) {
            Ksv[i] = Kt[i];
            Vsv[i] = Vt[i];
        }
        __syncthreads();

        for (int j0 = 0; j0 < BC; j0 += 8) {
            float s[8];
#pragma unroll
            for (int jj = 0; jj < 8; jj++) {
                const float4* kr = (const float4*)&Ks[j0 + jj][0];
                float a0 = 0.0f, a1 = 0.0f, a2 = 0.0f, a3 = 0.0f;
#pragma unroll
                for (int d4 = 0; d4 < DD / 4; d4++) {
                    float4 kv = kr[d4];
                    a0 = fmaf(q[4 * d4 + 0], kv.x, a0);
                    a1 = fmaf(q[4 * d4 + 1], kv.y, a1);
                    a2 = fmaf(q[4 * d4 + 2], kv.z, a2);
                    a3 = fmaf(q[4 * d4 + 3], kv.w, a3);
                }
                float a = (a0 + a1) + (a2 + a3);
                s[jj] = (k0 + j0 + jj <= nq) ? a : -1e30f;
            }

            float mt = m;
#pragma unroll
            for (int jj = 0; jj < 8; jj++) mt = fmaxf(mt, s[jj]);
            const float scale = __expf(m - mt);
            float p[8];
            float lsum = 0.0f;
#pragma unroll
            for (int jj = 0; jj < 8; jj++) {
                p[jj] = __expf(s[jj] - mt);
                lsum += p[jj];
            }
            l = l * scale + lsum;
            m = mt;

#pragma unroll
            for (int d4 = 0; d4 < DD / 4; d4++) {
                float ox = o[4 * d4 + 0] * scale;
                float oy = o[4 * d4 + 1] * scale;
                float oz = o[4 * d4 + 2] * scale;
                float ow = o[4 * d4 + 3] * scale;
#pragma unroll
                for (int jj = 0; jj < 8; jj++) {
                    float4 vv = ((const float4*)&Vs[j0 + jj][0])[d4];
                    ox = fmaf(p[jj], vv.x, ox);
                    oy = fmaf(p[jj], vv.y, oy);
                    oz = fmaf(p[jj], vv.z, oz);
                    ow = fmaf(p[jj], vv.w, ow);
                }
                o[4 * d4 + 0] = ox;
                o[4 * d4 + 1] = oy;
                o[4 * d4 + 2] = oz;
                o[4 * d4 + 3] = ow;
            }
        }
        __syncthreads();
    }

    const float inv = 1.0f / l;
    float* Zrow = Z + ((size_t)(b * NN + nq)) * HD + h * DD;
#pragma unroll
    for (int d = 0; d < DD; d += 4) {
        float4 v;
        v.x = o[d + 0] * inv;
        v.y = o[d + 1] * inv;
        v.z = o[d + 2] * inv;
        v.w = o[d + 3] * inv;
        *(float4*)&Zrow[d] = v;
    }
}

// ---------------------------------------------------------------------------
// Launch
// ---------------------------------------------------------------------------
extern "C" void kernel_launch(void* const* d_in, const int* in_sizes, int n_in,
                              void* d_out, int out_size)
{
    const float* X  = (const float*)d_in[0];  // (B,N,E)
    const float* Wq = (const float*)d_in[1];  // (E, H*D)
    const float* Wk = (const float*)d_in[2];  // (E, D)
    const float* Wv = (const float*)d_in[3];  // (E, D)
    const float* Wo = (const float*)d_in[4];  // (H*D, H*D)
    const float* bo = (const float*)d_in[5];  // (H*D,)
    float* out = (float*)d_out;               // (B,N,H*D)

    float *pQ, *pK, *pV, *pZ;
    cudaGetSymbolAddress((void**)&pQ, g_Q);
    cudaGetSymbolAddress((void**)&pK, g_K);
    cudaGetSymbolAddress((void**)&pV, g_V);
    cudaGetSymbolAddress((void**)&pZ, g_Z);

    // K / V projections fused into one launch: z=0 -> K, z=1 -> V (128 blocks)
    sgemm_kernel<64, 64, 16, 4, 4, false>
        <<<dim3(1, MTOT / 64, 2), 256>>>(X, Wk, nullptr, pK, MTOT, DD, EE,
                                         Wv, pV);

    // Q projection: (4096,1024) @ (1024,1024)
    sgemm_kernel<128, 128, 16, 8, 8, false>
        <<<dim3(HD / 128, MTOT / 128), 256>>>(X, Wq, nullptr, pQ, MTOT, HD, EE,
                                              nullptr, nullptr);

    // Causal MQA attention, heavy-first 1D grid (LPT)
    mqa_attn_kernel<<<NQT * BB * HH, BR>>>(pQ, pK, pV, pZ);

    // Output projection + bias
    sgemm_kernel<128, 128, 16, 8, 8, true>
        <<<dim3(HD / 128, MTOT / 128), 256>>>(pZ, Wo, bo, out, MTOT, HD, HD,
                                              nullptr, nullptr);
}

// round 5
// speedup vs baseline: 2.0163x; 1.2548x over previous
#include <cuda_runtime.h>
#include <cuda_bf16.h>
#include <math.h>
#include <stdint.h>

// Problem constants
#define BB 2
#define NN 2048
#define EE 1024
#define HH 16
#define DD 64
#define HD 1024            // H*D
#define MTOT 4096          // B*N

// ---------------------------------------------------------------------------
// Scratch (static device globals — no allocation allowed)
// ---------------------------------------------------------------------------
__device__ float g_Q[MTOT * HD];   // (B*N, H*D)
__device__ float g_K[MTOT * DD];   // (B*N, D)
__device__ float g_V[MTOT * DD];   // (B*N, D)
__device__ float g_Z[MTOT * HD];   // (B*N, H*D)

// ---------------------------------------------------------------------------
// tf32 tensor-core GEMM: C[M,N] = A[M,K] @ B[K,N] (+ bias)
// Block tile 128x128x32, 8 warps (2x4), warp tile 64x32.
// mma.sync.aligned.m16n8k8.row.col.f32.tf32.tf32.f32, fp32 accumulate.
// Inputs rounded to tf32 with cvt.rna at smem-store time.
// ---------------------------------------------------------------------------
#define GBM 128
#define GBN 128
#define GBK 32
#define LDA 36    // GBK + 4 pad  (36 mod 32 = 4 -> conflict-free frag loads)
#define LDB 132   // GBN + 4 pad  (132 mod 32 = 4)

__device__ __forceinline__ uint32_t f2tf32(float x) {
    uint32_t r;
    asm("cvt.rna.tf32.f32 %0, %1;" : "=r"(r) : "f"(x));
    return r;
}

__device__ __forceinline__ void mma_tf32(float c[4], uint32_t a0, uint32_t a1,
                                         uint32_t a2, uint32_t a3,
                                         uint32_t b0, uint32_t b1) {
    asm volatile(
        "mma.sync.aligned.m16n8k8.row.col.f32.tf32.tf32.f32 "
        "{%0,%1,%2,%3}, {%4,%5,%6,%7}, {%8,%9}, {%0,%1,%2,%3};"
        : "+f"(c[0]), "+f"(c[1]), "+f"(c[2]), "+f"(c[3])
        : "r"(a0), "r"(a1), "r"(a2), "r"(a3), "r"(b0), "r"(b1));
}

template <bool BIAS>
__global__ __launch_bounds__(256)
void tf32_gemm_kernel(const float* __restrict__ A, const float* __restrict__ B,
                      const float* __restrict__ bias, float* __restrict__ C,
                      int M, int N, int K)
{
    __shared__ uint32_t As[GBM * LDA];
    __shared__ uint32_t Bs[GBK * LDB];

    const int tid  = threadIdx.x;
    const int lane = tid & 31;
    const int w    = tid >> 5;
    const int wm   = w & 1;          // 2 warps along M
    const int wn   = w >> 1;         // 4 warps along N
    const int g    = lane >> 2;      // group id 0..7
    const int q    = lane & 3;       // quad lane 0..3
    const int row0 = blockIdx.y * GBM;
    const int col0 = blockIdx.x * GBN;

    // Global staging indices (4 float4 each for A and B per thread)
    // A tile: 128 rows x 32 cols;  idx -> r = idx/8, c = (idx%8)*4
    // B tile: 32 rows x 128 cols;  idx -> r = idx/32, c = (idx%32)*4
    int aIdx[4], bIdx[4];
#pragma unroll
    for (int i = 0; i < 4; i++) { aIdx[i] = tid + i * 256; bIdx[i] = tid + i * 256; }

    float c[4][4][4];
#pragma unroll
    for (int mi = 0; mi < 4; mi++)
#pragma unroll
        for (int ni = 0; ni < 4; ni++)
#pragma unroll
            for (int k = 0; k < 4; k++) c[mi][ni][k] = 0.0f;

    // Prologue: load tile 0
    float4 ra[4], rb[4];
#pragma unroll
    for (int i = 0; i < 4; i++) {
        int r = aIdx[i] >> 3, cc = (aIdx[i] & 7) * 4;
        ra[i] = *(const float4*)&A[(size_t)(row0 + r) * K + cc];
        int br = bIdx[i] >> 5, bc = (bIdx[i] & 31) * 4;
        rb[i] = *(const float4*)&B[(size_t)br * N + col0 + bc];
    }
#pragma unroll
    for (int i = 0; i < 4; i++) {
        int r = aIdx[i] >> 3, cc = (aIdx[i] & 7) * 4;
        As[r * LDA + cc + 0] = f2tf32(ra[i].x);
        As[r * LDA + cc + 1] = f2tf32(ra[i].y);
        As[r * LDA + cc + 2] = f2tf32(ra[i].z);
        As[r * LDA + cc + 3] = f2tf32(ra[i].w);
        int br = bIdx[i] >> 5, bc = (bIdx[i] & 31) * 4;
        uint4 v;
        v.x = f2tf32(rb[i].x); v.y = f2tf32(rb[i].y);
        v.z = f2tf32(rb[i].z); v.w = f2tf32(rb[i].w);
        *(uint4*)&Bs[br * LDB + bc] = v;
    }
    __syncthreads();

    const int NT = K / GBK;
    for (int kt = 0; kt < NT; kt++) {
        // Prefetch next tile into registers (overlaps with MMA below)
        if (kt + 1 < NT) {
            const int k0 = (kt + 1) * GBK;
#pragma unroll
            for (int i = 0; i < 4; i++) {
                int r = aIdx[i] >> 3, cc = (aIdx[i] & 7) * 4;
                ra[i] = *(const float4*)&A[(size_t)(row0 + r) * K + k0 + cc];
                int br = bIdx[i] >> 5, bc = (bIdx[i] & 31) * 4;
                rb[i] = *(const float4*)&B[(size_t)(k0 + br) * N + col0 + bc];
            }
        }

        // MMA over this k-tile (4 steps of k=8)
#pragma unroll
        for (int kk = 0; kk < GBK; kk += 8) {
            uint32_t af[4][4];
#pragma unroll
            for (int mi = 0; mi < 4; mi++) {
                int r = wm * 64 + mi * 16 + g;
                af[mi][0] = As[r * LDA + kk + q];
                af[mi][1] = As[(r + 8) * LDA + kk + q];
                af[mi][2] = As[r * LDA + kk + 4 + q];
                af[mi][3] = As[(r + 8) * LDA + kk + 4 + q];
            }
#pragma unroll
            for (int ni = 0; ni < 4; ni++) {
                int n  = wn * 32 + ni * 8 + g;
                uint32_t b0 = Bs[(kk + q) * LDB + n];
                uint32_t b1 = Bs[(kk + 4 + q) * LDB + n];
#pragma unroll
                for (int mi = 0; mi < 4; mi++)
                    mma_tf32(c[mi][ni], af[mi][0], af[mi][1], af[mi][2], af[mi][3],
                             b0, b1);
            }
        }

        if (kt + 1 < NT) {
            __syncthreads();
#pragma unroll
            for (int i = 0; i < 4; i++) {
                int r = aIdx[i] >> 3, cc = (aIdx[i] & 7) * 4;
                As[r * LDA + cc + 0] = f2tf32(ra[i].x);
                As[r * LDA + cc + 1] = f2tf32(ra[i].y);
                As[r * LDA + cc + 2] = f2tf32(ra[i].z);
                As[r * LDA + cc + 3] = f2tf32(ra[i].w);
                int br = bIdx[i] >> 5, bc = (bIdx[i] & 31) * 4;
                uint4 v;
                v.x = f2tf32(rb[i].x); v.y = f2tf32(rb[i].y);
                v.z = f2tf32(rb[i].z); v.w = f2tf32(rb[i].w);
                *(uint4*)&Bs[br * LDB + bc] = v;
            }
            __syncthreads();
        }
    }

    // Epilogue
#pragma unroll
    for (int mi = 0; mi < 4; mi++) {
        int row = row0 + wm * 64 + mi * 16 + g;
#pragma unroll
        for (int ni = 0; ni < 4; ni++) {
            int col = col0 + wn * 32 + ni * 8 + 2 * q;
            float2 v0 = make_float2(c[mi][ni][0], c[mi][ni][1]);
            float2 v1 = make_float2(c[mi][ni][2], c[mi][ni][3]);
            if (BIAS) {
                float2 bv = *(const float2*)&bias[col];
                v0.x += bv.x; v0.y += bv.y;
                v1.x += bv.x; v1.y += bv.y;
            }
            *(float2*)&C[(size_t)row * N + col] = v0;
            *(float2*)&C[(size_t)(row + 8) * N + col] = v1;
        }
    }
}

// ---------------------------------------------------------------------------
// SIMT SGEMM (kept for the small fused K/V projections only)
// ---------------------------------------------------------------------------
template <int BM, int BN, int BK, int TM, int TN>
__global__ __launch_bounds__((BM / TM) * (BN / TN))
void sgemm_kv_kernel(const float* __restrict__ A, const float* __restrict__ B,
                     float* __restrict__ C, int M, int N, int K,
                     const float* __restrict__ B2, float* __restrict__ C2)
{
    constexpr int THREADS = (BM / TM) * (BN / TN);
    __shared__ float As[BK][BM];
    __shared__ float Bs[BK][BN];

    if (blockIdx.z) { B = B2; C = C2; }

    const int tid  = threadIdx.x;
    const int tx   = tid % (BN / TN);
    const int ty   = tid / (BN / TN);
    const int row0 = blockIdx.y * BM;
    const int col0 = blockIdx.x * BN;

    float acc[TM][TN];
#pragma unroll
    for (int i = 0; i < TM; i++)
#pragma unroll
        for (int j = 0; j < TN; j++) acc[i][j] = 0.0f;

    constexpr int A_VECS     = BM * BK / 4 / THREADS;
    constexpr int B_VECS     = BK * BN / 4 / THREADS;
    constexpr int A_ROW_VECS = BK / 4;
    constexpr int B_ROW_VECS = BN / 4;

    for (int k0 = 0; k0 < K; k0 += BK) {
#pragma unroll
        for (int i = 0; i < A_VECS; i++) {
            int idx = tid + i * THREADS;
            int r   = idx / A_ROW_VECS;
            int cc  = (idx % A_ROW_VECS) * 4;
            float4 v = *(const float4*)&A[(size_t)(row0 + r) * K + k0 + cc];
            As[cc + 0][r] = v.x;
            As[cc + 1][r] = v.y;
            As[cc + 2][r] = v.z;
            As[cc + 3][r] = v.w;
        }
#pragma unroll
        for (int i = 0; i < B_VECS; i++) {
            int idx = tid + i * THREADS;
            int r   = idx / B_ROW_VECS;
            int cc  = (idx % B_ROW_VECS) * 4;
            *(float4*)&Bs[r][cc] =
                *(const float4*)&B[(size_t)(k0 + r) * N + col0 + cc];
        }
        __syncthreads();

#pragma unroll
        for (int kk = 0; kk < BK; kk++) {
            float ra[TM], rb[TN];
#pragma unroll
            for (int i = 0; i < TM; i++) ra[i] = As[kk][ty * TM + i];
#pragma unroll
            for (int j = 0; j < TN; j++) rb[j] = Bs[kk][tx * TN + j];
#pragma unroll
            for (int i = 0; i < TM; i++)
#pragma unroll
                for (int j = 0; j < TN; j++)
                    acc[i][j] = fmaf(ra[i], rb[j], acc[i][j]);
        }
        __syncthreads();
    }

#pragma unroll
    for (int i = 0; i < TM; i++) {
        int row = row0 + ty * TM + i;
#pragma unroll
        for (int j = 0; j < TN; j += 4) {
            int col = col0 + tx * TN + j;
            float4 v;
            v.x = acc[i][j + 0];
            v.y = acc[i][j + 1];
            v.z = acc[i][j + 2];
            v.w = acc[i][j + 3];
            *(float4*)&C[(size_t)row * N + col] = v;
        }
    }
}

// ---------------------------------------------------------------------------
// Causal MQA flash attention (R3 proven version).
// BR=64, 5 blocks/SM, heavy-first 1D grid (LPT). 1 thread = 1 query row.
// ---------------------------------------------------------------------------
#define BR 64    // query rows per block (== blockDim.x)
#define BC 64    // key rows per smem tile
#define NQT (NN / BR)   // 32 query tiles per (b,h)

__global__ __launch_bounds__(BR, 5)
void mqa_attn_kernel(const float* __restrict__ Q,
                     const float* __restrict__ K,
                     const float* __restrict__ V,
                     float* __restrict__ Z)
{
    __shared__ float Ks[BC][DD];
    __shared__ float Vs[BC][DD];

    const int wid = blockIdx.x;
    const int qt  = (NQT - 1) - (wid >> 5);   // heavy tiles dispatched first
    const int bh  = wid & 31;                 // 32 (b,h) pairs
    const int b   = bh >> 4;
    const int h   = bh & 15;
    const int tid = threadIdx.x;
    const int nq  = qt * BR + tid;            // query index within batch

    float q[DD], o[DD];
    const float* Qrow = Q + ((size_t)(b * NN + nq)) * HD + h * DD;
    const float qscale = 0.125f;              // 1/sqrt(64)
#pragma unroll
    for (int d = 0; d < DD; d++) {
        q[d] = Qrow[d] * qscale;
        o[d] = 0.0f;
    }

    float m = -1e30f, l = 0.0f;

    const int klimit = (qt + 1) * BR;         // exclusive key bound
    for (int k0 = 0; k0 < klimit; k0 += BC) {
        const float4* Kt = (const float4*)(K + ((size_t)(b * NN + k0)) * DD);
        const float4* Vt = (const float4*)(V + ((size_t)(b * NN + k0)) * DD);
        float4* Ksv = (float4*)&Ks[0][0];
        float4* Vsv = (float4*)&Vs[0][0];
#pragma unroll 4
        for (int i = tid; i < BC * DD / 4; i += BR) {
            Ksv[i] = Kt[i];
            Vsv[i] = Vt[i];
        }
        __syncthreads();

        for (int j0 = 0; j0 < BC; j0 += 8) {
            float s[8];
#pragma unroll
            for (int jj = 0; jj < 8; jj++) {
                const float4* kr = (const float4*)&Ks[j0 + jj][0];
                float a0 = 0.0f, a1 = 0.0f, a2 = 0.0f, a3 = 0.0f;
#pragma unroll
                for (int d4 = 0; d4 < DD / 4; d4++) {
                    float4 kv = kr[d4];
                    a0 = fmaf(q[4 * d4 + 0], kv.x, a0);
                    a1 = fmaf(q[4 * d4 + 1], kv.y, a1);
                    a2 = fmaf(q[4 * d4 + 2], kv.z, a2);
                    a3 = fmaf(q[4 * d4 + 3], kv.w, a3);
                }
                float a = (a0 + a1) + (a2 + a3);
                s[jj] = (k0 + j0 + jj <= nq) ? a : -1e30f;
            }

            float mt = m;
#pragma unroll
            for (int jj = 0; jj < 8; jj++) mt = fmaxf(mt, s[jj]);
            const float scale = __expf(m - mt);
            float p[8];
            float lsum = 0.0f;
#pragma unroll
            for (int jj = 0; jj < 8; jj++) {
                p[jj] = __expf(s[jj] - mt);
                lsum += p[jj];
            }
            l = l * scale + lsum;
            m = mt;

#pragma unroll
            for (int d4 = 0; d4 < DD / 4; d4++) {
                float ox = o[4 * d4 + 0] * scale;
                float oy = o[4 * d4 + 1] * scale;
                float oz = o[4 * d4 + 2] * scale;
                float ow = o[4 * d4 + 3] * scale;
#pragma unroll
                for (int jj = 0; jj < 8; jj++) {
                    float4 vv = ((const float4*)&Vs[j0 + jj][0])[d4];
                    ox = fmaf(p[jj], vv.x, ox);
                    oy = fmaf(p[jj], vv.y, oy);
                    oz = fmaf(p[jj], vv.z, oz);
                    ow = fmaf(p[jj], vv.w, ow);
                }
                o[4 * d4 + 0] = ox;
                o[4 * d4 + 1] = oy;
                o[4 * d4 + 2] = oz;
                o[4 * d4 + 3] = ow;
            }
        }
        __syncthreads();
    }

    const float inv = 1.0f / l;
    float* Zrow = Z + ((size_t)(b * NN + nq)) * HD + h * DD;
#pragma unroll
    for (int d = 0; d < DD; d += 4) {
        float4 v;
        v.x = o[d + 0] * inv;
        v.y = o[d + 1] * inv;
        v.z = o[d + 2] * inv;
        v.w = o[d + 3] * inv;
        *(float4*)&Zrow[d] = v;
    }
}

// ---------------------------------------------------------------------------
// Launch
// ---------------------------------------------------------------------------
extern "C" void kernel_launch(void* const* d_in, const int* in_sizes, int n_in,
                              void* d_out, int out_size)
{
    const float* X  = (const float*)d_in[0];  // (B,N,E)
    const float* Wq = (const float*)d_in[1];  // (E, H*D)
    const float* Wk = (const float*)d_in[2];  // (E, D)
    const float* Wv = (const float*)d_in[3];  // (E, D)
    const float* Wo = (const float*)d_in[4];  // (H*D, H*D)
    const float* bo = (const float*)d_in[5];  // (H*D,)
    float* out = (float*)d_out;               // (B,N,H*D)

    float *pQ, *pK, *pV, *pZ;
    cudaGetSymbolAddress((void**)&pQ, g_Q);
    cudaGetSymbolAddress((void**)&pK, g_K);
    cudaGetSymbolAddress((void**)&pV, g_V);
    cudaGetSymbolAddress((void**)&pZ, g_Z);

    // K / V projections fused into one launch: z=0 -> K, z=1 -> V (128 blocks)
    sgemm_kv_kernel<64, 64, 16, 4, 4>
        <<<dim3(1, MTOT / 64, 2), 256>>>(X, Wk, pK, MTOT, DD, EE, Wv, pV);

    // Q projection: tf32 tensor cores
    tf32_gemm_kernel<false>
        <<<dim3(HD / GBN, MTOT / GBM), 256>>>(X, Wq, nullptr, pQ, MTOT, HD, EE);

    // Causal MQA attention, heavy-first 1D grid (LPT)
    mqa_attn_kernel<<<NQT * BB * HH, BR>>>(pQ, pK, pV, pZ);

    // Output projection + bias: tf32 tensor cores
    tf32_gemm_kernel<true>
        <<<dim3(HD / GBN, MTOT / GBM), 256>>>(pZ, Wo, bo, out, MTOT, HD, HD);
}

// round 6
// speedup vs baseline: 4.3240x; 2.1445x over previous
#include <cuda_runtime.h>
#include <cuda_bf16.h>
#include <math.h>
#include <stdint.h>

// Problem constants
#define BB 2
#define NN 2048
#define EE 1024
#define HH 16
#define DD 64
#define HD 1024            // H*D
#define MTOT 4096          // B*N

// ---------------------------------------------------------------------------
// Scratch (static device globals — no allocation allowed)
// ---------------------------------------------------------------------------
__device__ float g_Q[MTOT * HD];   // (B*N, H*D)
__device__ float g_K[MTOT * DD];   // (B*N, D)
__device__ float g_V[MTOT * DD];   // (B*N, D)
__device__ float g_Z[MTOT * HD];   // (B*N, H*D)

// ---------------------------------------------------------------------------
// tf32 helpers (fragment maps verified in R4)
// ---------------------------------------------------------------------------
__device__ __forceinline__ uint32_t f2tf32(float x) {
    uint32_t r;
    asm("cvt.rna.tf32.f32 %0, %1;" : "=r"(r) : "f"(x));
    return r;
}

__device__ __forceinline__ void mma_tf32(float c[4], uint32_t a0, uint32_t a1,
                                         uint32_t a2, uint32_t a3,
                                         uint32_t b0, uint32_t b1) {
    asm volatile(
        "mma.sync.aligned.m16n8k8.row.col.f32.tf32.tf32.f32 "
        "{%0,%1,%2,%3}, {%4,%5,%6,%7}, {%8,%9}, {%0,%1,%2,%3};"
        : "+f"(c[0]), "+f"(c[1]), "+f"(c[2]), "+f"(c[3])
        : "r"(a0), "r"(a1), "r"(a2), "r"(a3), "r"(b0), "r"(b1));
}

// ---------------------------------------------------------------------------
// tf32 tensor-core GEMM (R4 proven): C[M,N] = A[M,K] @ B[K,N] (+ bias)
// ---------------------------------------------------------------------------
#define GBM 128
#define GBN 128
#define GBK 32
#define LDA 36
#define LDB 132

template <bool BIAS>
__global__ __launch_bounds__(256)
void tf32_gemm_kernel(const float* __restrict__ A, const float* __restrict__ B,
                      const float* __restrict__ bias, float* __restrict__ C,
                      int M, int N, int K)
{
    __shared__ uint32_t As[GBM * LDA];
    __shared__ uint32_t Bs[GBK * LDB];

    const int tid  = threadIdx.x;
    const int lane = tid & 31;
    const int w    = tid >> 5;
    const int wm   = w & 1;
    const int wn   = w >> 1;
    const int g    = lane >> 2;
    const int q    = lane & 3;
    const int row0 = blockIdx.y * GBM;
    const int col0 = blockIdx.x * GBN;

    float c[4][4][4];
#pragma unroll
    for (int mi = 0; mi < 4; mi++)
#pragma unroll
        for (int ni = 0; ni < 4; ni++)
#pragma unroll
            for (int k = 0; k < 4; k++) c[mi][ni][k] = 0.0f;

    float4 ra[4], rb[4];
#pragma unroll
    for (int i = 0; i < 4; i++) {
        int idx = tid + i * 256;
        int r = idx >> 3, cc = (idx & 7) * 4;
        ra[i] = *(const float4*)&A[(size_t)(row0 + r) * K + cc];
        int br = idx >> 5, bc = (idx & 31) * 4;
        rb[i] = *(const float4*)&B[(size_t)br * N + col0 + bc];
    }
#pragma unroll
    for (int i = 0; i < 4; i++) {
        int idx = tid + i * 256;
        int r = idx >> 3, cc = (idx & 7) * 4;
        As[r * LDA + cc + 0] = f2tf32(ra[i].x);
        As[r * LDA + cc + 1] = f2tf32(ra[i].y);
        As[r * LDA + cc + 2] = f2tf32(ra[i].z);
        As[r * LDA + cc + 3] = f2tf32(ra[i].w);
        int br = idx >> 5, bc = (idx & 31) * 4;
        uint4 v;
        v.x = f2tf32(rb[i].x); v.y = f2tf32(rb[i].y);
        v.z = f2tf32(rb[i].z); v.w = f2tf32(rb[i].w);
        *(uint4*)&Bs[br * LDB + bc] = v;
    }
    __syncthreads();

    const int NT = K / GBK;
    for (int kt = 0; kt < NT; kt++) {
        if (kt + 1 < NT) {
            const int k0 = (kt + 1) * GBK;
#pragma unroll
            for (int i = 0; i < 4; i++) {
                int idx = tid + i * 256;
                int r = idx >> 3, cc = (idx & 7) * 4;
                ra[i] = *(const float4*)&A[(size_t)(row0 + r) * K + k0 + cc];
                int br = idx >> 5, bc = (idx & 31) * 4;
                rb[i] = *(const float4*)&B[(size_t)(k0 + br) * N + col0 + bc];
            }
        }

#pragma unroll
        for (int kk = 0; kk < GBK; kk += 8) {
            uint32_t af[4][4];
#pragma unroll
            for (int mi = 0; mi < 4; mi++) {
                int r = wm * 64 + mi * 16 + g;
                af[mi][0] = As[r * LDA + kk + q];
                af[mi][1] = As[(r + 8) * LDA + kk + q];
                af[mi][2] = As[r * LDA + kk + 4 + q];
                af[mi][3] = As[(r + 8) * LDA + kk + 4 + q];
            }
#pragma unroll
            for (int ni = 0; ni < 4; ni++) {
                int n  = wn * 32 + ni * 8 + g;
                uint32_t b0 = Bs[(kk + q) * LDB + n];
                uint32_t b1 = Bs[(kk + 4 + q) * LDB + n];
#pragma unroll
                for (int mi = 0; mi < 4; mi++)
                    mma_tf32(c[mi][ni], af[mi][0], af[mi][1], af[mi][2], af[mi][3],
                             b0, b1);
            }
        }

        if (kt + 1 < NT) {
            __syncthreads();
#pragma unroll
            for (int i = 0; i < 4; i++) {
                int idx = tid + i * 256;
                int r = idx >> 3, cc = (idx & 7) * 4;
                As[r * LDA + cc + 0] = f2tf32(ra[i].x);
                As[r * LDA + cc + 1] = f2tf32(ra[i].y);
                As[r * LDA + cc + 2] = f2tf32(ra[i].z);
                As[r * LDA + cc + 3] = f2tf32(ra[i].w);
                int br = idx >> 5, bc = (idx & 31) * 4;
                uint4 v;
                v.x = f2tf32(rb[i].x); v.y = f2tf32(rb[i].y);
                v.z = f2tf32(rb[i].z); v.w = f2tf32(rb[i].w);
                *(uint4*)&Bs[br * LDB + bc] = v;
            }
            __syncthreads();
        }
    }

#pragma unroll
    for (int mi = 0; mi < 4; mi++) {
        int row = row0 + wm * 64 + mi * 16 + g;
#pragma unroll
        for (int ni = 0; ni < 4; ni++) {
            int col = col0 + wn * 32 + ni * 8 + 2 * q;
            float2 v0 = make_float2(c[mi][ni][0], c[mi][ni][1]);
            float2 v1 = make_float2(c[mi][ni][2], c[mi][ni][3]);
            if (BIAS) {
                float2 bv = *(const float2*)&bias[col];
                v0.x += bv.x; v0.y += bv.y;
                v1.x += bv.x; v1.y += bv.y;
            }
            *(float2*)&C[(size_t)row * N + col] = v0;
            *(float2*)&C[(size_t)(row + 8) * N + col] = v1;
        }
    }
}

// ---------------------------------------------------------------------------
// SIMT SGEMM (fused K/V projections only)
// ---------------------------------------------------------------------------
template <int BM, int BN, int BK, int TM, int TN>
__global__ __launch_bounds__((BM / TM) * (BN / TN))
void sgemm_kv_kernel(const float* __restrict__ A, const float* __restrict__ B,
                     float* __restrict__ C, int M, int N, int K,
                     const float* __restrict__ B2, float* __restrict__ C2)
{
    constexpr int THREADS = (BM / TM) * (BN / TN);
    __shared__ float As[BK][BM];
    __shared__ float Bs[BK][BN];

    if (blockIdx.z) { B = B2; C = C2; }

    const int tid  = threadIdx.x;
    const int tx   = tid % (BN / TN);
    const int ty   = tid / (BN / TN);
    const int row0 = blockIdx.y * BM;
    const int col0 = blockIdx.x * BN;

    float acc[TM][TN];
#pragma unroll
    for (int i = 0; i < TM; i++)
#pragma unroll
        for (int j = 0; j < TN; j++) acc[i][j] = 0.0f;

    constexpr int A_VECS     = BM * BK / 4 / THREADS;
    constexpr int B_VECS     = BK * BN / 4 / THREADS;
    constexpr int A_ROW_VECS = BK / 4;
    constexpr int B_ROW_VECS = BN / 4;

    for (int k0 = 0; k0 < K; k0 += BK) {
#pragma unroll
        for (int i = 0; i < A_VECS; i++) {
            int idx = tid + i * THREADS;
            int r   = idx / A_ROW_VECS;
            int cc  = (idx % A_ROW_VECS) * 4;
            float4 v = *(const float4*)&A[(size_t)(row0 + r) * K + k0 + cc];
            As[cc + 0][r] = v.x;
            As[cc + 1][r] = v.y;
            As[cc + 2][r] = v.z;
            As[cc + 3][r] = v.w;
        }
#pragma unroll
        for (int i = 0; i < B_VECS; i++) {
            int idx = tid + i * THREADS;
            int r   = idx / B_ROW_VECS;
            int cc  = (idx % B_ROW_VECS) * 4;
            *(float4*)&Bs[r][cc] =
                *(const float4*)&B[(size_t)(k0 + r) * N + col0 + cc];
        }
        __syncthreads();

#pragma unroll
        for (int kk = 0; kk < BK; kk++) {
            float ra[TM], rb[TN];
#pragma unroll
            for (int i = 0; i < TM; i++) ra[i] = As[kk][ty * TM + i];
#pragma unroll
            for (int j = 0; j < TN; j++) rb[j] = Bs[kk][tx * TN + j];
#pragma unroll
            for (int i = 0; i < TM; i++)
#pragma unroll
                for (int j = 0; j < TN; j++)
                    acc[i][j] = fmaf(ra[i], rb[j], acc[i][j]);
        }
        __syncthreads();
    }

#pragma unroll
    for (int i = 0; i < TM; i++) {
        int row = row0 + ty * TM + i;
#pragma unroll
        for (int j = 0; j < TN; j += 4) {
            int col = col0 + tx * TN + j;
            float4 v;
            v.x = acc[i][j + 0];
            v.y = acc[i][j + 1];
            v.z = acc[i][j + 2];
            v.w = acc[i][j + 3];
            *(float4*)&C[(size_t)row * N + col] = v;
        }
    }
}

// ---------------------------------------------------------------------------
// Tensor-core causal MQA flash attention (tf32 m16n8k8).
// Block = 4 warps = 64 query rows; warp owns 16 rows (m16 fragment rows).
// KV tiles of 64. K stored transposed [d][j] in smem (reused for P after S);
// V stored natural [j][d]. Online softmax in C-fragments, quad shuffles for
// row reductions. Heavy-first 1D grid (LPT): 1024 blocks.
// ---------------------------------------------------------------------------
#define AQT 64           // query rows per block
#define ANQT (NN / AQT)  // 32 query tiles per (b,h)
#define SKP 68           // smem row stride (uint32) for Kt/P and V

__global__ __launch_bounds__(128, 3)
void mqa_attn_tc_kernel(const float* __restrict__ Q,
                        const float* __restrict__ K,
                        const float* __restrict__ Vin,
                        float* __restrict__ Z)
{
    __shared__ uint32_t KtP[DD * SKP];   // K^T [d][j], then P [i][j]
    __shared__ uint32_t Vs[AQT * SKP];   // V [j][d]

    const int wid  = blockIdx.x;
    const int qt   = (ANQT - 1) - (wid >> 5);   // heavy-first
    const int bh   = wid & 31;
    const int b    = bh >> 4;
    const int h    = bh & 15;
    const int tid  = threadIdx.x;
    const int lane = tid & 31;
    const int wrp  = tid >> 5;
    const int g    = lane >> 2;
    const int q    = lane & 3;

    // Q fragments, resident for the whole sweep (scaled by 1/sqrt(D))
    uint32_t aq[8][4];
    const float* Qb = Q + ((size_t)(b * NN + qt * AQT + wrp * 16)) * HD + h * DD;
#pragma unroll
    for (int t = 0; t < 8; t++) {
        aq[t][0] = f2tf32(Qb[(size_t)g * HD       + t * 8 + q    ] * 0.125f);
        aq[t][1] = f2tf32(Qb[(size_t)(g + 8) * HD + t * 8 + q    ] * 0.125f);
        aq[t][2] = f2tf32(Qb[(size_t)g * HD       + t * 8 + q + 4] * 0.125f);
        aq[t][3] = f2tf32(Qb[(size_t)(g + 8) * HD + t * 8 + q + 4] * 0.125f);
    }

    float o[8][4];
#pragma unroll
    for (int nt = 0; nt < 8; nt++)
#pragma unroll
        for (int k = 0; k < 4; k++) o[nt][k] = 0.0f;
    float m0 = -1e30f, m1 = -1e30f, l0 = 0.0f, l1 = 0.0f;

    for (int kt = 0; kt <= qt; kt++) {
        // --- cooperative K^T / V tile load ---
        const float* Kg = K   + ((size_t)(b * NN + kt * 64)) * DD;
        const float* Vg = Vin + ((size_t)(b * NN + kt * 64)) * DD;
#pragma unroll
        for (int s8 = 0; s8 < 8; s8++) {
            int v = tid + s8 * 128;
            int j = v >> 4, c = (v & 15) * 4;
            float4 kf = *(const float4*)&Kg[j * DD + c];
            KtP[(c + 0) * SKP + j] = f2tf32(kf.x);
            KtP[(c + 1) * SKP + j] = f2tf32(kf.y);
            KtP[(c + 2) * SKP + j] = f2tf32(kf.z);
            KtP[(c + 3) * SKP + j] = f2tf32(kf.w);
            float4 vf = *(const float4*)&Vg[j * DD + c];
            uint4 u;
            u.x = f2tf32(vf.x); u.y = f2tf32(vf.y);
            u.z = f2tf32(vf.z); u.w = f2tf32(vf.w);
            *(uint4*)&Vs[j * SKP + c] = u;
        }
        __syncthreads();

        // --- S = Q K^T (16x64 per warp) ---
        float s[8][4];
#pragma unroll
        for (int nt = 0; nt < 8; nt++) {
            s[nt][0] = s[nt][1] = s[nt][2] = s[nt][3] = 0.0f;
#pragma unroll
            for (int kk = 0; kk < 8; kk++) {
                uint32_t b0 = KtP[(kk * 8 + q) * SKP + nt * 8 + g];
                uint32_t b1 = KtP[(kk * 8 + q + 4) * SKP + nt * 8 + g];
                mma_tf32(s[nt], aq[kk][0], aq[kk][1], aq[kk][2], aq[kk][3],
                         b0, b1);
            }
        }

        // --- causal mask on diagonal tile ---
        if (kt == qt) {
            const int r0 = wrp * 16 + g, r1 = r0 + 8;
#pragma unroll
            for (int nt = 0; nt < 8; nt++) {
                int c0 = nt * 8 + 2 * q, c1 = c0 + 1;
                if (c0 > r0) s[nt][0] = -1e30f;
                if (c1 > r0) s[nt][1] = -1e30f;
                if (c0 > r1) s[nt][2] = -1e30f;
                if (c1 > r1) s[nt][3] = -1e30f;
            }
        }

        // --- online softmax (rows live in quads: shfl xor 1,2) ---
        float ml0 = -1e30f, ml1 = -1e30f;
#pragma unroll
        for (int nt = 0; nt < 8; nt++) {
            ml0 = fmaxf(ml0, fmaxf(s[nt][0], s[nt][1]));
            ml1 = fmaxf(ml1, fmaxf(s[nt][2], s[nt][3]));
        }
        ml0 = fmaxf(ml0, __shfl_xor_sync(0xffffffffu, ml0, 1));
        ml0 = fmaxf(ml0, __shfl_xor_sync(0xffffffffu, ml0, 2));
        ml1 = fmaxf(ml1, __shfl_xor_sync(0xffffffffu, ml1, 1));
        ml1 = fmaxf(ml1, __shfl_xor_sync(0xffffffffu, ml1, 2));
        const float mn0 = fmaxf(m0, ml0), mn1 = fmaxf(m1, ml1);
        const float sc0 = __expf(m0 - mn0), sc1 = __expf(m1 - mn1);
        float ls0 = 0.0f, ls1 = 0.0f;
#pragma unroll
        for (int nt = 0; nt < 8; nt++) {
            s[nt][0] = __expf(s[nt][0] - mn0);
            s[nt][1] = __expf(s[nt][1] - mn0);
            s[nt][2] = __expf(s[nt][2] - mn1);
            s[nt][3] = __expf(s[nt][3] - mn1);
            ls0 += s[nt][0] + s[nt][1];
            ls1 += s[nt][2] + s[nt][3];
        }
        ls0 += __shfl_xor_sync(0xffffffffu, ls0, 1);
        ls0 += __shfl_xor_sync(0xffffffffu, ls0, 2);
        ls1 += __shfl_xor_sync(0xffffffffu, ls1, 1);
        ls1 += __shfl_xor_sync(0xffffffffu, ls1, 2);
        l0 = l0 * sc0 + ls0; m0 = mn0;
        l1 = l1 * sc1 + ls1; m1 = mn1;
#pragma unroll
        for (int nt = 0; nt < 8; nt++) {
            o[nt][0] *= sc0; o[nt][1] *= sc0;
            o[nt][2] *= sc1; o[nt][3] *= sc1;
        }

        __syncthreads();   // all warps done reading K^T before P overwrite

        // --- P to smem (C-layout -> A-layout round trip), own rows only ---
#pragma unroll
        for (int nt = 0; nt < 8; nt++) {
            KtP[(wrp * 16 + g) * SKP + nt * 8 + 2 * q    ] = f2tf32(s[nt][0]);
            KtP[(wrp * 16 + g) * SKP + nt * 8 + 2 * q + 1] = f2tf32(s[nt][1]);
            KtP[(wrp * 16 + g + 8) * SKP + nt * 8 + 2 * q    ] = f2tf32(s[nt][2]);
            KtP[(wrp * 16 + g + 8) * SKP + nt * 8 + 2 * q + 1] = f2tf32(s[nt][3]);
        }
        __syncwarp();

        // --- O += P V ---
#pragma unroll
        for (int kk = 0; kk < 8; kk++) {
            uint32_t p0 = KtP[(wrp * 16 + g) * SKP + kk * 8 + q];
            uint32_t p1 = KtP[(wrp * 16 + g + 8) * SKP + kk * 8 + q];
            uint32_t p2 = KtP[(wrp * 16 + g) * SKP + kk * 8 + q + 4];
            uint32_t p3 = KtP[(wrp * 16 + g + 8) * SKP + kk * 8 + q + 4];
#pragma unroll
            for (int nt = 0; nt < 8; nt++) {
                uint32_t b0 = Vs[(kk * 8 + q) * SKP + nt * 8 + g];
                uint32_t b1 = Vs[(kk * 8 + q + 4) * SKP + nt * 8 + g];
                mma_tf32(o[nt], p0, p1, p2, p3, b0, b1);
            }
        }
        __syncthreads();   // before next tile overwrites KtP / Vs
    }

    // --- normalize and write ---
    const float i0 = 1.0f / l0, i1 = 1.0f / l1;
    float* Z0 = Z + ((size_t)(b * NN + qt * AQT + wrp * 16 + g)) * HD + h * DD;
    float* Z1 = Z0 + (size_t)8 * HD;
#pragma unroll
    for (int nt = 0; nt < 8; nt++) {
        int c = nt * 8 + 2 * q;
        *(float2*)&Z0[c] = make_float2(o[nt][0] * i0, o[nt][1] * i0);
        *(float2*)&Z1[c] = make_float2(o[nt][2] * i1, o[nt][3] * i1);
    }
}

// ---------------------------------------------------------------------------
// Launch
// ---------------------------------------------------------------------------
extern "C" void kernel_launch(void* const* d_in, const int* in_sizes, int n_in,
                              void* d_out, int out_size)
{
    const float* X  = (const float*)d_in[0];  // (B,N,E)
    const float* Wq = (const float*)d_in[1];  // (E, H*D)
    const float* Wk = (const float*)d_in[2];  // (E, D)
    const float* Wv = (const float*)d_in[3];  // (E, D)
    const float* Wo = (const float*)d_in[4];  // (H*D, H*D)
    const float* bo = (const float*)d_in[5];  // (H*D,)
    float* out = (float*)d_out;               // (B,N,H*D)

    float *pQ, *pK, *pV, *pZ;
    cudaGetSymbolAddress((void**)&pQ, g_Q);
    cudaGetSymbolAddress((void**)&pK, g_K);
    cudaGetSymbolAddress((void**)&pV, g_V);
    cudaGetSymbolAddress((void**)&pZ, g_Z);

    // K / V projections fused: z=0 -> K, z=1 -> V (128 blocks)
    sgemm_kv_kernel<64, 64, 16, 4, 4>
        <<<dim3(1, MTOT / 64, 2), 256>>>(X, Wk, pK, MTOT, DD, EE, Wv, pV);

    // Q projection: tf32 tensor cores
    tf32_gemm_kernel<false>
        <<<dim3(HD / GBN, MTOT / GBM), 256>>>(X, Wq, nullptr, pQ, MTOT, HD, EE);

    // Tensor-core causal MQA attention, heavy-first 1D grid (LPT)
    mqa_attn_tc_kernel<<<ANQT * BB * HH, 128>>>(pQ, pK, pV, pZ);

    // Output projection + bias: tf32 tensor cores
    tf32_gemm_kernel<true>
        <<<dim3(HD / GBN, MTOT / GBM), 256>>>(pZ, Wo, bo, out, MTOT, HD, HD);
}

// round 8
// speedup vs baseline: 5.5824x; 1.2910x over previous
#include <cuda_runtime.h>
#include <cuda_bf16.h>
#include <math.h>
#include <stdint.h>

// Problem constants
#define BB 2
#define NN 2048
#define EE 1024
#define HH 16
#define DD 64
#define HD 1024            // H*D
#define MTOT 4096          // B*N

// ---------------------------------------------------------------------------
// Scratch (static device globals — no allocation allowed)
// ---------------------------------------------------------------------------
__device__ float g_Q[MTOT * HD];   // (B*N, H*D)
__device__ float g_K[MTOT * DD];   // (B*N, D)
__device__ float g_V[MTOT * DD];   // (B*N, D)
__device__ float g_Z[MTOT * HD];   // (B*N, H*D)

// ---------------------------------------------------------------------------
// tf32 helpers (fragment maps verified in R4/R5)
// ---------------------------------------------------------------------------
__device__ __forceinline__ uint32_t f2tf32(float x) {
    uint32_t r;
    asm("cvt.rna.tf32.f32 %0, %1;" : "=r"(r) : "f"(x));
    return r;
}

__device__ __forceinline__ void mma_tf32(float c[4], uint32_t a0, uint32_t a1,
                                         uint32_t a2, uint32_t a3,
                                         uint32_t b0, uint32_t b1) {
    asm volatile(
        "mma.sync.aligned.m16n8k8.row.col.f32.tf32.tf32.f32 "
        "{%0,%1,%2,%3}, {%4,%5,%6,%7}, {%8,%9}, {%0,%1,%2,%3};"
        : "+f"(c[0]), "+f"(c[1]), "+f"(c[2]), "+f"(c[3])
        : "r"(a0), "r"(a1), "r"(a2), "r"(a3), "r"(b0), "r"(b1));
}

// ---------------------------------------------------------------------------
// tf32 tensor-core GEMM with conflict-free layouts + double buffering.
// C[M,N] = A[M,K] @ B[K,N] (+ bias).
// A smem: natural [m][k], stride 36  -> A-frag banks 4g+q (conflict-free)
// B smem: XOR swizzle [k][n ^ 8(k&3)], stride 128 -> frag banks g+8((ni^q)&3)
// Double-buffered dynamic smem (68KB), ONE __syncthreads per k-tile.
// ---------------------------------------------------------------------------
#define GBM 128
#define GBN 128
#define GBK 32
#define LDA 36
#define ABUF (GBM * LDA)      // 4608 words per A buffer
#define BBUF (GBK * 128)      // 4096 words per B buffer
#define GEMM_SMEM ((2 * ABUF + 2 * BBUF) * 4)   // 69632 bytes

template <bool BIAS>
__global__ __launch_bounds__(256)
void tf32_gemm_kernel(const float* __restrict__ A, const float* __restrict__ B,
                      const float* __restrict__ bias, float* __restrict__ C,
                      int M, int N, int K)
{
    extern __shared__ uint32_t sm[];
    uint32_t* As = sm;                 // [2][GBM*LDA]
    uint32_t* Bs = sm + 2 * ABUF;      // [2][GBK*128]

    const int tid  = threadIdx.x;
    const int lane = tid & 31;
    const int w    = tid >> 5;
    const int wm   = w & 1;
    const int wn   = w >> 1;
    const int g    = lane >> 2;
    const int q    = lane & 3;
    const int row0 = blockIdx.y * GBM;
    const int col0 = blockIdx.x * GBN;

    float c[4][4][4];
#pragma unroll
    for (int mi = 0; mi < 4; mi++)
#pragma unroll
        for (int ni = 0; ni < 4; ni++)
#pragma unroll
            for (int k = 0; k < 4; k++) c[mi][ni][k] = 0.0f;

    // Staging maps (coalesced):
    //  A: idx = tid + i*256 -> r = idx>>3 (m), c = (idx&7)*4 (k)
    //  B: idx = tid + i*256 -> r = idx>>5 (k), c = (idx&31)*4 (n)
    float4 ra[4], rb[4];
#pragma unroll
    for (int i = 0; i < 4; i++) {
        int idx = tid + i * 256;
        ra[i] = *(const float4*)&A[(size_t)(row0 + (idx >> 3)) * K + (idx & 7) * 4];
        rb[i] = *(const float4*)&B[(size_t)(idx >> 5) * N + col0 + (idx & 31) * 4];
    }
#pragma unroll
    for (int i = 0; i < 4; i++) {
        int idx = tid + i * 256;
        int r = idx >> 3, cc = (idx & 7) * 4;
        uint4 av;
        av.x = f2tf32(ra[i].x); av.y = f2tf32(ra[i].y);
        av.z = f2tf32(ra[i].z); av.w = f2tf32(ra[i].w);
        *(uint4*)&As[r * LDA + cc] = av;
        int br = idx >> 5, bc = (idx & 31) * 4;
        uint4 bv;
        bv.x = f2tf32(rb[i].x); bv.y = f2tf32(rb[i].y);
        bv.z = f2tf32(rb[i].z); bv.w = f2tf32(rb[i].w);
        *(uint4*)&Bs[(br << 7) + (bc ^ (8 * (br & 3)))] = bv;
    }
    __syncthreads();

    const int NT = K / GBK;
    for (int kt = 0; kt < NT; kt++) {
        const int cur = kt & 1;
        const uint32_t* Ac = As + cur * ABUF;
        const uint32_t* Bc = Bs + cur * BBUF;

        if (kt + 1 < NT) {
            const int k0 = (kt + 1) * GBK;
#pragma unroll
            for (int i = 0; i < 4; i++) {
                int idx = tid + i * 256;
                ra[i] = *(const float4*)&A[(size_t)(row0 + (idx >> 3)) * K + k0 + (idx & 7) * 4];
                rb[i] = *(const float4*)&B[(size_t)(k0 + (idx >> 5)) * N + col0 + (idx & 31) * 4];
            }
        }

#pragma unroll
        for (int kk = 0; kk < GBK; kk += 8) {
            uint32_t af[4][4];
#pragma unroll
            for (int mi = 0; mi < 4; mi++) {
                int r = wm * 64 + mi * 16 + g;
                af[mi][0] = Ac[r * LDA + kk + q];
                af[mi][1] = Ac[(r + 8) * LDA + kk + q];
                af[mi][2] = Ac[r * LDA + kk + 4 + q];
                af[mi][3] = Ac[(r + 8) * LDA + kk + 4 + q];
            }
#pragma unroll
            for (int ni = 0; ni < 4; ni++) {
                int n  = wn * 32 + ni * 8 + g;
                int nx = n ^ (8 * q);
                uint32_t b0 = Bc[((kk + q) << 7) + nx];
                uint32_t b1 = Bc[((kk + q + 4) << 7) + nx];
#pragma unroll
                for (int mi = 0; mi < 4; mi++)
                    mma_tf32(c[mi][ni], af[mi][0], af[mi][1], af[mi][2], af[mi][3],
                             b0, b1);
            }
        }

        if (kt + 1 < NT) {
            const int nxt = cur ^ 1;
            uint32_t* An = As + nxt * ABUF;
            uint32_t* Bn = Bs + nxt * BBUF;
#pragma unroll
            for (int i = 0; i < 4; i++) {
                int idx = tid + i * 256;
                int r = idx >> 3, cc = (idx & 7) * 4;
                uint4 av;
                av.x = f2tf32(ra[i].x); av.y = f2tf32(ra[i].y);
                av.z = f2tf32(ra[i].z); av.w = f2tf32(ra[i].w);
                *(uint4*)&An[r * LDA + cc] = av;
                int br = idx >> 5, bc = (idx & 31) * 4;
                uint4 bv;
                bv.x = f2tf32(rb[i].x); bv.y = f2tf32(rb[i].y);
                bv.z = f2tf32(rb[i].z); bv.w = f2tf32(rb[i].w);
                *(uint4*)&Bn[(br << 7) + (bc ^ (8 * (br & 3)))] = bv;
            }
            __syncthreads();
        }
    }

#pragma unroll
    for (int mi = 0; mi < 4; mi++) {
        int row = row0 + wm * 64 + mi * 16 + g;
#pragma unroll
        for (int ni = 0; ni < 4; ni++) {
            int col = col0 + wn * 32 + ni * 8 + 2 * q;
            float2 v0 = make_float2(c[mi][ni][0], c[mi][ni][1]);
            float2 v1 = make_float2(c[mi][ni][2], c[mi][ni][3]);
            if (BIAS) {
                float2 bv = *(const float2*)&bias[col];
                v0.x += bv.x; v0.y += bv.y;
                v1.x += bv.x; v1.y += bv.y;
            }
            *(float2*)&C[(size_t)row * N + col] = v0;
            *(float2*)&C[(size_t)(row + 8) * N + col] = v1;
        }
    }
}

// ---------------------------------------------------------------------------
// SIMT SGEMM (fused K/V projections only)
// ---------------------------------------------------------------------------
template <int BM, int BN, int BK, int TM, int TN>
__global__ __launch_bounds__((BM / TM) * (BN / TN))
void sgemm_kv_kernel(const float* __restrict__ A, const float* __restrict__ B,
                     float* __restrict__ C, int M, int N, int K,
                     const float* __restrict__ B2, float* __restrict__ C2)
{
    constexpr int THREADS = (BM / TM) * (BN / TN);
    __shared__ float As[BK][BM];
    __shared__ float Bs[BK][BN];

    if (blockIdx.z) { B = B2; C = C2; }

    const int tid  = threadIdx.x;
    const int tx   = tid % (BN / TN);
    const int ty   = tid / (BN / TN);
    const int row0 = blockIdx.y * BM;
    const int col0 = blockIdx.x * BN;

    float acc[TM][TN];
#pragma unroll
    for (int i = 0; i < TM; i++)
#pragma unroll
        for (int j = 0; j < TN; j++) acc[i][j] = 0.0f;

    constexpr int A_VECS     = BM * BK / 4 / THREADS;
    constexpr int B_VECS     = BK * BN / 4 / THREADS;
    constexpr int A_ROW_VECS = BK / 4;
    constexpr int B_ROW_VECS = BN / 4;

    for (int k0 = 0; k0 < K; k0 += BK) {
#pragma unroll
        for (int i = 0; i < A_VECS; i++) {
            int idx = tid + i * THREADS;
            int r   = idx / A_ROW_VECS;
            int cc  = (idx % A_ROW_VECS) * 4;
            float4 v = *(const float4*)&A[(size_t)(row0 + r) * K + k0 + cc];
            As[cc + 0][r] = v.x;
            As[cc + 1][r] = v.y;
            As[cc + 2][r] = v.z;
            As[cc + 3][r] = v.w;
        }
#pragma unroll
        for (int i = 0; i < B_VECS; i++) {
            int idx = tid + i * THREADS;
            int r   = idx / B_ROW_VECS;
            int cc  = (idx % B_ROW_VECS) * 4;
            *(float4*)&Bs[r][cc] =
                *(const float4*)&B[(size_t)(k0 + r) * N + col0 + cc];
        }
        __syncthreads();

#pragma unroll
        for (int kk = 0; kk < BK; kk++) {
            float ra[TM], rb[TN];
#pragma unroll
            for (int i = 0; i < TM; i++) ra[i] = As[kk][ty * TM + i];
#pragma unroll
            for (int j = 0; j < TN; j++) rb[j] = Bs[kk][tx * TN + j];
#pragma unroll
            for (int i = 0; i < TM; i++)
#pragma unroll
                for (int j = 0; j < TN; j++)
                    acc[i][j] = fmaf(ra[i], rb[j], acc[i][j]);
        }
        __syncthreads();
    }

#pragma unroll
    for (int i = 0; i < TM; i++) {
        int row = row0 + ty * TM + i;
#pragma unroll
        for (int j = 0; j < TN; j += 4) {
            int col = col0 + tx * TN + j;
            float4 v;
            v.x = acc[i][j + 0];
            v.y = acc[i][j + 1];
            v.z = acc[i][j + 2];
            v.w = acc[i][j + 3];
            *(float4*)&C[(size_t)row * N + col] = v;
        }
    }
}

// ---------------------------------------------------------------------------
// Tensor-core causal MQA flash attention, conflict-free smem layouts.
// K smem: NATURAL [j][d], stride 68 -> S B-frag banks 4g+q (conflict-free),
//         vectorized STS.128 tile load.
// V smem: XOR swizzle [j][d ^ 8(j&3)], stride 64 -> PV B-frag conflict-free.
// P: separate buffer [i][j], stride 68 -> A-frag banks 4g+q, STS.64 writes.
// 2 syncthreads per kv-tile (load barrier + end barrier).
// ---------------------------------------------------------------------------
#define AQT 64           // query rows per block
#define ANQT (NN / AQT)  // 32 query tiles per (b,h)
#define SKK 68           // K row stride (words)
#define SKV 64           // V row stride (words)
#define SKP 68           // P row stride (words)
#define ATTN_SMEM ((AQT * SKK + AQT * SKV + AQT * SKP) * 4)   // 51200 bytes

__global__ __launch_bounds__(128, 3)
void mqa_attn_tc_kernel(const float* __restrict__ Q,
                        const float* __restrict__ K,
                        const float* __restrict__ Vin,
                        float* __restrict__ Z)
{
    extern __shared__ uint32_t dsm[];
    uint32_t* Ks = dsm;                        // [64][68]
    uint32_t* Vs = dsm + AQT * SKK;            // [64][64] swizzled
    uint32_t* Ps = dsm + AQT * SKK + AQT * SKV;// [64][68]

    const int wid  = blockIdx.x;
    const int qt   = (ANQT - 1) - (wid >> 5);   // heavy-first (LPT)
    const int bh   = wid & 31;
    const int b    = bh >> 4;
    const int h    = bh & 15;
    const int tid  = threadIdx.x;
    const int lane = tid & 31;
    const int wrp  = tid >> 5;
    const int g    = lane >> 2;
    const int q    = lane & 3;

    // Q fragments, resident for the whole sweep (scaled by 1/sqrt(D))
    uint32_t aq[8][4];
    const float* Qb = Q + ((size_t)(b * NN + qt * AQT + wrp * 16)) * HD + h * DD;
#pragma unroll
    for (int t = 0; t < 8; t++) {
        aq[t][0] = f2tf32(Qb[(size_t)g * HD       + t * 8 + q    ] * 0.125f);
        aq[t][1] = f2tf32(Qb[(size_t)(g + 8) * HD + t * 8 + q    ] * 0.125f);
        aq[t][2] = f2tf32(Qb[(size_t)g * HD       + t * 8 + q + 4] * 0.125f);
        aq[t][3] = f2tf32(Qb[(size_t)(g + 8) * HD + t * 8 + q + 4] * 0.125f);
    }

    float o[8][4];
#pragma unroll
    for (int nt = 0; nt < 8; nt++)
#pragma unroll
        for (int k = 0; k < 4; k++) o[nt][k] = 0.0f;
    float m0 = -1e30f, m1 = -1e30f, l0 = 0.0f, l1 = 0.0f;

    const int prow0 = wrp * 16 + g;      // P fragment row (this thread)

    for (int kt = 0; kt <= qt; kt++) {
        // --- cooperative K / V tile load (natural K, swizzled V) ---
        const float* Kg = K   + ((size_t)(b * NN + kt * 64)) * DD;
        const float* Vg = Vin + ((size_t)(b * NN + kt * 64)) * DD;
#pragma unroll
        for (int s8 = 0; s8 < 8; s8++) {
            int v = tid + s8 * 128;
            int j = v >> 4, c = (v & 15) * 4;
            float4 kf = *(const float4*)&Kg[j * DD + c];
            uint4 ku;
            ku.x = f2tf32(kf.x); ku.y = f2tf32(kf.y);
            ku.z = f2tf32(kf.z); ku.w = f2tf32(kf.w);
            *(uint4*)&Ks[j * SKK + c] = ku;
            float4 vf = *(const float4*)&Vg[j * DD + c];
            uint4 vu;
            vu.x = f2tf32(vf.x); vu.y = f2tf32(vf.y);
            vu.z = f2tf32(vf.z); vu.w = f2tf32(vf.w);
            *(uint4*)&Vs[j * SKV + (c ^ (8 * (j & 3)))] = vu;
        }
        __syncthreads();

        // --- S = Q K^T : B[k=d][n=j] = K[j][d] from natural layout ---
        float s[8][4];
#pragma unroll
        for (int nt = 0; nt < 8; nt++) {
            s[nt][0] = s[nt][1] = s[nt][2] = s[nt][3] = 0.0f;
            const uint32_t* Krow = Ks + (nt * 8 + g) * SKK;
#pragma unroll
            for (int kk = 0; kk < 8; kk++) {
                uint32_t b0 = Krow[kk * 8 + q];
                uint32_t b1 = Krow[kk * 8 + q + 4];
                mma_tf32(s[nt], aq[kk][0], aq[kk][1], aq[kk][2], aq[kk][3],
                         b0, b1);
            }
        }

        // --- causal mask on diagonal tile ---
        if (kt == qt) {
            const int r0 = prow0, r1 = prow0 + 8;
#pragma unroll
            for (int nt = 0; nt < 8; nt++) {
                int c0 = nt * 8 + 2 * q, c1 = c0 + 1;
                if (c0 > r0) s[nt][0] = -1e30f;
                if (c1 > r0) s[nt][1] = -1e30f;
                if (c0 > r1) s[nt][2] = -1e30f;
                if (c1 > r1) s[nt][3] = -1e30f;
            }
        }

        // --- online softmax (rows live in quads: shfl xor 1,2) ---
        float ml0 = -1e30f, ml1 = -1e30f;
#pragma unroll
        for (int nt = 0; nt < 8; nt++) {
            ml0 = fmaxf(ml0, fmaxf(s[nt][0], s[nt][1]));
            ml1 = fmaxf(ml1, fmaxf(s[nt][2], s[nt][3]));
        }
        ml0 = fmaxf(ml0, __shfl_xor_sync(0xffffffffu, ml0, 1));
        ml0 = fmaxf(ml0, __shfl_xor_sync(0xffffffffu, ml0, 2));
        ml1 = fmaxf(ml1, __shfl_xor_sync(0xffffffffu, ml1, 1));
        ml1 = fmaxf(ml1, __shfl_xor_sync(0xffffffffu, ml1, 2));
        const float mn0 = fmaxf(m0, ml0), mn1 = fmaxf(m1, ml1);
        const float sc0 = __expf(m0 - mn0), sc1 = __expf(m1 - mn1);
        float ls0 = 0.0f, ls1 = 0.0f;
#pragma unroll
        for (int nt = 0; nt < 8; nt++) {
            s[nt][0] = __expf(s[nt][0] - mn0);
            s[nt][1] = __expf(s[nt][1] - mn0);
            s[nt][2] = __expf(s[nt][2] - mn1);
            s[nt][3] = __expf(s[nt][3] - mn1);
            ls0 += s[nt][0] + s[nt][1];
            ls1 += s[nt][2] + s[nt][3];
        }
        ls0 += __shfl_xor_sync(0xffffffffu, ls0, 1);
        ls0 += __shfl_xor_sync(0xffffffffu, ls0, 2);
        ls1 += __shfl_xor_sync(0xffffffffu, ls1, 1);
        ls1 += __shfl_xor_sync(0xffffffffu, ls1, 2);
        l0 = l0 * sc0 + ls0; m0 = mn0;
        l1 = l1 * sc1 + ls1; m1 = mn1;
#pragma unroll
        for (int nt = 0; nt < 8; nt++) {
            o[nt][0] *= sc0; o[nt][1] *= sc0;
            o[nt][2] *= sc1; o[nt][3] *= sc1;
        }

        // --- P to its own buffer (no block barrier needed), STS.64 pairs ---
#pragma unroll
        for (int nt = 0; nt < 8; nt++) {
            uint2 p01, p23;
            p01.x = f2tf32(s[nt][0]); p01.y = f2tf32(s[nt][1]);
            p23.x = f2tf32(s[nt][2]); p23.y = f2tf32(s[nt][3]);
            *(uint2*)&Ps[prow0 * SKP + nt * 8 + 2 * q] = p01;
            *(uint2*)&Ps[(prow0 + 8) * SKP + nt * 8 + 2 * q] = p23;
        }
        __syncwarp();

        // --- O += P V : B[k=j][n=d] = V[j][d] from swizzled layout ---
#pragma unroll
        for (int kk = 0; kk < 8; kk++) {
            uint32_t p0 = Ps[prow0 * SKP + kk * 8 + q];
            uint32_t p1 = Ps[(prow0 + 8) * SKP + kk * 8 + q];
            uint32_t p2 = Ps[prow0 * SKP + kk * 8 + q + 4];
            uint32_t p3 = Ps[(prow0 + 8) * SKP + kk * 8 + q + 4];
#pragma unroll
            for (int nt = 0; nt < 8; nt++) {
                int nx = (nt * 8 + g) ^ (8 * q);
                uint32_t b0 = Vs[(kk * 8 + q) * SKV + nx];
                uint32_t b1 = Vs[(kk * 8 + q + 4) * SKV + nx];
                mma_tf32(o[nt], p0, p1, p2, p3, b0, b1);
            }
        }
        __syncthreads();   // protect Ks/Vs before next tile load
    }

    // --- normalize and write ---
    const float i0 = 1.0f / l0, i1 = 1.0f / l1;
    float* Z0 = Z + ((size_t)(b * NN + qt * AQT + prow0)) * HD + h * DD;
    float* Z1 = Z0 + (size_t)8 * HD;
#pragma unroll
    for (int nt = 0; nt < 8; nt++) {
        int c = nt * 8 + 2 * q;
        *(float2*)&Z0[c] = make_float2(o[nt][0] * i0, o[nt][1] * i0);
        *(float2*)&Z1[c] = make_float2(o[nt][2] * i1, o[nt][3] * i1);
    }
}

// ---------------------------------------------------------------------------
// Launch
// ---------------------------------------------------------------------------
extern "C" void kernel_launch(void* const* d_in, const int* in_sizes, int n_in,
                              void* d_out, int out_size)
{
    const float* X  = (const float*)d_in[0];  // (B,N,E)
    const float* Wq = (const float*)d_in[1];  // (E, H*D)
    const float* Wk = (const float*)d_in[2];  // (E, D)
    const float* Wv = (const float*)d_in[3];  // (E, D)
    const float* Wo = (const float*)d_in[4];  // (H*D, H*D)
    const float* bo = (const float*)d_in[5];  // (H*D,)
    float* out = (float*)d_out;               // (B,N,H*D)

    float *pQ, *pK, *pV, *pZ;
    cudaGetSymbolAddress((void**)&pQ, g_Q);
    cudaGetSymbolAddress((void**)&pK, g_K);
    cudaGetSymbolAddress((void**)&pV, g_V);
    cudaGetSymbolAddress((void**)&pZ, g_Z);

    // Opt into >48KB dynamic smem (host-side attribute, not captured)
    cudaFuncSetAttribute(tf32_gemm_kernel<false>,
                         cudaFuncAttributeMaxDynamicSharedMemorySize, GEMM_SMEM);
    cudaFuncSetAttribute(tf32_gemm_kernel<true>,
                         cudaFuncAttributeMaxDynamicSharedMemorySize, GEMM_SMEM);
    cudaFuncSetAttribute(mqa_attn_tc_kernel,
                         cudaFuncAttributeMaxDynamicSharedMemorySize, ATTN_SMEM);

    // K / V projections fused: z=0 -> K, z=1 -> V (128 blocks)
    sgemm_kv_kernel<64, 64, 16, 4, 4>
        <<<dim3(1, MTOT / 64, 2), 256>>>(X, Wk, pK, MTOT, DD, EE, Wv, pV);

    // Q projection: tf32 tensor cores, double-buffered
    tf32_gemm_kernel<false>
        <<<dim3(HD / GBN, MTOT / GBM), 256, GEMM_SMEM>>>(X, Wq, nullptr, pQ,
                                                         MTOT, HD, EE);

    // Tensor-core causal MQA attention, heavy-first 1D grid (LPT)
    mqa_attn_tc_kernel<<<ANQT * BB * HH, 128, ATTN_SMEM>>>(pQ, pK, pV, pZ);

    // Output projection + bias: tf32 tensor cores, double-buffered
    tf32_gemm_kernel<true>
        <<<dim3(HD / GBN, MTOT / GBM), 256, GEMM_SMEM>>>(pZ, Wo, bo, out,
                                                         MTOT, HD, HD);
}

// round 9
// speedup vs baseline: 6.0335x; 1.0808x over previous
#include <cuda_runtime.h>
#include <cuda_bf16.h>
#include <math.h>
#include <stdint.h>

// Problem constants
#define BB 2
#define NN 2048
#define EE 1024
#define HH 16
#define DD 64
#define HD 1024            // H*D
#define MTOT 4096          // B*N

// ---------------------------------------------------------------------------
// Scratch (static device globals — no allocation allowed)
// ---------------------------------------------------------------------------
__device__ float g_Q[MTOT * HD];   // (B*N, H*D)  tf32-rounded
__device__ float g_K[MTOT * DD];   // (B*N, D)    tf32-rounded
__device__ float g_V[MTOT * DD];   // (B*N, D)    tf32-rounded
__device__ float g_Z[MTOT * HD];   // (B*N, H*D)  tf32-rounded
__device__ float g_Xr[MTOT * EE];  // tf32-rounded X
__device__ float g_Wqr[EE * HD];   // tf32-rounded Wq
__device__ float g_Wor[HD * HD];   // tf32-rounded Wo

// ---------------------------------------------------------------------------
// Helpers
// ---------------------------------------------------------------------------
__device__ __forceinline__ uint32_t f2tf32(float x) {
    uint32_t r;
    asm("cvt.rna.tf32.f32 %0, %1;" : "=r"(r) : "f"(x));
    return r;
}

__device__ __forceinline__ float ex2f(float x) {
    float y;
    asm("ex2.approx.f32 %0, %1;" : "=f"(y) : "f"(x));
    return y;
}

__device__ __forceinline__ void mma_tf32(float c[4], uint32_t a0, uint32_t a1,
                                         uint32_t a2, uint32_t a3,
                                         uint32_t b0, uint32_t b1) {
    asm volatile(
        "mma.sync.aligned.m16n8k8.row.col.f32.tf32.tf32.f32 "
        "{%0,%1,%2,%3}, {%4,%5,%6,%7}, {%8,%9}, {%0,%1,%2,%3};"
        : "+f"(c[0]), "+f"(c[1]), "+f"(c[2]), "+f"(c[3])
        : "r"(a0), "r"(a1), "r"(a2), "r"(a3), "r"(b0), "r"(b1));
}

__device__ __forceinline__ void cpa16(uint32_t s, const float* g) {
    asm volatile("cp.async.cg.shared.global [%0], [%1], 16;" :: "r"(s), "l"(g));
}

// ---------------------------------------------------------------------------
// Elementwise tf32 pre-rounding pass (cvt.rna), float4-vectorized
// ---------------------------------------------------------------------------
__global__ void preround_kernel(const float4* __restrict__ src,
                                float4* __restrict__ dst, int n4)
{
    int i = blockIdx.x * blockDim.x + threadIdx.x;
    if (i < n4) {
        float4 v = src[i];
        float4 o;
        o.x = __uint_as_float(f2tf32(v.x));
        o.y = __uint_as_float(f2tf32(v.y));
        o.z = __uint_as_float(f2tf32(v.z));
        o.w = __uint_as_float(f2tf32(v.w));
        dst[i] = o;
    }
}

// ---------------------------------------------------------------------------
// tf32 tensor-core GEMM, cp.async 3-stage pipeline, inputs pre-rounded.
// C[M,N] = A[M,K] @ B[K,N] (+ bias) (optionally tf32-round output).
// A smem: natural [m][k], stride 36; B smem: XOR swizzle [k][n^8(k&3)].
// No inner-loop cvts; fragments feed mma as raw (pre-rounded) bits.
// ---------------------------------------------------------------------------
#define GBM 128
#define GBN 128
#define GBK 32
#define LDA 36
#define ABUF (GBM * LDA)      // 4608 words
#define BBUF (GBK * 128)      // 4096 words
#define STAGEW (ABUF + BBUF)  // 8704 words per stage
#define GEMM_SMEM (STAGEW * 3 * 4)   // 104448 bytes

template <bool BIAS, bool ROUND>
__global__ __launch_bounds__(256, 2)
void tf32_gemm_kernel(const float* __restrict__ A, const float* __restrict__ B,
                      const float* __restrict__ bias, float* __restrict__ C,
                      int M, int N, int K)
{
    extern __shared__ uint32_t sm[];
    const uint32_t smemBase = (uint32_t)__cvta_generic_to_shared(sm);

    const int tid  = threadIdx.x;
    const int lane = tid & 31;
    const int w    = tid >> 5;
    const int wm   = w & 1;
    const int wn   = w >> 1;
    const int g    = lane >> 2;
    const int q    = lane & 3;
    const int row0 = blockIdx.y * GBM;
    const int col0 = blockIdx.x * GBN;

    // Per-thread staging maps (4 x 16B for A, 4 x 16B for B)
    int aoffw[4], boffw[4];
    const float* aptr[4];
    const float* bptr[4];
#pragma unroll
    for (int i = 0; i < 4; i++) {
        int idx = tid + i * 256;
        int r = idx >> 3, cc = (idx & 7) * 4;
        aoffw[i] = r * LDA + cc;
        aptr[i]  = A + (size_t)(row0 + r) * K + cc;
        int br = idx >> 5, bc = (idx & 31) * 4;
        boffw[i] = (br << 7) + (bc ^ (8 * (br & 3)));
        bptr[i]  = B + (size_t)br * N + col0 + bc;
    }

    float c[4][4][4];
#pragma unroll
    for (int mi = 0; mi < 4; mi++)
#pragma unroll
        for (int ni = 0; ni < 4; ni++)
#pragma unroll
            for (int k = 0; k < 4; k++) c[mi][ni][k] = 0.0f;

    const int NT = K / GBK;

    // Issue tile kt into stage st
    auto issue = [&](int st, int kt) {
        uint32_t sA = smemBase + (uint32_t)(st * STAGEW) * 4;
        uint32_t sB = sA + ABUF * 4;
#pragma unroll
        for (int i = 0; i < 4; i++)
            cpa16(sA + aoffw[i] * 4, aptr[i] + kt * GBK);
#pragma unroll
        for (int i = 0; i < 4; i++)
            cpa16(sB + boffw[i] * 4, bptr[i] + (size_t)kt * GBK * N);
        asm volatile("cp.async.commit_group;");
    };

    issue(0, 0);
    issue(1, 1);

    for (int kt = 0; kt < NT; kt++) {
        if (kt == NT - 1) asm volatile("cp.async.wait_group 0;");
        else              asm volatile("cp.async.wait_group 1;");
        __syncthreads();
        if (kt + 2 < NT) issue((kt + 2) % 3, kt + 2);

        const uint32_t* Ac = sm + (kt % 3) * STAGEW;
        const uint32_t* Bc = Ac + ABUF;

#pragma unroll
        for (int kk = 0; kk < GBK; kk += 8) {
            uint32_t af[4][4];
#pragma unroll
            for (int mi = 0; mi < 4; mi++) {
                int r = wm * 64 + mi * 16 + g;
                af[mi][0] = Ac[r * LDA + kk + q];
                af[mi][1] = Ac[(r + 8) * LDA + kk + q];
                af[mi][2] = Ac[r * LDA + kk + 4 + q];
                af[mi][3] = Ac[(r + 8) * LDA + kk + 4 + q];
            }
#pragma unroll
            for (int ni = 0; ni < 4; ni++) {
                int n  = wn * 32 + ni * 8 + g;
                int nx = n ^ (8 * q);
                uint32_t b0 = Bc[((kk + q) << 7) + nx];
                uint32_t b1 = Bc[((kk + q + 4) << 7) + nx];
#pragma unroll
                for (int mi = 0; mi < 4; mi++)
                    mma_tf32(c[mi][ni], af[mi][0], af[mi][1], af[mi][2], af[mi][3],
                             b0, b1);
            }
        }
    }

#pragma unroll
    for (int mi = 0; mi < 4; mi++) {
        int row = row0 + wm * 64 + mi * 16 + g;
#pragma unroll
        for (int ni = 0; ni < 4; ni++) {
            int col = col0 + wn * 32 + ni * 8 + 2 * q;
            float2 v0 = make_float2(c[mi][ni][0], c[mi][ni][1]);
            float2 v1 = make_float2(c[mi][ni][2], c[mi][ni][3]);
            if (BIAS) {
                float2 bv = *(const float2*)&bias[col];
                v0.x += bv.x; v0.y += bv.y;
                v1.x += bv.x; v1.y += bv.y;
            }
            if (ROUND) {
                v0.x = __uint_as_float(f2tf32(v0.x));
                v0.y = __uint_as_float(f2tf32(v0.y));
                v1.x = __uint_as_float(f2tf32(v1.x));
                v1.y = __uint_as_float(f2tf32(v1.y));
            }
            *(float2*)&C[(size_t)row * N + col] = v0;
            *(float2*)&C[(size_t)(row + 8) * N + col] = v1;
        }
    }
}

// ---------------------------------------------------------------------------
// SIMT SGEMM, fused K/V projections. fp32 compute, tf32-rounded outputs.
// ---------------------------------------------------------------------------
template <int BM, int BN, int BK, int TM, int TN>
__global__ __launch_bounds__((BM / TM) * (BN / TN))
void sgemm_kv_kernel(const float* __restrict__ A, const float* __restrict__ B,
                     float* __restrict__ C, int M, int N, int K,
                     const float* __restrict__ B2, float* __restrict__ C2)
{
    constexpr int THREADS = (BM / TM) * (BN / TN);
    __shared__ float As[BK][BM];
    __shared__ float Bs[BK][BN];

    if (blockIdx.z) { B = B2; C = C2; }

    const int tid  = threadIdx.x;
    const int tx   = tid % (BN / TN);
    const int ty   = tid / (BN / TN);
    const int row0 = blockIdx.y * BM;
    const int col0 = blockIdx.x * BN;

    float acc[TM][TN];
#pragma unroll
    for (int i = 0; i < TM; i++)
#pragma unroll
        for (int j = 0; j < TN; j++) acc[i][j] = 0.0f;

    constexpr int A_VECS     = BM * BK / 4 / THREADS;
    constexpr int B_VECS     = BK * BN / 4 / THREADS;
    constexpr int A_ROW_VECS = BK / 4;
    constexpr int B_ROW_VECS = BN / 4;

    for (int k0 = 0; k0 < K; k0 += BK) {
#pragma unroll
        for (int i = 0; i < A_VECS; i++) {
            int idx = tid + i * THREADS;
            int r   = idx / A_ROW_VECS;
            int cc  = (idx % A_ROW_VECS) * 4;
            float4 v = *(const float4*)&A[(size_t)(row0 + r) * K + k0 + cc];
            As[cc + 0][r] = v.x;
            As[cc + 1][r] = v.y;
            As[cc + 2][r] = v.z;
            As[cc + 3][r] = v.w;
        }
#pragma unroll
        for (int i = 0; i < B_VECS; i++) {
            int idx = tid + i * THREADS;
            int r   = idx / B_ROW_VECS;
            int cc  = (idx % B_ROW_VECS) * 4;
            *(float4*)&Bs[r][cc] =
                *(const float4*)&B[(size_t)(k0 + r) * N + col0 + cc];
        }
        __syncthreads();

#pragma unroll
        for (int kk = 0; kk < BK; kk++) {
            float ra[TM], rb[TN];
#pragma unroll
            for (int i = 0; i < TM; i++) ra[i] = As[kk][ty * TM + i];
#pragma unroll
            for (int j = 0; j < TN; j++) rb[j] = Bs[kk][tx * TN + j];
#pragma unroll
            for (int i = 0; i < TM; i++)
#pragma unroll
                for (int j = 0; j < TN; j++)
                    acc[i][j] = fmaf(ra[i], rb[j], acc[i][j]);
        }
        __syncthreads();
    }

#pragma unroll
    for (int i = 0; i < TM; i++) {
        int row = row0 + ty * TM + i;
#pragma unroll
        for (int j = 0; j < TN; j += 4) {
            int col = col0 + tx * TN + j;
            float4 v;
            v.x = __uint_as_float(f2tf32(acc[i][j + 0]));
            v.y = __uint_as_float(f2tf32(acc[i][j + 1]));
            v.z = __uint_as_float(f2tf32(acc[i][j + 2]));
            v.w = __uint_as_float(f2tf32(acc[i][j + 3]));
            *(float4*)&C[(size_t)row * N + col] = v;
        }
    }
}

// ---------------------------------------------------------------------------
// Tensor-core causal MQA flash attention. Inputs pre-rounded tf32 -> raw-bit
// smem copies, no inner-loop cvts. Softmax in base-2 (ex2). Outputs rounded.
// K smem natural [j][d] (stride 68); V XOR-swizzled [j][d^8(j&3)] (stride 64);
// P separate buffer [i][j] (stride 68).
// ---------------------------------------------------------------------------
#define AQT 64           // query rows per block
#define ANQT (NN / AQT)  // 32 query tiles per (b,h)
#define SKK 68
#define SKV 64
#define SKP 68
#define ATTN_SMEM ((AQT * SKK + AQT * SKV + AQT * SKP) * 4)   // 51200 bytes

__global__ __launch_bounds__(128, 3)
void mqa_attn_tc_kernel(const float* __restrict__ Q,
                        const float* __restrict__ K,
                        const float* __restrict__ Vin,
                        float* __restrict__ Z)
{
    extern __shared__ uint32_t dsm[];
    uint32_t* Ks = dsm;                         // [64][68]
    uint32_t* Vs = dsm + AQT * SKK;             // [64][64] swizzled
    uint32_t* Ps = dsm + AQT * SKK + AQT * SKV; // [64][68]

    const int wid  = blockIdx.x;
    const int qt   = (ANQT - 1) - (wid >> 5);   // heavy-first (LPT)
    const int bh   = wid & 31;
    const int b    = bh >> 4;
    const int h    = bh & 15;
    const int tid  = threadIdx.x;
    const int lane = tid & 31;
    const int wrp  = tid >> 5;
    const int g    = lane >> 2;
    const int q    = lane & 3;

    // Q fragments, scaled by log2(e)/sqrt(D) (base-2 softmax), re-rounded
    const float QS = 0.125f * 1.4426950408889634f;
    uint32_t aq[8][4];
    const float* Qb = Q + ((size_t)(b * NN + qt * AQT + wrp * 16)) * HD + h * DD;
#pragma unroll
    for (int t = 0; t < 8; t++) {
        aq[t][0] = f2tf32(Qb[(size_t)g * HD       + t * 8 + q    ] * QS);
        aq[t][1] = f2tf32(Qb[(size_t)(g + 8) * HD + t * 8 + q    ] * QS);
        aq[t][2] = f2tf32(Qb[(size_t)g * HD       + t * 8 + q + 4] * QS);
        aq[t][3] = f2tf32(Qb[(size_t)(g + 8) * HD + t * 8 + q + 4] * QS);
    }

    float o[8][4];
#pragma unroll
    for (int nt = 0; nt < 8; nt++)
#pragma unroll
        for (int k = 0; k < 4; k++) o[nt][k] = 0.0f;
    float m0 = -1e30f, m1 = -1e30f, l0 = 0.0f, l1 = 0.0f;

    const int prow0 = wrp * 16 + g;

    for (int kt = 0; kt <= qt; kt++) {
        // --- cooperative K / V tile copy (raw pre-rounded bits) ---
        const uint4* Kg = (const uint4*)(K   + ((size_t)(b * NN + kt * 64)) * DD);
        const uint4* Vg = (const uint4*)(Vin + ((size_t)(b * NN + kt * 64)) * DD);
#pragma unroll
        for (int s8 = 0; s8 < 8; s8++) {
            int v = tid + s8 * 128;
            int j = v >> 4, c = (v & 15) * 4;
            *(uint4*)&Ks[j * SKK + c] = Kg[v];
            *(uint4*)&Vs[j * SKV + (c ^ (8 * (j & 3)))] = Vg[v];
        }
        __syncthreads();

        // --- S = Q K^T (scores in log2 domain) ---
        float s[8][4];
#pragma unroll
        for (int nt = 0; nt < 8; nt++) {
            s[nt][0] = s[nt][1] = s[nt][2] = s[nt][3] = 0.0f;
            const uint32_t* Krow = Ks + (nt * 8 + g) * SKK;
#pragma unroll
            for (int kk = 0; kk < 8; kk++) {
                uint32_t b0 = Krow[kk * 8 + q];
                uint32_t b1 = Krow[kk * 8 + q + 4];
                mma_tf32(s[nt], aq[kk][0], aq[kk][1], aq[kk][2], aq[kk][3],
                         b0, b1);
            }
        }

        // --- causal mask on diagonal tile ---
        if (kt == qt) {
            const int r0 = prow0, r1 = prow0 + 8;
#pragma unroll
            for (int nt = 0; nt < 8; nt++) {
                int c0 = nt * 8 + 2 * q, c1 = c0 + 1;
                if (c0 > r0) s[nt][0] = -1e30f;
                if (c1 > r0) s[nt][1] = -1e30f;
                if (c0 > r1) s[nt][2] = -1e30f;
                if (c1 > r1) s[nt][3] = -1e30f;
            }
        }

        // --- online softmax (base-2), quad shuffles for row reductions ---
        float ml0 = -1e30f, ml1 = -1e30f;
#pragma unroll
        for (int nt = 0; nt < 8; nt++) {
            ml0 = fmaxf(ml0, fmaxf(s[nt][0], s[nt][1]));
            ml1 = fmaxf(ml1, fmaxf(s[nt][2], s[nt][3]));
        }
        ml0 = fmaxf(ml0, __shfl_xor_sync(0xffffffffu, ml0, 1));
        ml0 = fmaxf(ml0, __shfl_xor_sync(0xffffffffu, ml0, 2));
        ml1 = fmaxf(ml1, __shfl_xor_sync(0xffffffffu, ml1, 1));
        ml1 = fmaxf(ml1, __shfl_xor_sync(0xffffffffu, ml1, 2));
        const float mn0 = fmaxf(m0, ml0), mn1 = fmaxf(m1, ml1);
        const float sc0 = ex2f(m0 - mn0), sc1 = ex2f(m1 - mn1);
        float ls0 = 0.0f, ls1 = 0.0f;
#pragma unroll
        for (int nt = 0; nt < 8; nt++) {
            s[nt][0] = ex2f(s[nt][0] - mn0);
            s[nt][1] = ex2f(s[nt][1] - mn0);
            s[nt][2] = ex2f(s[nt][2] - mn1);
            s[nt][3] = ex2f(s[nt][3] - mn1);
            ls0 += s[nt][0] + s[nt][1];
            ls1 += s[nt][2] + s[nt][3];
        }
        ls0 += __shfl_xor_sync(0xffffffffu, ls0, 1);
        ls0 += __shfl_xor_sync(0xffffffffu, ls0, 2);
        ls1 += __shfl_xor_sync(0xffffffffu, ls1, 1);
        ls1 += __shfl_xor_sync(0xffffffffu, ls1, 2);
        l0 = l0 * sc0 + ls0; m0 = mn0;
        l1 = l1 * sc1 + ls1; m1 = mn1;
#pragma unroll
        for (int nt = 0; nt < 8; nt++) {
            o[nt][0] *= sc0; o[nt][1] *= sc0;
            o[nt][2] *= sc1; o[nt][3] *= sc1;
        }

        // --- P to its own buffer, STS.64 pairs (cvt.rna kept for P) ---
#pragma unroll
        for (int nt = 0; nt < 8; nt++) {
            uint2 p01, p23;
            p01.x = f2tf32(s[nt][0]); p01.y = f2tf32(s[nt][1]);
            p23.x = f2tf32(s[nt][2]); p23.y = f2tf32(s[nt][3]);
            *(uint2*)&Ps[prow0 * SKP + nt * 8 + 2 * q] = p01;
            *(uint2*)&Ps[(prow0 + 8) * SKP + nt * 8 + 2 * q] = p23;
        }
        __syncwarp();

        // --- O += P V ---
#pragma unroll
        for (int kk = 0; kk < 8; kk++) {
            uint32_t p0 = Ps[prow0 * SKP + kk * 8 + q];
            uint32_t p1 = Ps[(prow0 + 8) * SKP + kk * 8 + q];
            uint32_t p2 = Ps[prow0 * SKP + kk * 8 + q + 4];
            uint32_t p3 = Ps[(prow0 + 8) * SKP + kk * 8 + q + 4];
#pragma unroll
            for (int nt = 0; nt < 8; nt++) {
                int nx = (nt * 8 + g) ^ (8 * q);
                uint32_t b0 = Vs[(kk * 8 + q) * SKV + nx];
                uint32_t b1 = Vs[(kk * 8 + q + 4) * SKV + nx];
                mma_tf32(o[nt], p0, p1, p2, p3, b0, b1);
            }
        }
        __syncthreads();   // protect Ks/Vs before next tile load
    }

    // --- normalize, round to tf32 (oproj consumes raw bits), write ---
    const float i0 = 1.0f / l0, i1 = 1.0f / l1;
    float* Z0 = Z + ((size_t)(b * NN + qt * AQT + prow0)) * HD + h * DD;
    float* Z1 = Z0 + (size_t)8 * HD;
#pragma unroll
    for (int nt = 0; nt < 8; nt++) {
        int c = nt * 8 + 2 * q;
        *(float2*)&Z0[c] = make_float2(__uint_as_float(f2tf32(o[nt][0] * i0)),
                                       __uint_as_float(f2tf32(o[nt][1] * i0)));
        *(float2*)&Z1[c] = make_float2(__uint_as_float(f2tf32(o[nt][2] * i1)),
                                       __uint_as_float(f2tf32(o[nt][3] * i1)));
    }
}

// ---------------------------------------------------------------------------
// Launch
// ---------------------------------------------------------------------------
extern "C" void kernel_launch(void* const* d_in, const int* in_sizes, int n_in,
                              void* d_out, int out_size)
{
    const float* X  = (const float*)d_in[0];  // (B,N,E)
    const float* Wq = (const float*)d_in[1];  // (E, H*D)
    const float* Wk = (const float*)d_in[2];  // (E, D)
    const float* Wv = (const float*)d_in[3];  // (E, D)
    const float* Wo = (const float*)d_in[4];  // (H*D, H*D)
    const float* bo = (const float*)d_in[5];  // (H*D,)
    float* out = (float*)d_out;               // (B,N,H*D)

    float *pQ, *pK, *pV, *pZ, *pXr, *pWqr, *pWor;
    cudaGetSymbolAddress((void**)&pQ,  g_Q);
    cudaGetSymbolAddress((void**)&pK,  g_K);
    cudaGetSymbolAddress((void**)&pV,  g_V);
    cudaGetSymbolAddress((void**)&pZ,  g_Z);
    cudaGetSymbolAddress((void**)&pXr, g_Xr);
    cudaGetSymbolAddress((void**)&pWqr, g_Wqr);
    cudaGetSymbolAddress((void**)&pWor, g_Wor);

    // >48KB dynamic smem opt-in (host-side attributes, not captured)
    cudaFuncSetAttribute(tf32_gemm_kernel<false, true>,
                         cudaFuncAttributeMaxDynamicSharedMemorySize, GEMM_SMEM);
    cudaFuncSetAttribute(tf32_gemm_kernel<true, false>,
                         cudaFuncAttributeMaxDynamicSharedMemorySize, GEMM_SMEM);
    cudaFuncSetAttribute(mqa_attn_tc_kernel,
                         cudaFuncAttributeMaxDynamicSharedMemorySize, ATTN_SMEM);

    // Pre-round X, Wq, Wo to tf32 bit patterns
    preround_kernel<<<(MTOT * EE / 4 + 255) / 256, 256>>>((const float4*)X,
                                                          (float4*)pXr,
                                                          MTOT * EE / 4);
    preround_kernel<<<(EE * HD / 4 + 255) / 256, 256>>>((const float4*)Wq,
                                                        (float4*)pWqr,
                                                        EE * HD / 4);
    preround_kernel<<<(HD * HD / 4 + 255) / 256, 256>>>((const float4*)Wo,
                                                        (float4*)pWor,
                                                        HD * HD / 4);

    // K / V projections fused (fp32 SIMT, rounded outputs)
    sgemm_kv_kernel<64, 64, 16, 4, 4>
        <<<dim3(1, MTOT / 64, 2), 256>>>(X, Wk, pK, MTOT, DD, EE, Wv, pV);

    // Q projection (rounded output for attention)
    tf32_gemm_kernel<false, true>
        <<<dim3(HD / GBN, MTOT / GBM), 256, GEMM_SMEM>>>(pXr, pWqr, nullptr, pQ,
                                                         MTOT, HD, EE);

    // Tensor-core causal MQA attention, heavy-first 1D grid (LPT)
    mqa_attn_tc_kernel<<<ANQT * BB * HH, 128, ATTN_SMEM>>>(pQ, pK, pV, pZ);

    // Output projection + bias (full fp32 output)
    tf32_gemm_kernel<true, false>
        <<<dim3(HD / GBN, MTOT / GBM), 256, GEMM_SMEM>>>(pZ, pWor, bo, out,
                                                         MTOT, HD, HD);
}

// round 11
// speedup vs baseline: 7.5079x; 1.2444x over previous
#include <cuda_runtime.h>
#include <cuda_bf16.h>
#include <math.h>
#include <stdint.h>

// Problem constants
#define BB 2
#define NN 2048
#define EE 1024
#define HH 16
#define DD 64
#define HD 1024            // H*D
#define MTOT 4096          // B*N
#define NQKV 1152          // HD + 2*DD  (fused QKV output columns)

// ---------------------------------------------------------------------------
// Scratch (static device globals — no allocation allowed)
// ---------------------------------------------------------------------------
__device__ float g_QKV[MTOT * NQKV]; // (B*N, 1152): Q | K | V  (tf32-rounded)
__device__ float g_Z[MTOT * HD];     // (B*N, H*D)  tf32-rounded
__device__ float g_Xr[MTOT * EE];    // tf32-rounded X
__device__ float g_Wall[EE * NQKV];  // tf32-rounded [Wq | Wk | Wv]
__device__ float g_Wor[HD * HD];     // tf32-rounded Wo

// ---------------------------------------------------------------------------
// Helpers
// ---------------------------------------------------------------------------
__device__ __forceinline__ uint32_t f2tf32(float x) {
    uint32_t r;
    asm("cvt.rna.tf32.f32 %0, %1;" : "=r"(r) : "f"(x));
    return r;
}

__device__ __forceinline__ float ex2f(float x) {
    float y;
    asm("ex2.approx.f32 %0, %1;" : "=f"(y) : "f"(x));
    return y;
}

__device__ __forceinline__ void mma_tf32(float c[4], uint32_t a0, uint32_t a1,
                                         uint32_t a2, uint32_t a3,
                                         uint32_t b0, uint32_t b1) {
    asm volatile(
        "mma.sync.aligned.m16n8k8.row.col.f32.tf32.tf32.f32 "
        "{%0,%1,%2,%3}, {%4,%5,%6,%7}, {%8,%9}, {%0,%1,%2,%3};"
        : "+f"(c[0]), "+f"(c[1]), "+f"(c[2]), "+f"(c[3])
        : "r"(a0), "r"(a1), "r"(a2), "r"(a3), "r"(b0), "r"(b1));
}

__device__ __forceinline__ void cpa16(uint32_t s, const float* g) {
    asm volatile("cp.async.cg.shared.global [%0], [%1], 16;" :: "r"(s), "l"(g));
}

// ---------------------------------------------------------------------------
// Elementwise tf32 pre-rounding pass (cvt.rna), float4-vectorized
// ---------------------------------------------------------------------------
__global__ void preround_kernel(const float4* __restrict__ src,
                                float4* __restrict__ dst, int n4)
{
    int i = blockIdx.x * blockDim.x + threadIdx.x;
    if (i < n4) {
        float4 v = src[i];
        float4 o;
        o.x = __uint_as_float(f2tf32(v.x));
        o.y = __uint_as_float(f2tf32(v.y));
        o.z = __uint_as_float(f2tf32(v.z));
        o.w = __uint_as_float(f2tf32(v.w));
        dst[i] = o;
    }
}

// Build W_all[E][1152] = [Wq | Wk | Wv], tf32-rounded
__global__ void build_wall_kernel(const float* __restrict__ Wq,
                                  const float* __restrict__ Wk,
                                  const float* __restrict__ Wv,
                                  float* __restrict__ Wall)
{
    int i = blockIdx.x * blockDim.x + threadIdx.x;   // over E*1152/4
    if (i >= EE * NQKV / 4) return;
    int r  = i / (NQKV / 4);
    int cc = (i % (NQKV / 4)) * 4;
    const float* src;
    if (cc < HD)            src = Wq + (size_t)r * HD + cc;
    else if (cc < HD + DD)  src = Wk + (size_t)r * DD + (cc - HD);
    else                    src = Wv + (size_t)r * DD + (cc - HD - DD);
    float4 v = *(const float4*)src;
    float4 o;
    o.x = __uint_as_float(f2tf32(v.x));
    o.y = __uint_as_float(f2tf32(v.y));
    o.z = __uint_as_float(f2tf32(v.z));
    o.w = __uint_as_float(f2tf32(v.w));
    *(float4*)&Wall[(size_t)r * NQKV + cc] = o;
}

// ---------------------------------------------------------------------------
// tf32 tensor-core GEMM, cp.async 3-stage pipeline, inputs pre-rounded.
// C[M,N] = A[M,K] @ B[K,N] (+ bias) (optionally tf32-round output).
// A smem: natural [m][k], stride 36; B smem: XOR swizzle [k][n^8(k&3)].
// ---------------------------------------------------------------------------
#define GBM 128
#define GBN 128
#define GBK 32
#define LDA 36
#define ABUF (GBM * LDA)      // 4608 words
#define BBUF (GBK * 128)      // 4096 words
#define STAGEW (ABUF + BBUF)  // 8704 words per stage
#define GEMM_SMEM (STAGEW * 3 * 4)   // 104448 bytes

template <bool BIAS, bool ROUND>
__global__ __launch_bounds__(256, 2)
void tf32_gemm_kernel(const float* __restrict__ A, const float* __restrict__ B,
                      const float* __restrict__ bias, float* __restrict__ C,
                      int M, int N, int K)
{
    extern __shared__ uint32_t sm[];
    const uint32_t smemBase = (uint32_t)__cvta_generic_to_shared(sm);

    const int tid  = threadIdx.x;
    const int lane = tid & 31;
    const int w    = tid >> 5;
    const int wm   = w & 1;
    const int wn   = w >> 1;
    const int g    = lane >> 2;
    const int q    = lane & 3;
    const int row0 = blockIdx.y * GBM;
    const int col0 = blockIdx.x * GBN;

    // Per-thread staging maps (4 x 16B for A, 4 x 16B for B)
    int aoffw[4], boffw[4];
    const float* aptr[4];
    const float* bptr[4];
#pragma unroll
    for (int i = 0; i < 4; i++) {
        int idx = tid + i * 256;
        int r = idx >> 3, cc = (idx & 7) * 4;
        aoffw[i] = r * LDA + cc;
        aptr[i]  = A + (size_t)(row0 + r) * K + cc;
        int br = idx >> 5, bc = (idx & 31) * 4;
        boffw[i] = (br << 7) + (bc ^ (8 * (br & 3)));
        bptr[i]  = B + (size_t)br * N + col0 + bc;
    }

    float c[4][4][4];
#pragma unroll
    for (int mi = 0; mi < 4; mi++)
#pragma unroll
        for (int ni = 0; ni < 4; ni++)
#pragma unroll
            for (int k = 0; k < 4; k++) c[mi][ni][k] = 0.0f;

    const int NT = K / GBK;

    auto issue = [&](int st, int kt) {
        uint32_t sA = smemBase + (uint32_t)(st * STAGEW) * 4;
        uint32_t sB = sA + ABUF * 4;
#pragma unroll
        for (int i = 0; i < 4; i++)
            cpa16(sA + aoffw[i] * 4, aptr[i] + kt * GBK);
#pragma unroll
        for (int i = 0; i < 4; i++)
            cpa16(sB + boffw[i] * 4, bptr[i] + (size_t)kt * GBK * N);
        asm volatile("cp.async.commit_group;");
    };

    issue(0, 0);
    issue(1, 1);

    for (int kt = 0; kt < NT; kt++) {
        if (kt == NT - 1) asm volatile("cp.async.wait_group 0;");
        else              asm volatile("cp.async.wait_group 1;");
        __syncthreads();
        if (kt + 2 < NT) issue((kt + 2) % 3, kt + 2);

        const uint32_t* Ac = sm + (kt % 3) * STAGEW;
        const uint32_t* Bc = Ac + ABUF;

#pragma unroll
        for (int kk = 0; kk < GBK; kk += 8) {
            uint32_t af[4][4];
#pragma unroll
            for (int mi = 0; mi < 4; mi++) {
                int r = wm * 64 + mi * 16 + g;
                af[mi][0] = Ac[r * LDA + kk + q];
                af[mi][1] = Ac[(r + 8) * LDA + kk + q];
                af[mi][2] = Ac[r * LDA + kk + 4 + q];
                af[mi][3] = Ac[(r + 8) * LDA + kk + 4 + q];
            }
#pragma unroll
            for (int ni = 0; ni < 4; ni++) {
                int n  = wn * 32 + ni * 8 + g;
                int nx = n ^ (8 * q);
                uint32_t b0 = Bc[((kk + q) << 7) + nx];
                uint32_t b1 = Bc[((kk + q + 4) << 7) + nx];
#pragma unroll
                for (int mi = 0; mi < 4; mi++)
                    mma_tf32(c[mi][ni], af[mi][0], af[mi][1], af[mi][2], af[mi][3],
                             b0, b1);
            }
        }
    }

#pragma unroll
    for (int mi = 0; mi < 4; mi++) {
        int row = row0 + wm * 64 + mi * 16 + g;
#pragma unroll
        for (int ni = 0; ni < 4; ni++) {
            int col = col0 + wn * 32 + ni * 8 + 2 * q;
            float2 v0 = make_float2(c[mi][ni][0], c[mi][ni][1]);
            float2 v1 = make_float2(c[mi][ni][2], c[mi][ni][3]);
            if (BIAS) {
                float2 bv = *(const float2*)&bias[col];
                v0.x += bv.x; v0.y += bv.y;
                v1.x += bv.x; v1.y += bv.y;
            }
            if (ROUND) {
                v0.x = __uint_as_float(f2tf32(v0.x));
                v0.y = __uint_as_float(f2tf32(v0.y));
                v1.x = __uint_as_float(f2tf32(v1.x));
                v1.y = __uint_as_float(f2tf32(v1.y));
            }
            *(float2*)&C[(size_t)row * N + col] = v0;
            *(float2*)&C[(size_t)(row + 8) * N + col] = v1;
        }
    }
}

// ---------------------------------------------------------------------------
// Tensor-core causal MQA flash attention. Reads Q/K/V from fused QKV buffer
// (row stride 1152: Q at col 0 + h*64, K at col 1024, V at col 1088).
// K smem natural [j][d] (stride 68); V XOR-swizzled (stride 64); P buffer
// (stride 68). Base-2 softmax, no inner-loop cvts.
// ---------------------------------------------------------------------------
#define AQT 64           // query rows per block
#define ANQT (NN / AQT)  // 32 query tiles per (b,h)
#define SKK 68
#define SKV 64
#define SKP 68
#define ATTN_SMEM ((AQT * SKK + AQT * SKV + AQT * SKP) * 4)   // 51200 bytes

__global__ __launch_bounds__(128, 3)
void mqa_attn_tc_kernel(const float* __restrict__ QKV,
                        float* __restrict__ Z)
{
    extern __shared__ uint32_t dsm[];
    uint32_t* Ks = dsm;                         // [64][68]
    uint32_t* Vs = dsm + AQT * SKK;             // [64][64] swizzled
    uint32_t* Ps = dsm + AQT * SKK + AQT * SKV; // [64][68]

    const int wid  = blockIdx.x;
    const int qt   = (ANQT - 1) - (wid >> 5);   // heavy-first (LPT)
    const int bh   = wid & 31;
    const int b    = bh >> 4;
    const int h    = bh & 15;
    const int tid  = threadIdx.x;
    const int lane = tid & 31;
    const int wrp  = tid >> 5;
    const int g    = lane >> 2;
    const int q    = lane & 3;

    // Q fragments, scaled by log2(e)/sqrt(D) (base-2 softmax), re-rounded
    const float QS = 0.125f * 1.4426950408889634f;
    uint32_t aq[8][4];
    const float* Qb = QKV + (size_t)(b * NN + qt * AQT + wrp * 16) * NQKV + h * DD;
#pragma unroll
    for (int t = 0; t < 8; t++) {
        aq[t][0] = f2tf32(Qb[(size_t)g * NQKV       + t * 8 + q    ] * QS);
        aq[t][1] = f2tf32(Qb[(size_t)(g + 8) * NQKV + t * 8 + q    ] * QS);
        aq[t][2] = f2tf32(Qb[(size_t)g * NQKV       + t * 8 + q + 4] * QS);
        aq[t][3] = f2tf32(Qb[(size_t)(g + 8) * NQKV + t * 8 + q + 4] * QS);
    }

    float o[8][4];
#pragma unroll
    for (int nt = 0; nt < 8; nt++)
#pragma unroll
        for (int k = 0; k < 4; k++) o[nt][k] = 0.0f;
    float m0 = -1e30f, m1 = -1e30f, l0 = 0.0f, l1 = 0.0f;

    const int prow0 = wrp * 16 + g;

    for (int kt = 0; kt <= qt; kt++) {
        // --- cooperative K / V tile copy (raw pre-rounded bits) ---
        const float* KVg = QKV + (size_t)(b * NN + kt * 64) * NQKV;
#pragma unroll
        for (int s8 = 0; s8 < 8; s8++) {
            int v = tid + s8 * 128;
            int j = v >> 4, c = (v & 15) * 4;
            const uint4* Krow = (const uint4*)(KVg + (size_t)j * NQKV + HD);
            const uint4* Vrow = (const uint4*)(KVg + (size_t)j * NQKV + HD + DD);
            *(uint4*)&Ks[j * SKK + c] = Krow[c >> 2];
            *(uint4*)&Vs[j * SKV + (c ^ (8 * (j & 3)))] = Vrow[c >> 2];
        }
        __syncthreads();

        // --- S = Q K^T (scores in log2 domain) ---
        float s[8][4];
#pragma unroll
        for (int nt = 0; nt < 8; nt++) {
            s[nt][0] = s[nt][1] = s[nt][2] = s[nt][3] = 0.0f;
            const uint32_t* Krow = Ks + (nt * 8 + g) * SKK;
#pragma unroll
            for (int kk = 0; kk < 8; kk++) {
                uint32_t b0 = Krow[kk * 8 + q];
                uint32_t b1 = Krow[kk * 8 + q + 4];
                mma_tf32(s[nt], aq[kk][0], aq[kk][1], aq[kk][2], aq[kk][3],
                         b0, b1);
            }
        }

        // --- causal mask on diagonal tile ---
        if (kt == qt) {
            const int r0 = prow0, r1 = prow0 + 8;
#pragma unroll
            for (int nt = 0; nt < 8; nt++) {
                int c0 = nt * 8 + 2 * q, c1 = c0 + 1;
                if (c0 > r0) s[nt][0] = -1e30f;
                if (c1 > r0) s[nt][1] = -1e30f;
                if (c0 > r1) s[nt][2] = -1e30f;
                if (c1 > r1) s[nt][3] = -1e30f;
            }
        }

        // --- online softmax (base-2), quad shuffles for row reductions ---
        float ml0 = -1e30f, ml1 = -1e30f;
#pragma unroll
        for (int nt = 0; nt < 8; nt++) {
            ml0 = fmaxf(ml0, fmaxf(s[nt][0], s[nt][1]));
            ml1 = fmaxf(ml1, fmaxf(s[nt][2], s[nt][3]));
        }
        ml0 = fmaxf(ml0, __shfl_xor_sync(0xffffffffu, ml0, 1));
        ml0 = fmaxf(ml0, __shfl_xor_sync(0xffffffffu, ml0, 2));
        ml1 = fmaxf(ml1, __shfl_xor_sync(0xffffffffu, ml1, 1));
        ml1 = fmaxf(ml1, __shfl_xor_sync(0xffffffffu, ml1, 2));
        const float mn0 = fmaxf(m0, ml0), mn1 = fmaxf(m1, ml1);
        const float sc0 = ex2f(m0 - mn0), sc1 = ex2f(m1 - mn1);
        float ls0 = 0.0f, ls1 = 0.0f;
#pragma unroll
        for (int nt = 0; nt < 8; nt++) {
            s[nt][0] = ex2f(s[nt][0] - mn0);
            s[nt][1] = ex2f(s[nt][1] - mn0);
            s[nt][2] = ex2f(s[nt][2] - mn1);
            s[nt][3] = ex2f(s[nt][3] - mn1);
            ls0 += s[nt][0] + s[nt][1];
            ls1 += s[nt][2] + s[nt][3];
        }
        ls0 += __shfl_xor_sync(0xffffffffu, ls0, 1);
        ls0 += __shfl_xor_sync(0xffffffffu, ls0, 2);
        ls1 += __shfl_xor_sync(0xffffffffu, ls1, 1);
        ls1 += __shfl_xor_sync(0xffffffffu, ls1, 2);
        l0 = l0 * sc0 + ls0; m0 = mn0;
        l1 = l1 * sc1 + ls1; m1 = mn1;
#pragma unroll
        for (int nt = 0; nt < 8; nt++) {
            o[nt][0] *= sc0; o[nt][1] *= sc0;
            o[nt][2] *= sc1; o[nt][3] *= sc1;
        }

        // --- P to its own buffer, STS.64 pairs ---
#pragma unroll
        for (int nt = 0; nt < 8; nt++) {
            uint2 p01, p23;
            p01.x = f2tf32(s[nt][0]); p01.y = f2tf32(s[nt][1]);
            p23.x = f2tf32(s[nt][2]); p23.y = f2tf32(s[nt][3]);
            *(uint2*)&Ps[prow0 * SKP + nt * 8 + 2 * q] = p01;
            *(uint2*)&Ps[(prow0 + 8) * SKP + nt * 8 + 2 * q] = p23;
        }
        __syncwarp();

        // --- O += P V ---
#pragma unroll
        for (int kk = 0; kk < 8; kk++) {
            uint32_t p0 = Ps[prow0 * SKP + kk * 8 + q];
            uint32_t p1 = Ps[(prow0 + 8) * SKP + kk * 8 + q];
            uint32_t p2 = Ps[prow0 * SKP + kk * 8 + q + 4];
            uint32_t p3 = Ps[(prow0 + 8) * SKP + kk * 8 + q + 4];
#pragma unroll
            for (int nt = 0; nt < 8; nt++) {
                int nx = (nt * 8 + g) ^ (8 * q);
                uint32_t b0 = Vs[(kk * 8 + q) * SKV + nx];
                uint32_t b1 = Vs[(kk * 8 + q + 4) * SKV + nx];
                mma_tf32(o[nt], p0, p1, p2, p3, b0, b1);
            }
        }
        __syncthreads();   // protect Ks/Vs before next tile load
    }

    // --- normalize, round to tf32 (oproj consumes raw bits), write ---
    const float i0 = 1.0f / l0, i1 = 1.0f / l1;
    float* Z0 = Z + ((size_t)(b * NN + qt * AQT + prow0)) * HD + h * DD;
    float* Z1 = Z0 + (size_t)8 * HD;
#pragma unroll
    for (int nt = 0; nt < 8; nt++) {
        int c = nt * 8 + 2 * q;
        *(float2*)&Z0[c] = make_float2(__uint_as_float(f2tf32(o[nt][0] * i0)),
                                       __uint_as_float(f2tf32(o[nt][1] * i0)));
        *(float2*)&Z1[c] = make_float2(__uint_as_float(f2tf32(o[nt][2] * i1)),
                                       __uint_as_float(f2tf32(o[nt][3] * i1)));
    }
}

// ---------------------------------------------------------------------------
// Launch
// ---------------------------------------------------------------------------
extern "C" void kernel_launch(void* const* d_in, const int* in_sizes, int n_in,
                              void* d_out, int out_size)
{
    const float* X  = (const float*)d_in[0];  // (B,N,E)
    const float* Wq = (const float*)d_in[1];  // (E, H*D)
    const float* Wk = (const float*)d_in[2];  // (E, D)
    const float* Wv = (const float*)d_in[3];  // (E, D)
    const float* Wo = (const float*)d_in[4];  // (H*D, H*D)
    const float* bo = (const float*)d_in[5];  // (H*D,)
    float* out = (float*)d_out;               // (B,N,H*D)

    float *pQKV, *pZ, *pXr, *pWall, *pWor;
    cudaGetSymbolAddress((void**)&pQKV, g_QKV);
    cudaGetSymbolAddress((void**)&pZ,   g_Z);
    cudaGetSymbolAddress((void**)&pXr,  g_Xr);
    cudaGetSymbolAddress((void**)&pWall, g_Wall);
    cudaGetSymbolAddress((void**)&pWor, g_Wor);

    // >48KB dynamic smem opt-in (host-side attributes, not captured)
    cudaFuncSetAttribute(tf32_gemm_kernel<false, true>,
                         cudaFuncAttributeMaxDynamicSharedMemorySize, GEMM_SMEM);
    cudaFuncSetAttribute(tf32_gemm_kernel<true, false>,
                         cudaFuncAttributeMaxDynamicSharedMemorySize, GEMM_SMEM);
    cudaFuncSetAttribute(mqa_attn_tc_kernel,
                         cudaFuncAttributeMaxDynamicSharedMemorySize, ATTN_SMEM);

    // Pre-round X, Wo; build fused W_all = [Wq | Wk | Wv]
    preround_kernel<<<(MTOT * EE / 4 + 255) / 256, 256>>>((const float4*)X,
                                                          (float4*)pXr,
                                                          MTOT * EE / 4);
    build_wall_kernel<<<(EE * NQKV / 4 + 255) / 256, 256>>>(Wq, Wk, Wv, pWall);
    preround_kernel<<<(HD * HD / 4 + 255) / 256, 256>>>((const float4*)Wo,
                                                        (float4*)pWor,
                                                        HD * HD / 4);

    // Fused QKV projection: (4096,1024) @ (1024,1152), rounded output
    tf32_gemm_kernel<false, true>
        <<<dim3(NQKV / GBN, MTOT / GBM), 256, GEMM_SMEM>>>(pXr, pWall, nullptr,
                                                           pQKV, MTOT, NQKV, EE);

    // Tensor-core causal MQA attention, heavy-first 1D grid (LPT)
    mqa_attn_tc_kernel<<<ANQT * BB * HH, 128, ATTN_SMEM>>>(pQKV, pZ);

    // Output projection + bias (full fp32 output)
    tf32_gemm_kernel<true, false>
        <<<dim3(HD / GBN, MTOT / GBM), 256, GEMM_SMEM>>>(pZ, pWor, bo, out,
                                                         MTOT, HD, HD);
}

// round 12
// speedup vs baseline: 7.5699x; 1.0083x over previous
#include <cuda_runtime.h>
#include <cuda_bf16.h>
#include <math.h>
#include <stdint.h>

// Problem constants
#define BB 2
#define NN 2048
#define EE 1024
#define HH 16
#define DD 64
#define HD 1024            // H*D
#define MTOT 4096          // B*N
#define NQKV 1152          // HD + 2*DD  (fused QKV output columns)

// ---------------------------------------------------------------------------
// Scratch (static device globals — no allocation allowed)
// ---------------------------------------------------------------------------
__device__ float g_QKV[MTOT * NQKV]; // (B*N, 1152): Q | K | V  (tf32-rounded)
__device__ float g_Z[MTOT * HD];     // (B*N, H*D)  tf32-rounded
__device__ float g_Xr[MTOT * EE];    // tf32-rounded X
__device__ float g_Wall[EE * NQKV];  // tf32-rounded [Wq | Wk | Wv]
__device__ float g_Wor[HD * HD];     // tf32-rounded Wo

// ---------------------------------------------------------------------------
// Helpers
// ---------------------------------------------------------------------------
__device__ __forceinline__ uint32_t f2tf32(float x) {
    uint32_t r;
    asm("cvt.rna.tf32.f32 %0, %1;" : "=r"(r) : "f"(x));
    return r;
}

__device__ __forceinline__ float ex2f(float x) {
    float y;
    asm("ex2.approx.f32 %0, %1;" : "=f"(y) : "f"(x));
    return y;
}

__device__ __forceinline__ void mma_tf32(float c[4], uint32_t a0, uint32_t a1,
                                         uint32_t a2, uint32_t a3,
                                         uint32_t b0, uint32_t b1) {
    asm volatile(
        "mma.sync.aligned.m16n8k8.row.col.f32.tf32.tf32.f32 "
        "{%0,%1,%2,%3}, {%4,%5,%6,%7}, {%8,%9}, {%0,%1,%2,%3};"
        : "+f"(c[0]), "+f"(c[1]), "+f"(c[2]), "+f"(c[3])
        : "r"(a0), "r"(a1), "r"(a2), "r"(a3), "r"(b0), "r"(b1));
}

__device__ __forceinline__ void cpa16(uint32_t s, const float* g) {
    asm volatile("cp.async.cg.shared.global [%0], [%1], 16;" :: "r"(s), "l"(g));
}

// ---------------------------------------------------------------------------
// Elementwise tf32 pre-rounding pass (cvt.rna), float4-vectorized
// ---------------------------------------------------------------------------
__global__ void preround_kernel(const float4* __restrict__ src,
                                float4* __restrict__ dst, int n4)
{
    int i = blockIdx.x * blockDim.x + threadIdx.x;
    if (i < n4) {
        float4 v = src[i];
        float4 o;
        o.x = __uint_as_float(f2tf32(v.x));
        o.y = __uint_as_float(f2tf32(v.y));
        o.z = __uint_as_float(f2tf32(v.z));
        o.w = __uint_as_float(f2tf32(v.w));
        dst[i] = o;
    }
}

// Build W_all[E][1152] = [Wq | Wk | Wv], tf32-rounded
__global__ void build_wall_kernel(const float* __restrict__ Wq,
                                  const float* __restrict__ Wk,
                                  const float* __restrict__ Wv,
                                  float* __restrict__ Wall)
{
    int i = blockIdx.x * blockDim.x + threadIdx.x;   // over E*1152/4
    if (i >= EE * NQKV / 4) return;
    int r  = i / (NQKV / 4);
    int cc = (i % (NQKV / 4)) * 4;
    const float* src;
    if (cc < HD)            src = Wq + (size_t)r * HD + cc;
    else if (cc < HD + DD)  src = Wk + (size_t)r * DD + (cc - HD);
    else                    src = Wv + (size_t)r * DD + (cc - HD - DD);
    float4 v = *(const float4*)src;
    float4 o;
    o.x = __uint_as_float(f2tf32(v.x));
    o.y = __uint_as_float(f2tf32(v.y));
    o.z = __uint_as_float(f2tf32(v.z));
    o.w = __uint_as_float(f2tf32(v.w));
    *(float4*)&Wall[(size_t)r * NQKV + cc] = o;
}

// ---------------------------------------------------------------------------
// tf32 tensor-core GEMM, cp.async 3-stage pipeline, inputs pre-rounded.
// C[M,N] = A[M,K] @ B[K,N] (+ bias) (optionally tf32-round output).
// A smem: natural [m][k], stride 36; B smem: XOR swizzle [k][n^8(k&3)].
// ---------------------------------------------------------------------------
#define GBM 128
#define GBN 128
#define GBK 32
#define LDA 36
#define ABUF (GBM * LDA)      // 4608 words
#define BBUF (GBK * 128)      // 4096 words
#define STAGEW (ABUF + BBUF)  // 8704 words per stage
#define GEMM_SMEM (STAGEW * 3 * 4)   // 104448 bytes

template <bool BIAS, bool ROUND>
__global__ __launch_bounds__(256, 2)
void tf32_gemm_kernel(const float* __restrict__ A, const float* __restrict__ B,
                      const float* __restrict__ bias, float* __restrict__ C,
                      int M, int N, int K)
{
    extern __shared__ uint32_t sm[];
    const uint32_t smemBase = (uint32_t)__cvta_generic_to_shared(sm);

    const int tid  = threadIdx.x;
    const int lane = tid & 31;
    const int w    = tid >> 5;
    const int wm   = w & 1;
    const int wn   = w >> 1;
    const int g    = lane >> 2;
    const int q    = lane & 3;
    const int row0 = blockIdx.y * GBM;
    const int col0 = blockIdx.x * GBN;

    // Per-thread staging maps (4 x 16B for A, 4 x 16B for B)
    int aoffw[4], boffw[4];
    const float* aptr[4];
    const float* bptr[4];
#pragma unroll
    for (int i = 0; i < 4; i++) {
        int idx = tid + i * 256;
        int r = idx >> 3, cc = (idx & 7) * 4;
        aoffw[i] = r * LDA + cc;
        aptr[i]  = A + (size_t)(row0 + r) * K + cc;
        int br = idx >> 5, bc = (idx & 31) * 4;
        boffw[i] = (br << 7) + (bc ^ (8 * (br & 3)));
        bptr[i]  = B + (size_t)br * N + col0 + bc;
    }

    float c[4][4][4];
#pragma unroll
    for (int mi = 0; mi < 4; mi++)
#pragma unroll
        for (int ni = 0; ni < 4; ni++)
#pragma unroll
            for (int k = 0; k < 4; k++) c[mi][ni][k] = 0.0f;

    const int NT = K / GBK;

    auto issue = [&](int st, int kt) {
        uint32_t sA = smemBase + (uint32_t)(st * STAGEW) * 4;
        uint32_t sB = sA + ABUF * 4;
#pragma unroll
        for (int i = 0; i < 4; i++)
            cpa16(sA + aoffw[i] * 4, aptr[i] + kt * GBK);
#pragma unroll
        for (int i = 0; i < 4; i++)
            cpa16(sB + boffw[i] * 4, bptr[i] + (size_t)kt * GBK * N);
        asm volatile("cp.async.commit_group;");
    };

    issue(0, 0);
    issue(1, 1);

    for (int kt = 0; kt < NT; kt++) {
        if (kt == NT - 1) asm volatile("cp.async.wait_group 0;");
        else              asm volatile("cp.async.wait_group 1;");
        __syncthreads();
        if (kt + 2 < NT) issue((kt + 2) % 3, kt + 2);

        const uint32_t* Ac = sm + (kt % 3) * STAGEW;
        const uint32_t* Bc = Ac + ABUF;

#pragma unroll
        for (int kk = 0; kk < GBK; kk += 8) {
            uint32_t af[4][4];
#pragma unroll
            for (int mi = 0; mi < 4; mi++) {
                int r = wm * 64 + mi * 16 + g;
                af[mi][0] = Ac[r * LDA + kk + q];
                af[mi][1] = Ac[(r + 8) * LDA + kk + q];
                af[mi][2] = Ac[r * LDA + kk + 4 + q];
                af[mi][3] = Ac[(r + 8) * LDA + kk + 4 + q];
            }
#pragma unroll
            for (int ni = 0; ni < 4; ni++) {
                int n  = wn * 32 + ni * 8 + g;
                int nx = n ^ (8 * q);
                uint32_t b0 = Bc[((kk + q) << 7) + nx];
                uint32_t b1 = Bc[((kk + q + 4) << 7) + nx];
#pragma unroll
                for (int mi = 0; mi < 4; mi++)
                    mma_tf32(c[mi][ni], af[mi][0], af[mi][1], af[mi][2], af[mi][3],
                             b0, b1);
            }
        }
    }

#pragma unroll
    for (int mi = 0; mi < 4; mi++) {
        int row = row0 + wm * 64 + mi * 16 + g;
#pragma unroll
        for (int ni = 0; ni < 4; ni++) {
            int col = col0 + wn * 32 + ni * 8 + 2 * q;
            float2 v0 = make_float2(c[mi][ni][0], c[mi][ni][1]);
            float2 v1 = make_float2(c[mi][ni][2], c[mi][ni][3]);
            if (BIAS) {
                float2 bv = *(const float2*)&bias[col];
                v0.x += bv.x; v0.y += bv.y;
                v1.x += bv.x; v1.y += bv.y;
            }
            if (ROUND) {
                v0.x = __uint_as_float(f2tf32(v0.x));
                v0.y = __uint_as_float(f2tf32(v0.y));
                v1.x = __uint_as_float(f2tf32(v1.x));
                v1.y = __uint_as_float(f2tf32(v1.y));
            }
            *(float2*)&C[(size_t)row * N + col] = v0;
            *(float2*)&C[(size_t)(row + 8) * N + col] = v1;
        }
    }
}

// ---------------------------------------------------------------------------
// Tensor-core causal MQA flash attention, 128 q-rows per block (8 warps).
// Each 64-row KV tile is loaded once and consumed by all 8 warps -> KV
// traffic and barriers per unit work halved vs 64-row blocks.
// All warps execute the same barrier sequence for all tiles; warps 0-3 skip
// compute on the final (out-of-causal-range) tile.
// Reads Q/K/V from fused QKV buffer (row stride 1152).
// ---------------------------------------------------------------------------
#define AQR 128          // query rows per block
#define ANQB (NN / AQR)  // 16 q-blocks per (b,h)
#define SKK 68
#define SKV 64
#define SKP 68
#define ATTN_SMEM ((64 * SKK + 64 * SKV + AQR * SKP) * 4)   // 68608 bytes

__global__ __launch_bounds__(256, 2)
void mqa_attn_tc_kernel(const float* __restrict__ QKV,
                        float* __restrict__ Z)
{
    extern __shared__ uint32_t dsm[];
    uint32_t* Ks = dsm;                        // [64][68]
    uint32_t* Vs = dsm + 64 * SKK;             // [64][64] swizzled
    uint32_t* Ps = dsm + 64 * SKK + 64 * SKV;  // [128][68]

    const int wid  = blockIdx.x;
    const int qb   = (ANQB - 1) - (wid >> 5);   // heavy-first (LPT)
    const int bh   = wid & 31;
    const int b    = bh >> 4;
    const int h    = bh & 15;
    const int tid  = threadIdx.x;
    const int lane = tid & 31;
    const int w    = tid >> 5;                  // 8 warps
    const int g    = lane >> 2;
    const int q    = lane & 3;

    // Q fragments, scaled by log2(e)/sqrt(D) (base-2 softmax), re-rounded
    const float QS = 0.125f * 1.4426950408889634f;
    uint32_t aq[8][4];
    const float* Qb = QKV + (size_t)(b * NN + qb * AQR + w * 16) * NQKV + h * DD;
#pragma unroll
    for (int t = 0; t < 8; t++) {
        aq[t][0] = f2tf32(Qb[(size_t)g * NQKV       + t * 8 + q    ] * QS);
        aq[t][1] = f2tf32(Qb[(size_t)(g + 8) * NQKV + t * 8 + q    ] * QS);
        aq[t][2] = f2tf32(Qb[(size_t)g * NQKV       + t * 8 + q + 4] * QS);
        aq[t][3] = f2tf32(Qb[(size_t)(g + 8) * NQKV + t * 8 + q + 4] * QS);
    }

    float o[8][4];
#pragma unroll
    for (int nt = 0; nt < 8; nt++)
#pragma unroll
        for (int k = 0; k < 4; k++) o[nt][k] = 0.0f;
    float m0 = -1e30f, m1 = -1e30f, l0 = 0.0f, l1 = 0.0f;

    const int prow0 = w * 16 + g;          // local row in [0,128)
    const int NT    = 2 * qb + 2;          // kv tiles for this q-block

    for (int kt = 0; kt < NT; kt++) {
        // --- cooperative K / V tile copy, 256 threads, 4 uint4 each ---
        const float* KVg = QKV + (size_t)(b * NN + kt * 64) * NQKV;
#pragma unroll
        for (int s8 = 0; s8 < 4; s8++) {
            int v = tid + s8 * 256;                 // 0..1023
            int j = v >> 4, c = (v & 15) * 4;
            const uint4* Krow = (const uint4*)(KVg + (size_t)j * NQKV + HD);
            const uint4* Vrow = (const uint4*)(KVg + (size_t)j * NQKV + HD + DD);
            *(uint4*)&Ks[j * SKK + c] = Krow[c >> 2];
            *(uint4*)&Vs[j * SKV + (c ^ (8 * (j & 3)))] = Vrow[c >> 2];
        }
        __syncthreads();

        // Warp active iff tile start is within its causal range
        const bool active = (kt * 64) <= (qb * AQR + w * 16 + 15);
        if (active) {
            // --- S = Q K^T ---
            float s[8][4];
#pragma unroll
            for (int nt = 0; nt < 8; nt++) {
                s[nt][0] = s[nt][1] = s[nt][2] = s[nt][3] = 0.0f;
                const uint32_t* Krow = Ks + (nt * 8 + g) * SKK;
#pragma unroll
                for (int kk = 0; kk < 8; kk++) {
                    uint32_t b0 = Krow[kk * 8 + q];
                    uint32_t b1 = Krow[kk * 8 + q + 4];
                    mma_tf32(s[nt], aq[kk][0], aq[kk][1], aq[kk][2], aq[kk][3],
                             b0, b1);
                }
            }

            // --- causal mask where tile cols can exceed warp rows ---
            const int off = kt * 64 - qb * AQR;   // col offset rel. to block rows
            if (off + 63 > w * 16) {
                const int r0 = prow0, r1 = prow0 + 8;
#pragma unroll
                for (int nt = 0; nt < 8; nt++) {
                    int c0 = nt * 8 + 2 * q + off, c1 = c0 + 1;
                    if (c0 > r0) s[nt][0] = -1e30f;
                    if (c1 > r0) s[nt][1] = -1e30f;
                    if (c0 > r1) s[nt][2] = -1e30f;
                    if (c1 > r1) s[nt][3] = -1e30f;
                }
            }

            // --- online softmax (base-2), quad shuffles ---
            float ml0 = -1e30f, ml1 = -1e30f;
#pragma unroll
            for (int nt = 0; nt < 8; nt++) {
                ml0 = fmaxf(ml0, fmaxf(s[nt][0], s[nt][1]));
                ml1 = fmaxf(ml1, fmaxf(s[nt][2], s[nt][3]));
            }
            ml0 = fmaxf(ml0, __shfl_xor_sync(0xffffffffu, ml0, 1));
            ml0 = fmaxf(ml0, __shfl_xor_sync(0xffffffffu, ml0, 2));
            ml1 = fmaxf(ml1, __shfl_xor_sync(0xffffffffu, ml1, 1));
            ml1 = fmaxf(ml1, __shfl_xor_sync(0xffffffffu, ml1, 2));
            const float mn0 = fmaxf(m0, ml0), mn1 = fmaxf(m1, ml1);
            const float sc0 = ex2f(m0 - mn0), sc1 = ex2f(m1 - mn1);
            float ls0 = 0.0f, ls1 = 0.0f;
#pragma unroll
            for (int nt = 0; nt < 8; nt++) {
                s[nt][0] = ex2f(s[nt][0] - mn0);
                s[nt][1] = ex2f(s[nt][1] - mn0);
                s[nt][2] = ex2f(s[nt][2] - mn1);
                s[nt][3] = ex2f(s[nt][3] - mn1);
                ls0 += s[nt][0] + s[nt][1];
                ls1 += s[nt][2] + s[nt][3];
            }
            ls0 += __shfl_xor_sync(0xffffffffu, ls0, 1);
            ls0 += __shfl_xor_sync(0xffffffffu, ls0, 2);
            ls1 += __shfl_xor_sync(0xffffffffu, ls1, 1);
            ls1 += __shfl_xor_sync(0xffffffffu, ls1, 2);
            l0 = l0 * sc0 + ls0; m0 = mn0;
            l1 = l1 * sc1 + ls1; m1 = mn1;
#pragma unroll
            for (int nt = 0; nt < 8; nt++) {
                o[nt][0] *= sc0; o[nt][1] *= sc0;
                o[nt][2] *= sc1; o[nt][3] *= sc1;
            }

            // --- P to its own rows of the P buffer, STS.64 pairs ---
#pragma unroll
            for (int nt = 0; nt < 8; nt++) {
                uint2 p01, p23;
                p01.x = f2tf32(s[nt][0]); p01.y = f2tf32(s[nt][1]);
                p23.x = f2tf32(s[nt][2]); p23.y = f2tf32(s[nt][3]);
                *(uint2*)&Ps[prow0 * SKP + nt * 8 + 2 * q] = p01;
                *(uint2*)&Ps[(prow0 + 8) * SKP + nt * 8 + 2 * q] = p23;
            }
            __syncwarp();

            // --- O += P V ---
#pragma unroll
            for (int kk = 0; kk < 8; kk++) {
                uint32_t p0 = Ps[prow0 * SKP + kk * 8 + q];
                uint32_t p1 = Ps[(prow0 + 8) * SKP + kk * 8 + q];
                uint32_t p2 = Ps[prow0 * SKP + kk * 8 + q + 4];
                uint32_t p3 = Ps[(prow0 + 8) * SKP + kk * 8 + q + 4];
#pragma unroll
                for (int nt = 0; nt < 8; nt++) {
                    int nx = (nt * 8 + g) ^ (8 * q);
                    uint32_t b0 = Vs[(kk * 8 + q) * SKV + nx];
                    uint32_t b1 = Vs[(kk * 8 + q + 4) * SKV + nx];
                    mma_tf32(o[nt], p0, p1, p2, p3, b0, b1);
                }
            }
        }
        __syncthreads();   // protect Ks/Vs before next tile load
    }

    // --- normalize, round to tf32 (oproj consumes raw bits), write ---
    const float i0 = 1.0f / l0, i1 = 1.0f / l1;
    float* Z0 = Z + ((size_t)(b * NN + qb * AQR + prow0)) * HD + h * DD;
    float* Z1 = Z0 + (size_t)8 * HD;
#pragma unroll
    for (int nt = 0; nt < 8; nt++) {
        int c = nt * 8 + 2 * q;
        *(float2*)&Z0[c] = make_float2(__uint_as_float(f2tf32(o[nt][0] * i0)),
                                       __uint_as_float(f2tf32(o[nt][1] * i0)));
        *(float2*)&Z1[c] = make_float2(__uint_as_float(f2tf32(o[nt][2] * i1)),
                                       __uint_as_float(f2tf32(o[nt][3] * i1)));
    }
}

// ---------------------------------------------------------------------------
// Launch
// ---------------------------------------------------------------------------
extern "C" void kernel_launch(void* const* d_in, const int* in_sizes, int n_in,
                              void* d_out, int out_size)
{
    const float* X  = (const float*)d_in[0];  // (B,N,E)
    const float* Wq = (const float*)d_in[1];  // (E, H*D)
    const float* Wk = (const float*)d_in[2];  // (E, D)
    const float* Wv = (const float*)d_in[3];  // (E, D)
    const float* Wo = (const float*)d_in[4];  // (H*D, H*D)
    const float* bo = (const float*)d_in[5];  // (H*D,)
    float* out = (float*)d_out;               // (B,N,H*D)

    float *pQKV, *pZ, *pXr, *pWall, *pWor;
    cudaGetSymbolAddress((void**)&pQKV, g_QKV);
    cudaGetSymbolAddress((void**)&pZ,   g_Z);
    cudaGetSymbolAddress((void**)&pXr,  g_Xr);
    cudaGetSymbolAddress((void**)&pWall, g_Wall);
    cudaGetSymbolAddress((void**)&pWor, g_Wor);

    // >48KB dynamic smem opt-in (host-side attributes, not captured)
    cudaFuncSetAttribute(tf32_gemm_kernel<false, true>,
                         cudaFuncAttributeMaxDynamicSharedMemorySize, GEMM_SMEM);
    cudaFuncSetAttribute(tf32_gemm_kernel<true, false>,
                         cudaFuncAttributeMaxDynamicSharedMemorySize, GEMM_SMEM);
    cudaFuncSetAttribute(mqa_attn_tc_kernel,
                         cudaFuncAttributeMaxDynamicSharedMemorySize, ATTN_SMEM);

    // Pre-round X, Wo; build fused W_all = [Wq | Wk | Wv]
    preround_kernel<<<(MTOT * EE / 4 + 255) / 256, 256>>>((const float4*)X,
                                                          (float4*)pXr,
                                                          MTOT * EE / 4);
    build_wall_kernel<<<(EE * NQKV / 4 + 255) / 256, 256>>>(Wq, Wk, Wv, pWall);
    preround_kernel<<<(HD * HD / 4 + 255) / 256, 256>>>((const float4*)Wo,
                                                        (float4*)pWor,
                                                        HD * HD / 4);

    // Fused QKV projection: (4096,1024) @ (1024,1152), rounded output
    tf32_gemm_kernel<false, true>
        <<<dim3(NQKV / GBN, MTOT / GBM), 256, GEMM_SMEM>>>(pXr, pWall, nullptr,
                                                           pQKV, MTOT, NQKV, EE);

    // Tensor-core causal MQA attention, 128-row q-blocks, heavy-first (LPT)
    mqa_attn_tc_kernel<<<ANQB * BB * HH, 256, ATTN_SMEM>>>(pQKV, pZ);

    // Output projection + bias (full fp32 output)
    tf32_gemm_kernel<true, false>
        <<<dim3(HD / GBN, MTOT / GBM), 256, GEMM_SMEM>>>(pZ, pWor, bo, out,
                                                         MTOT, HD, HD);
}

// round 13
// speedup vs baseline: 11.7657x; 1.5543x over previous
#include <cuda_runtime.h>
#include <cuda_fp16.h>
#include <math.h>
#include <stdint.h>

// Problem constants
#define BB 2
#define NN 2048
#define EE 1024
#define HH 16
#define DD 64
#define HD 1024            // H*D
#define MTOT 4096          // B*N
#define NQKV 1152          // HD + 2*DD  (fused QKV output columns)

// ---------------------------------------------------------------------------
// Scratch (static device globals — no allocation allowed)
// ---------------------------------------------------------------------------
__device__ __half   g_QKV[MTOT * NQKV];       // (B*N,1152): Q|K|V  fp16
__device__ __half   g_Zh[MTOT * HD];          // attention out, fp16
__device__ __half   g_Xh[MTOT * EE];          // X as fp16
__device__ uint32_t g_Wallp[(EE / 2) * NQKV]; // [Wq|Wk|Wv] k-pair packed half2
__device__ uint32_t g_Worp[(HD / 2) * HD];    // Wo k-pair packed half2

// ---------------------------------------------------------------------------
// Helpers
// ---------------------------------------------------------------------------
__device__ __forceinline__ float ex2f(float x) {
    float y;
    asm("ex2.approx.f32 %0, %1;" : "=f"(y) : "f"(x));
    return y;
}

__device__ __forceinline__ uint32_t packh2(float lo, float hi) {
    __half2 h = __floats2half2_rn(lo, hi);
    return *(uint32_t*)&h;
}

__device__ __forceinline__ void mma_f16(float c[4], uint32_t a0, uint32_t a1,
                                        uint32_t a2, uint32_t a3,
                                        uint32_t b0, uint32_t b1) {
    asm volatile(
        "mma.sync.aligned.m16n8k16.row.col.f32.f16.f16.f32 "
        "{%0,%1,%2,%3}, {%4,%5,%6,%7}, {%8,%9}, {%0,%1,%2,%3};"
        : "+f"(c[0]), "+f"(c[1]), "+f"(c[2]), "+f"(c[3])
        : "r"(a0), "r"(a1), "r"(a2), "r"(a3), "r"(b0), "r"(b1));
}

__device__ __forceinline__ void cpa16(uint32_t s, const void* g) {
    asm volatile("cp.async.cg.shared.global [%0], [%1], 16;" :: "r"(s), "l"(g));
}

// Rescale a half2 word by s (used once per Q fragment at load)
__device__ __forceinline__ uint32_t scaleh2(uint32_t w, float s) {
    __half2 h = *(__half2*)&w;
    float2 f = __half22float2(h);
    return packh2(f.x * s, f.y * s);
}

// ---------------------------------------------------------------------------
// Conversion / packing kernels (one-time prologue)
// ---------------------------------------------------------------------------
// fp32 -> fp16, natural layout (A operands)
__global__ void tohalf_kernel(const float4* __restrict__ src,
                              uint2* __restrict__ dst, int n4)
{
    int i = blockIdx.x * blockDim.x + threadIdx.x;
    if (i < n4) {
        float4 v = src[i];
        uint2 o;
        o.x = packh2(v.x, v.y);
        o.y = packh2(v.z, v.w);
        dst[i] = o;
    }
}

// Build W_all packed: word (kp, n) = half2(W[2kp][n], W[2kp+1][n])
__global__ void build_wall_kernel(const float* __restrict__ Wq,
                                  const float* __restrict__ Wk,
                                  const float* __restrict__ Wv,
                                  uint32_t* __restrict__ Wp)
{
    int i = blockIdx.x * blockDim.x + threadIdx.x;   // over (EE/2)*(NQKV/4)
    if (i >= (EE / 2) * (NQKV / 4)) return;
    int kp = i / (NQKV / 4);
    int c4 = (i % (NQKV / 4)) * 4;
    const float *r0, *r1;
    if (c4 < HD) {
        r0 = Wq + (size_t)(2 * kp) * HD + c4;
        r1 = Wq + (size_t)(2 * kp + 1) * HD + c4;
    } else if (c4 < HD + DD) {
        r0 = Wk + (size_t)(2 * kp) * DD + (c4 - HD);
        r1 = Wk + (size_t)(2 * kp + 1) * DD + (c4 - HD);
    } else {
        r0 = Wv + (size_t)(2 * kp) * DD + (c4 - HD - DD);
        r1 = Wv + (size_t)(2 * kp + 1) * DD + (c4 - HD - DD);
    }
    float4 a = *(const float4*)r0;
    float4 b = *(const float4*)r1;
    uint4 o;
    o.x = packh2(a.x, b.x);
    o.y = packh2(a.y, b.y);
    o.z = packh2(a.z, b.z);
    o.w = packh2(a.w, b.w);
    *(uint4*)&Wp[(size_t)kp * NQKV + c4] = o;
}

// Pack a square weight (Wo): word (kp, n) = half2(W[2kp][n], W[2kp+1][n])
__global__ void pack_w_kernel(const float* __restrict__ W,
                              uint32_t* __restrict__ Wp, int ncols)
{
    int i = blockIdx.x * blockDim.x + threadIdx.x;
    if (i >= (HD / 2) * (ncols / 4)) return;
    int kp = i / (ncols / 4);
    int c4 = (i % (ncols / 4)) * 4;
    float4 a = *(const float4*)&W[(size_t)(2 * kp) * ncols + c4];
    float4 b = *(const float4*)&W[(size_t)(2 * kp + 1) * ncols + c4];
    uint4 o;
    o.x = packh2(a.x, b.x);
    o.y = packh2(a.y, b.y);
    o.z = packh2(a.z, b.z);
    o.w = packh2(a.w, b.w);
    *(uint4*)&Wp[(size_t)kp * ncols + c4] = o;
}

// ---------------------------------------------------------------------------
// fp16 tensor-core GEMM, cp.async 3-stage pipeline.
// C[M,N] = A[M,K] @ B[K,N] (+ bias). A: fp16 natural [m][k]. B: packed
// half2-pair words [k/2][n]. mma.m16n8k16, fp32 accumulate.
// A smem: [m][k/2] words, stride 20 (banks 20g+q all distinct).
// B smem: [kp][n ^ 8(kp&3)], stride 128 (banks g+8((ni^q)&3) distinct).
// ---------------------------------------------------------------------------
#define GBM 128
#define GBN 128
#define LDAH 20
#define ABUFH (GBM * LDAH)      // 2560 words
#define BBUFH (16 * 128)        // 2048 words (16 k-pair rows)
#define STAGEH (ABUFH + BBUFH)  // 4608 words
#define GEMM_SMEM (STAGEH * 3 * 4)   // 55296 bytes

template <bool BIAS, bool OUTHALF>
__global__ __launch_bounds__(256, 2)
void f16_gemm_kernel(const __half* __restrict__ A,
                     const uint32_t* __restrict__ B,
                     const float* __restrict__ bias, void* __restrict__ Cout,
                     int M, int N, int K)
{
    extern __shared__ uint32_t sm[];
    const uint32_t smemBase = (uint32_t)__cvta_generic_to_shared(sm);

    const int tid  = threadIdx.x;
    const int lane = tid & 31;
    const int w    = tid >> 5;
    const int wm   = w & 1;
    const int wn   = w >> 1;
    const int g    = lane >> 2;
    const int q    = lane & 3;
    const int row0 = blockIdx.y * GBM;
    const int col0 = blockIdx.x * GBN;

    // Staging maps: A 2 chunks/thread (128 rows x 4 chunks), B 2 chunks/thread
    int aoffw[2], boffw[2];
    const __half* aptr[2];
    const uint32_t* bptr[2];
#pragma unroll
    for (int i = 0; i < 2; i++) {
        int idx = tid + i * 256;
        int r = idx >> 2, c = (idx & 3) * 4;          // A: word col c
        aoffw[i] = r * LDAH + c;
        aptr[i]  = A + (size_t)(row0 + r) * K + c * 2;
        int kp = idx >> 5, bc = (idx & 31) * 4;       // B: pair-row kp
        boffw[i] = (kp << 7) + (bc ^ (8 * (kp & 3)));
        bptr[i]  = B + (size_t)kp * N + col0 + bc;
    }

    float c[4][4][4];
#pragma unroll
    for (int mi = 0; mi < 4; mi++)
#pragma unroll
        for (int ni = 0; ni < 4; ni++)
#pragma unroll
            for (int k = 0; k < 4; k++) c[mi][ni][k] = 0.0f;

    const int NT = K / 32;   // 32-half k-tiles

    auto issue = [&](int st, int kt) {
        uint32_t sA = smemBase + (uint32_t)(st * STAGEH) * 4;
        uint32_t sB = sA + ABUFH * 4;
#pragma unroll
        for (int i = 0; i < 2; i++)
            cpa16(sA + aoffw[i] * 4, aptr[i] + kt * 32);
#pragma unroll
        for (int i = 0; i < 2; i++)
            cpa16(sB + boffw[i] * 4, bptr[i] + (size_t)kt * 16 * N);
        asm volatile("cp.async.commit_group;");
    };

    issue(0, 0);
    issue(1, 1);

    for (int kt = 0; kt < NT; kt++) {
        if (kt == NT - 1) asm volatile("cp.async.wait_group 0;");
        else              asm volatile("cp.async.wait_group 1;");
        __syncthreads();
        if (kt + 2 < NT) issue((kt + 2) % 3, kt + 2);

        const uint32_t* Ac = sm + (kt % 3) * STAGEH;
        const uint32_t* Bc = Ac + ABUFH;

#pragma unroll
        for (int s2 = 0; s2 < 2; s2++) {     // two k=16 steps per 32-tile
            const int kw = s2 * 8;           // word base
            uint32_t af[4][4];
#pragma unroll
            for (int mi = 0; mi < 4; mi++) {
                int r = wm * 64 + mi * 16 + g;
                af[mi][0] = Ac[r * LDAH + kw + q];
                af[mi][1] = Ac[(r + 8) * LDAH + kw + q];
                af[mi][2] = Ac[r * LDAH + kw + q + 4];
                af[mi][3] = Ac[(r + 8) * LDAH + kw + q + 4];
            }
#pragma unroll
            for (int ni = 0; ni < 4; ni++) {
                int n  = wn * 32 + ni * 8 + g;
                int r0 = kw + q, r1 = kw + q + 4;
                uint32_t b0 = Bc[(r0 << 7) + (n ^ (8 * (r0 & 3)))];
                uint32_t b1 = Bc[(r1 << 7) + (n ^ (8 * (r1 & 3)))];
#pragma unroll
                for (int mi = 0; mi < 4; mi++)
                    mma_f16(c[mi][ni], af[mi][0], af[mi][1], af[mi][2], af[mi][3],
                            b0, b1);
            }
        }
    }

#pragma unroll
    for (int mi = 0; mi < 4; mi++) {
        int row = row0 + wm * 64 + mi * 16 + g;
#pragma unroll
        for (int ni = 0; ni < 4; ni++) {
            int col = col0 + wn * 32 + ni * 8 + 2 * q;
            if (OUTHALF) {
                uint32_t* C32 = (uint32_t*)Cout;
                C32[(size_t)row * (N / 2) + col / 2] =
                    packh2(c[mi][ni][0], c[mi][ni][1]);
                C32[(size_t)(row + 8) * (N / 2) + col / 2] =
                    packh2(c[mi][ni][2], c[mi][ni][3]);
            } else {
                float* Cf = (float*)Cout;
                float2 v0 = make_float2(c[mi][ni][0], c[mi][ni][1]);
                float2 v1 = make_float2(c[mi][ni][2], c[mi][ni][3]);
                if (BIAS) {
                    float2 bv = *(const float2*)&bias[col];
                    v0.x += bv.x; v0.y += bv.y;
                    v1.x += bv.x; v1.y += bv.y;
                }
                *(float2*)&Cf[(size_t)row * N + col] = v0;
                *(float2*)&Cf[(size_t)(row + 8) * N + col] = v1;
            }
        }
    }
}

// ---------------------------------------------------------------------------
// fp16 tensor-core causal MQA flash attention, 128 q-rows / 8 warps.
// K smem natural word layout [j][d/2] stride 36 (S B-frag banks 4g+q).
// V smem j-pair packed [j/2][d] stride 68 (PV B-frag banks 4q+g).
// P smem half2-pair [i][j/2] stride 36 (A-frag banks 4g+q; STS.32 writes).
// Base-2 online softmax in fp32 C-fragments.
// ---------------------------------------------------------------------------
#define AQR 128
#define ANQB (NN / AQR)     // 16 q-blocks per (b,h)
#define SKKW 36             // K row stride (words)
#define SVW 68              // V pair-row stride (words)
#define SPW 36              // P row stride (words)
#define ATTN_SMEM ((64 * SKKW + 32 * SVW + AQR * SPW) * 4)   // 36352 bytes

__global__ __launch_bounds__(256, 2)
void mqa_attn_tc_kernel(const __half* __restrict__ QKV,
                        __half* __restrict__ Z)
{
    extern __shared__ uint32_t dsm[];
    uint32_t* Ks = dsm;                         // [64][36]
    uint32_t* Vs = dsm + 64 * SKKW;             // [32][68]
    uint32_t* Ps = dsm + 64 * SKKW + 32 * SVW;  // [128][36]

    const int wid  = blockIdx.x;
    const int qb   = (ANQB - 1) - (wid >> 5);   // heavy-first (LPT)
    const int bh   = wid & 31;
    const int b    = bh >> 4;
    const int h    = bh & 15;
    const int tid  = threadIdx.x;
    const int lane = tid & 31;
    const int w    = tid >> 5;                  // 8 warps
    const int g    = lane >> 2;
    const int q    = lane & 3;

    // Q fragments (half2 pairs along d), scaled by log2(e)/sqrt(D)
    const float QS = 0.125f * 1.4426950408889634f;
    uint32_t aq[4][4];
    const uint32_t* Qw = (const uint32_t*)QKV +
        (size_t)(b * NN + qb * AQR + w * 16) * (NQKV / 2) + h * (DD / 2);
#pragma unroll
    for (int t = 0; t < 4; t++) {
        aq[t][0] = scaleh2(Qw[(size_t)g * (NQKV / 2)       + t * 8 + q    ], QS);
        aq[t][1] = scaleh2(Qw[(size_t)(g + 8) * (NQKV / 2) + t * 8 + q    ], QS);
        aq[t][2] = scaleh2(Qw[(size_t)g * (NQKV / 2)       + t * 8 + q + 4], QS);
        aq[t][3] = scaleh2(Qw[(size_t)(g + 8) * (NQKV / 2) + t * 8 + q + 4], QS);
    }

    float o[8][4];
#pragma unroll
    for (int nt = 0; nt < 8; nt++)
#pragma unroll
        for (int k = 0; k < 4; k++) o[nt][k] = 0.0f;
    float m0 = -1e30f, m1 = -1e30f, l0 = 0.0f, l1 = 0.0f;

    const int prow0 = w * 16 + g;
    const int NT    = 2 * qb + 2;

    for (int kt = 0; kt < NT; kt++) {
        const uint32_t* KVw = (const uint32_t*)QKV +
            (size_t)(b * NN + kt * 64) * (NQKV / 2);
        // K copy: 64 rows x 32 words, natural
#pragma unroll
        for (int i = 0; i < 2; i++) {
            int idx = tid + i * 256;
            int j = idx >> 3, cc = (idx & 7) * 4;
            *(uint4*)&Ks[j * SKKW + cc] =
                *(const uint4*)(KVw + (size_t)j * (NQKV / 2) + (HD / 2) + cc);
        }
        // V interleave: word (jp, d) = half2(V[2jp][d], V[2jp+1][d])
        {
            int jp = tid >> 3, oc = (tid & 7) * 8;    // d base (halves)
            const uint32_t* r0 = KVw + (size_t)(2 * jp) * (NQKV / 2) +
                                 (HD + DD) / 2 + oc / 2;
            const uint32_t* r1 = r0 + (NQKV / 2);
            uint4 a = *(const uint4*)r0;
            uint4 bb = *(const uint4*)r1;
            uint4 o0, o1;
            o0.x = __byte_perm(a.x, bb.x, 0x5410);
            o0.y = __byte_perm(a.x, bb.x, 0x7632);
            o0.z = __byte_perm(a.y, bb.y, 0x5410);
            o0.w = __byte_perm(a.y, bb.y, 0x7632);
            o1.x = __byte_perm(a.z, bb.z, 0x5410);
            o1.y = __byte_perm(a.z, bb.z, 0x7632);
            o1.z = __byte_perm(a.w, bb.w, 0x5410);
            o1.w = __byte_perm(a.w, bb.w, 0x7632);
            *(uint4*)&Vs[jp * SVW + oc]     = o0;
            *(uint4*)&Vs[jp * SVW + oc + 4] = o1;
        }
        __syncthreads();

        const bool active = (kt * 64) <= (qb * AQR + w * 16 + 15);
        if (active) {
            // --- S = Q K^T ---
            float s[8][4];
#pragma unroll
            for (int nt = 0; nt < 8; nt++) {
                s[nt][0] = s[nt][1] = s[nt][2] = s[nt][3] = 0.0f;
                const uint32_t* Krow = Ks + (nt * 8 + g) * SKKW;
#pragma unroll
                for (int t = 0; t < 4; t++) {
                    uint32_t b0 = Krow[t * 8 + q];
                    uint32_t b1 = Krow[t * 8 + q + 4];
                    mma_f16(s[nt], aq[t][0], aq[t][1], aq[t][2], aq[t][3],
                            b0, b1);
                }
            }

            // --- causal mask ---
            const int off = kt * 64 - qb * AQR;
            if (off + 63 > w * 16) {
                const int r0 = prow0, r1 = prow0 + 8;
#pragma unroll
                for (int nt = 0; nt < 8; nt++) {
                    int c0 = nt * 8 + 2 * q + off, c1 = c0 + 1;
                    if (c0 > r0) s[nt][0] = -1e30f;
                    if (c1 > r0) s[nt][1] = -1e30f;
                    if (c0 > r1) s[nt][2] = -1e30f;
                    if (c1 > r1) s[nt][3] = -1e30f;
                }
            }

            // --- online softmax (base-2), quad shuffles ---
            float ml0 = -1e30f, ml1 = -1e30f;
#pragma unroll
            for (int nt = 0; nt < 8; nt++) {
                ml0 = fmaxf(ml0, fmaxf(s[nt][0], s[nt][1]));
                ml1 = fmaxf(ml1, fmaxf(s[nt][2], s[nt][3]));
            }
            ml0 = fmaxf(ml0, __shfl_xor_sync(0xffffffffu, ml0, 1));
            ml0 = fmaxf(ml0, __shfl_xor_sync(0xffffffffu, ml0, 2));
            ml1 = fmaxf(ml1, __shfl_xor_sync(0xffffffffu, ml1, 1));
            ml1 = fmaxf(ml1, __shfl_xor_sync(0xffffffffu, ml1, 2));
            const float mn0 = fmaxf(m0, ml0), mn1 = fmaxf(m1, ml1);
            const float sc0 = ex2f(m0 - mn0), sc1 = ex2f(m1 - mn1);
            float ls0 = 0.0f, ls1 = 0.0f;
#pragma unroll
            for (int nt = 0; nt < 8; nt++) {
                s[nt][0] = ex2f(s[nt][0] - mn0);
                s[nt][1] = ex2f(s[nt][1] - mn0);
                s[nt][2] = ex2f(s[nt][2] - mn1);
                s[nt][3] = ex2f(s[nt][3] - mn1);
                ls0 += s[nt][0] + s[nt][1];
                ls1 += s[nt][2] + s[nt][3];
            }
            ls0 += __shfl_xor_sync(0xffffffffu, ls0, 1);
            ls0 += __shfl_xor_sync(0xffffffffu, ls0, 2);
            ls1 += __shfl_xor_sync(0xffffffffu, ls1, 1);
            ls1 += __shfl_xor_sync(0xffffffffu, ls1, 2);
            l0 = l0 * sc0 + ls0; m0 = mn0;
            l1 = l1 * sc1 + ls1; m1 = mn1;
#pragma unroll
            for (int nt = 0; nt < 8; nt++) {
                o[nt][0] *= sc0; o[nt][1] *= sc0;
                o[nt][2] *= sc1; o[nt][3] *= sc1;
            }

            // --- P as half2 pairs, single-word stores ---
#pragma unroll
            for (int nt = 0; nt < 8; nt++) {
                Ps[prow0 * SPW + nt * 4 + q]       = packh2(s[nt][0], s[nt][1]);
                Ps[(prow0 + 8) * SPW + nt * 4 + q] = packh2(s[nt][2], s[nt][3]);
            }
            __syncwarp();

            // --- O += P V ---
#pragma unroll
            for (int t = 0; t < 4; t++) {
                uint32_t p0 = Ps[prow0 * SPW + t * 8 + q];
                uint32_t p1 = Ps[(prow0 + 8) * SPW + t * 8 + q];
                uint32_t p2 = Ps[prow0 * SPW + t * 8 + q + 4];
                uint32_t p3 = Ps[(prow0 + 8) * SPW + t * 8 + q + 4];
#pragma unroll
                for (int nt = 0; nt < 8; nt++) {
                    int d = nt * 8 + g;
                    uint32_t b0 = Vs[(t * 8 + q) * SVW + d];
                    uint32_t b1 = Vs[(t * 8 + q + 4) * SVW + d];
                    mma_f16(o[nt], p0, p1, p2, p3, b0, b1);
                }
            }
        }
        __syncthreads();
    }

    // --- normalize, write Z as fp16 (oproj A operand) ---
    const float i0 = 1.0f / l0, i1 = 1.0f / l1;
    uint32_t* Zw = (uint32_t*)Z +
        (size_t)(b * NN + qb * AQR + prow0) * (HD / 2) + h * (DD / 2);
#pragma unroll
    for (int nt = 0; nt < 8; nt++) {
        Zw[nt * 4 + q] = packh2(o[nt][0] * i0, o[nt][1] * i0);
        Zw[(size_t)8 * (HD / 2) + nt * 4 + q] = packh2(o[nt][2] * i1,
                                                       o[nt][3] * i1);
    }
}

// ---------------------------------------------------------------------------
// Launch
// ---------------------------------------------------------------------------
extern "C" void kernel_launch(void* const* d_in, const int* in_sizes, int n_in,
                              void* d_out, int out_size)
{
    const float* X  = (const float*)d_in[0];
    const float* Wq = (const float*)d_in[1];
    const float* Wk = (const float*)d_in[2];
    const float* Wv = (const float*)d_in[3];
    const float* Wo = (const float*)d_in[4];
    const float* bo = (const float*)d_in[5];
    float* out = (float*)d_out;

    __half *pQKV, *pZh, *pXh;
    uint32_t *pWallp, *pWorp;
    cudaGetSymbolAddress((void**)&pQKV,  g_QKV);
    cudaGetSymbolAddress((void**)&pZh,   g_Zh);
    cudaGetSymbolAddress((void**)&pXh,   g_Xh);
    cudaGetSymbolAddress((void**)&pWallp, g_Wallp);
    cudaGetSymbolAddress((void**)&pWorp, g_Worp);

    cudaFuncSetAttribute(f16_gemm_kernel<false, true>,
                         cudaFuncAttributeMaxDynamicSharedMemorySize, GEMM_SMEM);
    cudaFuncSetAttribute(f16_gemm_kernel<true, false>,
                         cudaFuncAttributeMaxDynamicSharedMemorySize, GEMM_SMEM);
    cudaFuncSetAttribute(mqa_attn_tc_kernel,
                         cudaFuncAttributeMaxDynamicSharedMemorySize, ATTN_SMEM);

    // Prologue: convert X, pack weights
    tohalf_kernel<<<(MTOT * EE / 4 + 255) / 256, 256>>>((const float4*)X,
                                                        (uint2*)pXh,
                                                        MTOT * EE / 4);
    build_wall_kernel<<<((EE / 2) * (NQKV / 4) + 255) / 256, 256>>>(Wq, Wk, Wv,
                                                                    pWallp);
    pack_w_kernel<<<((HD / 2) * (HD / 4) + 255) / 256, 256>>>(Wo, pWorp, HD);

    // Fused QKV projection: (4096,1024)@(1024,1152), fp16 out
    f16_gemm_kernel<false, true>
        <<<dim3(NQKV / GBN, MTOT / GBM), 256, GEMM_SMEM>>>(pXh, pWallp, nullptr,
                                                           pQKV, MTOT, NQKV, EE);

    // Causal MQA attention, 128-row q-blocks, heavy-first (LPT)
    mqa_attn_tc_kernel<<<ANQB * BB * HH, 256, ATTN_SMEM>>>(pQKV, pZh);

    // Output projection + bias, fp32 out
    f16_gemm_kernel<true, false>
        <<<dim3(HD / GBN, MTOT / GBM), 256, GEMM_SMEM>>>(pZh, pWorp, bo, out,
                                                         MTOT, HD, HD);
}

// round 14
// speedup vs baseline: 12.8794x; 1.0947x over previous
#include <cuda_runtime.h>
#include <cuda_fp16.h>
#include <math.h>
#include <stdint.h>

// Problem constants
#define BB 2
#define NN 2048
#define EE 1024
#define HH 16
#define DD 64
#define HD 1024            // H*D
#define MTOT 4096          // B*N
#define NQKV 1152          // HD + 2*DD

// ---------------------------------------------------------------------------
// Scratch (static device globals — no allocation allowed)
// ---------------------------------------------------------------------------
__device__ __half g_QKV[MTOT * NQKV];   // (B*N,1152): Q|K|V  fp16
__device__ __half g_Zh[MTOT * HD];      // attention out, fp16
__device__ __half g_Xh[MTOT * EE];      // X as fp16
__device__ __half g_WT[NQKV * EE];      // [Wq|Wk|Wv]^T  n-major rows, fp16
__device__ __half g_WoT[HD * HD];       // Wo^T n-major, fp16

// ---------------------------------------------------------------------------
// Helpers
// ---------------------------------------------------------------------------
__device__ __forceinline__ float ex2f(float x) {
    float y;
    asm("ex2.approx.f32 %0, %1;" : "=f"(y) : "f"(x));
    return y;
}

__device__ __forceinline__ uint32_t packh2(float lo, float hi) {
    __half2 h = __floats2half2_rn(lo, hi);
    return *(uint32_t*)&h;
}

__device__ __forceinline__ void mma_f16(float c[4], uint32_t a0, uint32_t a1,
                                        uint32_t a2, uint32_t a3,
                                        uint32_t b0, uint32_t b1) {
    asm volatile(
        "mma.sync.aligned.m16n8k16.row.col.f32.f16.f16.f32 "
        "{%0,%1,%2,%3}, {%4,%5,%6,%7}, {%8,%9}, {%0,%1,%2,%3};"
        : "+f"(c[0]), "+f"(c[1]), "+f"(c[2]), "+f"(c[3])
        : "r"(a0), "r"(a1), "r"(a2), "r"(a3), "r"(b0), "r"(b1));
}

__device__ __forceinline__ void cpa16(uint32_t s, const void* g) {
    asm volatile("cp.async.cg.shared.global [%0], [%1], 16;" :: "r"(s), "l"(g));
}

__device__ __forceinline__ void ldsm4(uint32_t& r0, uint32_t& r1,
                                      uint32_t& r2, uint32_t& r3, uint32_t a) {
    asm volatile("ldmatrix.sync.aligned.m8n8.x4.shared.b16 {%0,%1,%2,%3}, [%4];"
                 : "=r"(r0), "=r"(r1), "=r"(r2), "=r"(r3) : "r"(a));
}

__device__ __forceinline__ void ldsm4t(uint32_t& r0, uint32_t& r1,
                                       uint32_t& r2, uint32_t& r3, uint32_t a) {
    asm volatile("ldmatrix.sync.aligned.m8n8.x4.trans.shared.b16 {%0,%1,%2,%3}, [%4];"
                 : "=r"(r0), "=r"(r1), "=r"(r2), "=r"(r3) : "r"(a));
}

__device__ __forceinline__ uint32_t scaleh2(uint32_t w, float s) {
    __half2 h = *(__half2*)&w;
    float2 f = __half22float2(h);
    return packh2(f.x * s, f.y * s);
}

// ---------------------------------------------------------------------------
// Prologue kernels
// ---------------------------------------------------------------------------
// fp32 -> fp16, natural layout (A operands)
__global__ void tohalf_kernel(const float4* __restrict__ src,
                              uint2* __restrict__ dst, int n4)
{
    int i = blockIdx.x * blockDim.x + threadIdx.x;
    if (i < n4) {
        float4 v = src[i];
        uint2 o;
        o.x = packh2(v.x, v.y);
        o.y = packh2(v.z, v.w);
        dst[i] = o;
    }
}

// Transpose-pack: W[1024 rows k][N cols n] fp32 -> Wt[nOff+n][k] fp16 (ld 1024)
__global__ void packT_kernel(const float* __restrict__ W, __half* __restrict__ Wt,
                             int N, int nOff)
{
    __shared__ __half t[64][72];   // [n][k], padded
    const int k0 = blockIdx.y * 64, n0 = blockIdx.x * 64;
    const int tid = threadIdx.x;
    const int r = tid >> 4;
    const int c = (tid & 15) * 4;
#pragma unroll
    for (int i = 0; i < 4; i++) {
        int kk = r + i * 16;
        float4 v = *(const float4*)&W[(size_t)(k0 + kk) * N + n0 + c];
        t[c + 0][kk] = __float2half_rn(v.x);
        t[c + 1][kk] = __float2half_rn(v.y);
        t[c + 2][kk] = __float2half_rn(v.z);
        t[c + 3][kk] = __float2half_rn(v.w);
    }
    __syncthreads();
#pragma unroll
    for (int i = 0; i < 2; i++) {
        int idx = tid + i * 256;
        int n = idx >> 3, cc = (idx & 7) * 8;
        *(uint4*)&Wt[(size_t)(nOff + n0 + n) * 1024 + k0 + cc] =
            *(const uint4*)&t[n][cc];
    }
}

// ---------------------------------------------------------------------------
// fp16 GEMM, ldmatrix fragments, cp.async 3-stage pipeline.
// C[M,N] = A[M,K] @ BT[N,K]^T (+ bias). A,BT natural [row][k] fp16.
// smem: A [128][20w], B [128][20w] per stage (stride 80B -> LDSM conflict-free)
// ---------------------------------------------------------------------------
#define GBM 128
#define GBN 128
#define LDW 20
#define TBUF (128 * LDW)        // 2560 words per operand tile
#define STAGEH (2 * TBUF)       // 5120 words per stage
#define GEMM_SMEM (STAGEH * 3 * 4)   // 61440 bytes

template <bool BIAS, bool OUTHALF>
__global__ __launch_bounds__(256, 2)
void f16_gemm_kernel(const __half* __restrict__ A,
                     const __half* __restrict__ BT,
                     const float* __restrict__ bias, void* __restrict__ Cout,
                     int M, int N, int K)
{
    extern __shared__ uint32_t sm[];
    const uint32_t smemBase = (uint32_t)__cvta_generic_to_shared(sm);

    const int tid  = threadIdx.x;
    const int lane = tid & 31;
    const int w    = tid >> 5;
    const int wm   = w & 1;
    const int wn   = w >> 1;
    const int g    = lane >> 2;
    const int q    = lane & 3;
    const int lmat = lane >> 3;
    const int lrow = lane & 7;
    const int row0 = blockIdx.y * GBM;
    const int col0 = blockIdx.x * GBN;

    // cp.async staging: 2 chunks per thread per operand
    int soffA[2], soffB[2];
    const __half* gA[2];
    const __half* gB[2];
#pragma unroll
    for (int i = 0; i < 2; i++) {
        int idx = tid + i * 256;
        int r = idx >> 2, c = idx & 3;
        soffA[i] = r * LDW + c * 4;
        gA[i] = A + (size_t)(row0 + r) * K + c * 8;
        soffB[i] = TBUF + r * LDW + c * 4;
        gB[i] = BT + (size_t)(col0 + r) * K + c * 8;
    }

    // ldmatrix lane-constant address parts (words)
    // A-pattern: row = base + (lmat&1)*8 + lrow, col += (lmat>>1)*4
    const int aLanePart = (wm * 64 + (lmat & 1) * 8 + lrow) * LDW + (lmat >> 1) * 4;
    // B-pattern: row = base + (lmat>>1)*8 + lrow, col += (lmat&1)*4
    const int bLanePart = TBUF + (wn * 32 + (lmat >> 1) * 8 + lrow) * LDW + (lmat & 1) * 4;

    float c[4][4][4];
#pragma unroll
    for (int mi = 0; mi < 4; mi++)
#pragma unroll
        for (int ni = 0; ni < 4; ni++)
#pragma unroll
            for (int k = 0; k < 4; k++) c[mi][ni][k] = 0.0f;

    const int NT = K / 32;

    auto issue = [&](int st, int kt) {
        uint32_t s0 = smemBase + (uint32_t)(st * STAGEH) * 4;
#pragma unroll
        for (int i = 0; i < 2; i++) {
            cpa16(s0 + soffA[i] * 4, gA[i] + kt * 32);
            cpa16(s0 + soffB[i] * 4, gB[i] + kt * 32);
        }
        asm volatile("cp.async.commit_group;");
    };

    issue(0, 0);
    issue(1, 1);

    for (int kt = 0; kt < NT; kt++) {
        if (kt == NT - 1) asm volatile("cp.async.wait_group 0;");
        else              asm volatile("cp.async.wait_group 1;");
        __syncthreads();
        if (kt + 2 < NT) issue((kt + 2) % 3, kt + 2);

        const uint32_t st0 = smemBase + (uint32_t)((kt % 3) * STAGEH) * 4;
        const uint32_t aB = st0 + aLanePart * 4;
        const uint32_t bB = st0 + bLanePart * 4;

#pragma unroll
        for (int s2 = 0; s2 < 2; s2++) {
            const int kwB = s2 * 8 * 4;   // byte offset of k16 step
            uint32_t a[4][4];
#pragma unroll
            for (int mi = 0; mi < 4; mi++)
                ldsm4(a[mi][0], a[mi][1], a[mi][2], a[mi][3],
                      aB + mi * (16 * LDW * 4) + kwB);
            uint32_t bf[4][2];
            ldsm4(bf[0][0], bf[0][1], bf[1][0], bf[1][1], bB + kwB);
            ldsm4(bf[2][0], bf[2][1], bf[3][0], bf[3][1],
                  bB + 16 * LDW * 4 + kwB);
#pragma unroll
            for (int ni = 0; ni < 4; ni++)
#pragma unroll
                for (int mi = 0; mi < 4; mi++)
                    mma_f16(c[mi][ni], a[mi][0], a[mi][1], a[mi][2], a[mi][3],
                            bf[ni][0], bf[ni][1]);
        }
    }

#pragma unroll
    for (int mi = 0; mi < 4; mi++) {
        int row = row0 + wm * 64 + mi * 16 + g;
#pragma unroll
        for (int ni = 0; ni < 4; ni++) {
            int col = col0 + wn * 32 + ni * 8 + 2 * q;
            if (OUTHALF) {
                uint32_t* C32 = (uint32_t*)Cout;
                C32[(size_t)row * (N / 2) + col / 2] =
                    packh2(c[mi][ni][0], c[mi][ni][1]);
                C32[(size_t)(row + 8) * (N / 2) + col / 2] =
                    packh2(c[mi][ni][2], c[mi][ni][3]);
            } else {
                float* Cf = (float*)Cout;
                float2 v0 = make_float2(c[mi][ni][0], c[mi][ni][1]);
                float2 v1 = make_float2(c[mi][ni][2], c[mi][ni][3]);
                if (BIAS) {
                    float2 bv = *(const float2*)&bias[col];
                    v0.x += bv.x; v0.y += bv.y;
                    v1.x += bv.x; v1.y += bv.y;
                }
                *(float2*)&Cf[(size_t)row * N + col] = v0;
                *(float2*)&Cf[(size_t)(row + 8) * N + col] = v1;
            }
        }
    }
}

// ---------------------------------------------------------------------------
// fp16 causal MQA flash attention, 128 q-rows / 8 warps.
// K,V tiles: NATURAL [j][d/2 words] stride 36, cp.async double-buffered.
// S B-frags: ldmatrix.x4 (B-pattern on K rows).
// PV A-frags: ldmatrix.x4 (A-pattern on P); PV B-frags: ldmatrix.x4.trans on V.
// P buffer [i][j/2 words] stride 36. Base-2 online softmax.
// ---------------------------------------------------------------------------
#define AQR 128
#define ANQB (NN / AQR)     // 16 q-blocks per (b,h)
#define SKW 36              // row stride (words) for K, V, P
#define KVSTG (64 * SKW * 2)      // K+V per stage = 4608 words
#define PSOFF (2 * KVSTG)         // P at word 9216
#define ATTN_SMEM ((2 * KVSTG + AQR * SKW) * 4)   // 55296 bytes

__global__ __launch_bounds__(256, 2)
void mqa_attn_tc_kernel(const __half* __restrict__ QKV,
                        __half* __restrict__ Z)
{
    extern __shared__ uint32_t dsm[];
    const uint32_t smemBase = (uint32_t)__cvta_generic_to_shared(dsm);
    uint32_t* Ps = dsm + PSOFF;

    const int wid  = blockIdx.x;
    const int qb   = (ANQB - 1) - (wid >> 5);   // heavy-first (LPT)
    const int bh   = wid & 31;
    const int b    = bh >> 4;
    const int h    = bh & 15;
    const int tid  = threadIdx.x;
    const int lane = tid & 31;
    const int w    = tid >> 5;
    const int g    = lane >> 2;
    const int q    = lane & 3;
    const int lmat = lane >> 3;
    const int lrow = lane & 7;

    // Q fragments, scaled by log2(e)/sqrt(D)
    const float QS = 0.125f * 1.4426950408889634f;
    uint32_t aq[4][4];
    const uint32_t* Qw = (const uint32_t*)QKV +
        (size_t)(b * NN + qb * AQR + w * 16) * (NQKV / 2) + h * (DD / 2);
#pragma unroll
    for (int t = 0; t < 4; t++) {
        aq[t][0] = scaleh2(Qw[(size_t)g * (NQKV / 2)       + t * 8 + q    ], QS);
        aq[t][1] = scaleh2(Qw[(size_t)(g + 8) * (NQKV / 2) + t * 8 + q    ], QS);
        aq[t][2] = scaleh2(Qw[(size_t)g * (NQKV / 2)       + t * 8 + q + 4], QS);
        aq[t][3] = scaleh2(Qw[(size_t)(g + 8) * (NQKV / 2) + t * 8 + q + 4], QS);
    }

    float o[8][4];
#pragma unroll
    for (int nt = 0; nt < 8; nt++)
#pragma unroll
        for (int k = 0; k < 4; k++) o[nt][k] = 0.0f;
    float m0 = -1e30f, m1 = -1e30f, l0 = 0.0f, l1 = 0.0f;

    const int prow0 = w * 16 + g;
    const int NT    = 2 * qb + 2;

    // ldmatrix lane-constant parts (words)
    // K (B-pattern): row = ntpair*16 + (lmat>>1)*8 + lrow, col = t*8 + (lmat&1)*4
    const int kLane = ((lmat >> 1) * 8 + lrow) * SKW + (lmat & 1) * 4;
    // P (A-pattern): row = w*16 + (lmat&1)*8 + lrow, col = t*8 + (lmat>>1)*4
    const uint32_t pLane = smemBase +
        (PSOFF + (w * 16 + (lmat & 1) * 8 + lrow) * SKW + (lmat >> 1) * 4) * 4;
    // V (trans B): row j = 16t + (lmat&1)*8 + lrow, col = ntpair*8 + (lmat>>1)*4
    const int vLane = ((lmat & 1) * 8 + lrow) * SKW + (lmat >> 1) * 4;

    // KV prefetch: K and V natural rows, 2 chunks each per thread
    auto issueKV = [&](int st, int kt) {
        const __half* base = QKV + (size_t)(b * NN + kt * 64) * NQKV;
        uint32_t sK = smemBase + (uint32_t)(st * KVSTG) * 4;
        uint32_t sV = sK + (64 * SKW) * 4;
#pragma unroll
        for (int i = 0; i < 2; i++) {
            int idx = tid + i * 256;
            int j = idx >> 3, cc = idx & 7;
            const __half* rowp = base + (size_t)j * NQKV + HD + cc * 8;
            cpa16(sK + (j * SKW + cc * 4) * 4, rowp);
            cpa16(sV + (j * SKW + cc * 4) * 4, rowp + DD);
        }
        asm volatile("cp.async.commit_group;");
    };

    issueKV(0, 0);

    for (int kt = 0; kt < NT; kt++) {
        if (kt + 1 < NT) {
            issueKV((kt + 1) & 1, kt + 1);
            asm volatile("cp.async.wait_group 1;");
        } else {
            asm volatile("cp.async.wait_group 0;");
        }
        __syncthreads();

        const uint32_t sK = smemBase + (uint32_t)(((kt & 1) * KVSTG)) * 4;
        const uint32_t sV = sK + (64 * SKW) * 4;

        const bool active = (kt * 64) <= (qb * AQR + w * 16 + 15);
        if (active) {
            // --- S = Q K^T ---
            float s[8][4];
#pragma unroll
            for (int nt = 0; nt < 8; nt++)
                s[nt][0] = s[nt][1] = s[nt][2] = s[nt][3] = 0.0f;
#pragma unroll
            for (int t = 0; t < 4; t++) {
                uint32_t bf[8][2];
#pragma unroll
                for (int p = 0; p < 4; p++)
                    ldsm4(bf[2 * p][0], bf[2 * p][1], bf[2 * p + 1][0],
                          bf[2 * p + 1][1],
                          sK + (kLane + p * 16 * SKW + t * 8) * 4);
#pragma unroll
                for (int nt = 0; nt < 8; nt++)
                    mma_f16(s[nt], aq[t][0], aq[t][1], aq[t][2], aq[t][3],
                            bf[nt][0], bf[nt][1]);
            }

            // --- causal mask ---
            const int off = kt * 64 - qb * AQR;
            if (off + 63 > w * 16) {
                const int r0 = prow0, r1 = prow0 + 8;
#pragma unroll
                for (int nt = 0; nt < 8; nt++) {
                    int c0 = nt * 8 + 2 * q + off, c1 = c0 + 1;
                    if (c0 > r0) s[nt][0] = -1e30f;
                    if (c1 > r0) s[nt][1] = -1e30f;
                    if (c0 > r1) s[nt][2] = -1e30f;
                    if (c1 > r1) s[nt][3] = -1e30f;
                }
            }

            // --- online softmax (base-2) ---
            float ml0 = -1e30f, ml1 = -1e30f;
#pragma unroll
            for (int nt = 0; nt < 8; nt++) {
                ml0 = fmaxf(ml0, fmaxf(s[nt][0], s[nt][1]));
                ml1 = fmaxf(ml1, fmaxf(s[nt][2], s[nt][3]));
            }
            ml0 = fmaxf(ml0, __shfl_xor_sync(0xffffffffu, ml0, 1));
            ml0 = fmaxf(ml0, __shfl_xor_sync(0xffffffffu, ml0, 2));
            ml1 = fmaxf(ml1, __shfl_xor_sync(0xffffffffu, ml1, 1));
            ml1 = fmaxf(ml1, __shfl_xor_sync(0xffffffffu, ml1, 2));
            const float mn0 = fmaxf(m0, ml0), mn1 = fmaxf(m1, ml1);
            const float sc0 = ex2f(m0 - mn0), sc1 = ex2f(m1 - mn1);
            float ls0 = 0.0f, ls1 = 0.0f;
#pragma unroll
            for (int nt = 0; nt < 8; nt++) {
                s[nt][0] = ex2f(s[nt][0] - mn0);
                s[nt][1] = ex2f(s[nt][1] - mn0);
                s[nt][2] = ex2f(s[nt][2] - mn1);
                s[nt][3] = ex2f(s[nt][3] - mn1);
                ls0 += s[nt][0] + s[nt][1];
                ls1 += s[nt][2] + s[nt][3];
            }
            ls0 += __shfl_xor_sync(0xffffffffu, ls0, 1);
            ls0 += __shfl_xor_sync(0xffffffffu, ls0, 2);
            ls1 += __shfl_xor_sync(0xffffffffu, ls1, 1);
            ls1 += __shfl_xor_sync(0xffffffffu, ls1, 2);
            l0 = l0 * sc0 + ls0; m0 = mn0;
            l1 = l1 * sc1 + ls1; m1 = mn1;
#pragma unroll
            for (int nt = 0; nt < 8; nt++) {
                o[nt][0] *= sc0; o[nt][1] *= sc0;
                o[nt][2] *= sc1; o[nt][3] *= sc1;
            }

            // --- P to smem (half2 words) ---
#pragma unroll
            for (int nt = 0; nt < 8; nt++) {
                Ps[prow0 * SKW + nt * 4 + q]       = packh2(s[nt][0], s[nt][1]);
                Ps[(prow0 + 8) * SKW + nt * 4 + q] = packh2(s[nt][2], s[nt][3]);
            }
            __syncwarp();

            // --- O += P V ---
#pragma unroll
            for (int t = 0; t < 4; t++) {
                uint32_t pa[4];
                ldsm4(pa[0], pa[1], pa[2], pa[3], pLane + (t * 8) * 4);
                uint32_t vf[8][2];
#pragma unroll
                for (int p = 0; p < 4; p++)
                    ldsm4t(vf[2 * p][0], vf[2 * p][1], vf[2 * p + 1][0],
                           vf[2 * p + 1][1],
                           sV + (vLane + t * 16 * SKW + p * 8) * 4);
#pragma unroll
                for (int nt = 0; nt < 8; nt++)
                    mma_f16(o[nt], pa[0], pa[1], pa[2], pa[3],
                            vf[nt][0], vf[nt][1]);
            }
        }
        __syncthreads();   // readers done before stage reuse
    }

    // --- normalize, write Z as fp16 ---
    const float i0 = 1.0f / l0, i1 = 1.0f / l1;
    uint32_t* Zw = (uint32_t*)Z +
        (size_t)(b * NN + qb * AQR + prow0) * (HD / 2) + h * (DD / 2);
#pragma unroll
    for (int nt = 0; nt < 8; nt++) {
        Zw[nt * 4 + q] = packh2(o[nt][0] * i0, o[nt][1] * i0);
        Zw[(size_t)8 * (HD / 2) + nt * 4 + q] = packh2(o[nt][2] * i1,
                                                       o[nt][3] * i1);
    }
}

// ---------------------------------------------------------------------------
// Launch
// ---------------------------------------------------------------------------
extern "C" void kernel_launch(void* const* d_in, const int* in_sizes, int n_in,
                              void* d_out, int out_size)
{
    const float* X  = (const float*)d_in[0];
    const float* Wq = (const float*)d_in[1];
    const float* Wk = (const float*)d_in[2];
    const float* Wv = (const float*)d_in[3];
    const float* Wo = (const float*)d_in[4];
    const float* bo = (const float*)d_in[5];
    float* out = (float*)d_out;

    __half *pQKV, *pZh, *pXh, *pWT, *pWoT;
    cudaGetSymbolAddress((void**)&pQKV, g_QKV);
    cudaGetSymbolAddress((void**)&pZh,  g_Zh);
    cudaGetSymbolAddress((void**)&pXh,  g_Xh);
    cudaGetSymbolAddress((void**)&pWT,  g_WT);
    cudaGetSymbolAddress((void**)&pWoT, g_WoT);

    cudaFuncSetAttribute(f16_gemm_kernel<false, true>,
                         cudaFuncAttributeMaxDynamicSharedMemorySize, GEMM_SMEM);
    cudaFuncSetAttribute(f16_gemm_kernel<true, false>,
                         cudaFuncAttributeMaxDynamicSharedMemorySize, GEMM_SMEM);
    cudaFuncSetAttribute(mqa_attn_tc_kernel,
                         cudaFuncAttributeMaxDynamicSharedMemorySize, ATTN_SMEM);

    // Prologue: X->half; transpose-pack weights n-major
    tohalf_kernel<<<(MTOT * EE / 4 + 255) / 256, 256>>>((const float4*)X,
                                                        (uint2*)pXh,
                                                        MTOT * EE / 4);
    packT_kernel<<<dim3(16, 16), 256>>>(Wq, pWT, 1024, 0);
    packT_kernel<<<dim3(1, 16), 256>>>(Wk, pWT, 64, 1024);
    packT_kernel<<<dim3(1, 16), 256>>>(Wv, pWT, 64, 1088);
    packT_kernel<<<dim3(16, 16), 256>>>(Wo, pWoT, 1024, 0);

    // Fused QKV projection: (4096,1024)@(1024,1152), fp16 out
    f16_gemm_kernel<false, true>
        <<<dim3(NQKV / GBN, MTOT / GBM), 256, GEMM_SMEM>>>(pXh, pWT, nullptr,
                                                           pQKV, MTOT, NQKV, EE);

    // Causal MQA attention, 128-row q-blocks, heavy-first (LPT)
    mqa_attn_tc_kernel<<<ANQB * BB * HH, 256, ATTN_SMEM>>>(pQKV, pZh);

    // Output projection + bias, fp32 out
    f16_gemm_kernel<true, false>
        <<<dim3(HD / GBN, MTOT / GBM), 256, GEMM_SMEM>>>(pZh, pWoT, bo, out,
                                                         MTOT, HD, HD);
}

// round 16
// speedup vs baseline: 13.3692x; 1.0380x over previous
#include <cuda_runtime.h>
#include <cuda_fp16.h>
#include <math.h>
#include <stdint.h>

// Problem constants
#define BB 2
#define NN 2048
#define EE 1024
#define HH 16
#define DD 64
#define HD 1024            // H*D
#define MTOT 4096          // B*N
#define NQKV 1152          // HD + 2*DD

// ---------------------------------------------------------------------------
// Scratch (static device globals — no allocation allowed)
// ---------------------------------------------------------------------------
__device__ __half g_QKV[MTOT * NQKV];   // (B*N,1152): Q|K|V  fp16
__device__ __half g_Zh[MTOT * HD];      // attention out, fp16
__device__ __half g_Xh[MTOT * EE];      // X as fp16
__device__ __half g_WT[NQKV * EE];      // [Wq|Wk|Wv]^T  n-major rows, fp16
__device__ __half g_WoT[HD * HD];       // Wo^T n-major, fp16

// ---------------------------------------------------------------------------
// Helpers
// ---------------------------------------------------------------------------
__device__ __forceinline__ float ex2f(float x) {
    float y;
    asm("ex2.approx.f32 %0, %1;" : "=f"(y) : "f"(x));
    return y;
}

__device__ __forceinline__ uint32_t packh2(float lo, float hi) {
    __half2 h = __floats2half2_rn(lo, hi);
    return *(uint32_t*)&h;
}

__device__ __forceinline__ void mma_f16(float c[4], uint32_t a0, uint32_t a1,
                                        uint32_t a2, uint32_t a3,
                                        uint32_t b0, uint32_t b1) {
    asm volatile(
        "mma.sync.aligned.m16n8k16.row.col.f32.f16.f16.f32 "
        "{%0,%1,%2,%3}, {%4,%5,%6,%7}, {%8,%9}, {%0,%1,%2,%3};"
        : "+f"(c[0]), "+f"(c[1]), "+f"(c[2]), "+f"(c[3])
        : "r"(a0), "r"(a1), "r"(a2), "r"(a3), "r"(b0), "r"(b1));
}

__device__ __forceinline__ void cpa16(uint32_t s, const void* g) {
    asm volatile("cp.async.cg.shared.global [%0], [%1], 16;" :: "r"(s), "l"(g));
}

__device__ __forceinline__ void ldsm4(uint32_t& r0, uint32_t& r1,
                                      uint32_t& r2, uint32_t& r3, uint32_t a) {
    asm volatile("ldmatrix.sync.aligned.m8n8.x4.shared.b16 {%0,%1,%2,%3}, [%4];"
                 : "=r"(r0), "=r"(r1), "=r"(r2), "=r"(r3) : "r"(a));
}

__device__ __forceinline__ void ldsm4t(uint32_t& r0, uint32_t& r1,
                                       uint32_t& r2, uint32_t& r3, uint32_t a) {
    asm volatile("ldmatrix.sync.aligned.m8n8.x4.trans.shared.b16 {%0,%1,%2,%3}, [%4];"
                 : "=r"(r0), "=r"(r1), "=r"(r2), "=r"(r3) : "r"(a));
}

__device__ __forceinline__ uint32_t scaleh2(uint32_t w, float s) {
    __half2 h = *(__half2*)&w;
    float2 f = __half22float2(h);
    return packh2(f.x * s, f.y * s);
}

// ---------------------------------------------------------------------------
// FUSED prologue: one launch.
// Blocks [0, 4096): X fp32 -> fp16 (float4 per thread).
// Blocks [4096, 4640): transpose-pack Wq/Wk/Wv/Wo into n-major fp16 rows.
// ---------------------------------------------------------------------------
#define PREP_X_BLOCKS (MTOT * EE / 4 / 256)   // 4096

__global__ __launch_bounds__(256)
void prep_kernel(const float* __restrict__ X,
                 const float* __restrict__ Wq, const float* __restrict__ Wk,
                 const float* __restrict__ Wv, const float* __restrict__ Wo,
                 __half* __restrict__ Xh, __half* __restrict__ WT,
                 __half* __restrict__ WoT)
{
    __shared__ __half t[64][72];   // transpose staging [n][k]
    const int bid = blockIdx.x;
    const int tid = threadIdx.x;

    if (bid < PREP_X_BLOCKS) {
        int i = bid * 256 + tid;
        float4 v = ((const float4*)X)[i];
        uint2 o;
        o.x = packh2(v.x, v.y);
        o.y = packh2(v.z, v.w);
        ((uint2*)Xh)[i] = o;
        return;
    }

    // Weight transpose-pack jobs
    int pb = bid - PREP_X_BLOCKS;
    const float* W;
    __half* dst;
    int N, nOff, bx, by;
    if (pb < 256)      { W = Wq; dst = WT;  N = 1024; nOff = 0;    bx = pb & 15; by = pb >> 4; }
    else if (pb < 272) { W = Wk; dst = WT;  N = 64;   nOff = 1024; bx = 0;       by = pb - 256; }
    else if (pb < 288) { W = Wv; dst = WT;  N = 64;   nOff = 1088; bx = 0;       by = pb - 272; }
    else               { pb -= 288; W = Wo; dst = WoT; N = 1024; nOff = 0; bx = pb & 15; by = pb >> 4; }

    const int k0 = by * 64, n0 = bx * 64;
    const int r = tid >> 4;
    const int c = (tid & 15) * 4;
#pragma unroll
    for (int i = 0; i < 4; i++) {
        int kk = r + i * 16;
        float4 v = *(const float4*)&W[(size_t)(k0 + kk) * N + n0 + c];
        t[c + 0][kk] = __float2half_rn(v.x);
        t[c + 1][kk] = __float2half_rn(v.y);
        t[c + 2][kk] = __float2half_rn(v.z);
        t[c + 3][kk] = __float2half_rn(v.w);
    }
    __syncthreads();
#pragma unroll
    for (int i = 0; i < 2; i++) {
        int idx = tid + i * 256;
        int n = idx >> 3, cc = (idx & 7) * 8;
        *(uint4*)&dst[(size_t)(nOff + n0 + n) * 1024 + k0 + cc] =
            *(const uint4*)&t[n][cc];
    }
}

// ---------------------------------------------------------------------------
// fp16 GEMM, ldmatrix fragments, cp.async 3-stage pipeline (R13 proven).
// C[M,N] = A[M,K] @ BT[N,K]^T (+ bias). A,BT natural [row][k] fp16.
// ---------------------------------------------------------------------------
#define GBM 128
#define GBN 128
#define LDW 20
#define TBUF (128 * LDW)        // 2560 words per operand tile
#define STAGEH (2 * TBUF)       // 5120 words per stage
#define GEMM_SMEM (STAGEH * 3 * 4)   // 61440 bytes

template <bool BIAS, bool OUTHALF>
__global__ __launch_bounds__(256, 2)
void f16_gemm_kernel(const __half* __restrict__ A,
                     const __half* __restrict__ BT,
                     const float* __restrict__ bias, void* __restrict__ Cout,
                     int M, int N, int K)
{
    extern __shared__ uint32_t sm[];
    const uint32_t smemBase = (uint32_t)__cvta_generic_to_shared(sm);

    const int tid  = threadIdx.x;
    const int lane = tid & 31;
    const int w    = tid >> 5;
    const int wm   = w & 1;
    const int wn   = w >> 1;
    const int g    = lane >> 2;
    const int q    = lane & 3;
    const int lmat = lane >> 3;
    const int lrow = lane & 7;
    const int row0 = blockIdx.y * GBM;
    const int col0 = blockIdx.x * GBN;

    int soffA[2], soffB[2];
    const __half* gA[2];
    const __half* gB[2];
#pragma unroll
    for (int i = 0; i < 2; i++) {
        int idx = tid + i * 256;
        int r = idx >> 2, c = idx & 3;
        soffA[i] = r * LDW + c * 4;
        gA[i] = A + (size_t)(row0 + r) * K + c * 8;
        soffB[i] = TBUF + r * LDW + c * 4;
        gB[i] = BT + (size_t)(col0 + r) * K + c * 8;
    }

    const int aLanePart = (wm * 64 + (lmat & 1) * 8 + lrow) * LDW + (lmat >> 1) * 4;
    const int bLanePart = TBUF + (wn * 32 + (lmat >> 1) * 8 + lrow) * LDW + (lmat & 1) * 4;

    float c[4][4][4];
#pragma unroll
    for (int mi = 0; mi < 4; mi++)
#pragma unroll
        for (int ni = 0; ni < 4; ni++)
#pragma unroll
            for (int k = 0; k < 4; k++) c[mi][ni][k] = 0.0f;

    const int NT = K / 32;

    auto issue = [&](int st, int kt) {
        uint32_t s0 = smemBase + (uint32_t)(st * STAGEH) * 4;
#pragma unroll
        for (int i = 0; i < 2; i++) {
            cpa16(s0 + soffA[i] * 4, gA[i] + kt * 32);
            cpa16(s0 + soffB[i] * 4, gB[i] + kt * 32);
        }
        asm volatile("cp.async.commit_group;");
    };

    issue(0, 0);
    issue(1, 1);

    for (int kt = 0; kt < NT; kt++) {
        if (kt == NT - 1) asm volatile("cp.async.wait_group 0;");
        else              asm volatile("cp.async.wait_group 1;");
        __syncthreads();
        if (kt + 2 < NT) issue((kt + 2) % 3, kt + 2);

        const uint32_t st0 = smemBase + (uint32_t)((kt % 3) * STAGEH) * 4;
        const uint32_t aB = st0 + aLanePart * 4;
        const uint32_t bB = st0 + bLanePart * 4;

#pragma unroll
        for (int s2 = 0; s2 < 2; s2++) {
            const int kwB = s2 * 8 * 4;
            uint32_t a[4][4];
#pragma unroll
            for (int mi = 0; mi < 4; mi++)
                ldsm4(a[mi][0], a[mi][1], a[mi][2], a[mi][3],
                      aB + mi * (16 * LDW * 4) + kwB);
            uint32_t bf[4][2];
            ldsm4(bf[0][0], bf[0][1], bf[1][0], bf[1][1], bB + kwB);
            ldsm4(bf[2][0], bf[2][1], bf[3][0], bf[3][1],
                  bB + 16 * LDW * 4 + kwB);
#pragma unroll
            for (int ni = 0; ni < 4; ni++)
#pragma unroll
                for (int mi = 0; mi < 4; mi++)
                    mma_f16(c[mi][ni], a[mi][0], a[mi][1], a[mi][2], a[mi][3],
                            bf[ni][0], bf[ni][1]);
        }
    }

#pragma unroll
    for (int mi = 0; mi < 4; mi++) {
        int row = row0 + wm * 64 + mi * 16 + g;
#pragma unroll
        for (int ni = 0; ni < 4; ni++) {
            int col = col0 + wn * 32 + ni * 8 + 2 * q;
            if (OUTHALF) {
                uint32_t* C32 = (uint32_t*)Cout;
                C32[(size_t)row * (N / 2) + col / 2] =
                    packh2(c[mi][ni][0], c[mi][ni][1]);
                C32[(size_t)(row + 8) * (N / 2) + col / 2] =
                    packh2(c[mi][ni][2], c[mi][ni][3]);
            } else {
                float* Cf = (float*)Cout;
                float2 v0 = make_float2(c[mi][ni][0], c[mi][ni][1]);
                float2 v1 = make_float2(c[mi][ni][2], c[mi][ni][3]);
                if (BIAS) {
                    float2 bv = *(const float2*)&bias[col];
                    v0.x += bv.x; v0.y += bv.y;
                    v1.x += bv.x; v1.y += bv.y;
                }
                *(float2*)&Cf[(size_t)row * N + col] = v0;
                *(float2*)&Cf[(size_t)(row + 8) * N + col] = v1;
            }
        }
    }
}

// ---------------------------------------------------------------------------
// fp16 causal MQA flash attention, 128 q-rows / 8 warps.
// K,V tiles natural [j][d/2 words] stride 36, cp.async 3-STAGE ring:
// one __syncthreads per tile (issue kt+2 after the post-wait barrier; stage
// (kt+2)%3's last readers ran at kt-1 and are past the barrier at kt).
// ---------------------------------------------------------------------------
#define AQR 128
#define ANQB (NN / AQR)     // 16 q-blocks per (b,h)
#define SKW 36              // row stride (words) for K, V, P
#define KVSTG (64 * SKW * 2)      // K+V per stage = 4608 words
#define PSOFF (3 * KVSTG)         // P after 3 stages
#define ATTN_SMEM ((3 * KVSTG + AQR * SKW) * 4)   // 73728 bytes

__global__ __launch_bounds__(256, 2)
void mqa_attn_tc_kernel(const __half* __restrict__ QKV,
                        __half* __restrict__ Z)
{
    extern __shared__ uint32_t dsm[];
    const uint32_t smemBase = (uint32_t)__cvta_generic_to_shared(dsm);
    uint32_t* Ps = dsm + PSOFF;

    const int wid  = blockIdx.x;
    const int qb   = (ANQB - 1) - (wid >> 5);   // heavy-first (LPT)
    const int bh   = wid & 31;
    const int b    = bh >> 4;
    const int h    = bh & 15;
    const int tid  = threadIdx.x;
    const int lane = tid & 31;
    const int w    = tid >> 5;
    const int g    = lane >> 2;
    const int q    = lane & 3;
    const int lmat = lane >> 3;
    const int lrow = lane & 7;

    // Q fragments, scaled by log2(e)/sqrt(D)
    const float QS = 0.125f * 1.4426950408889634f;
    uint32_t aq[4][4];
    const uint32_t* Qw = (const uint32_t*)QKV +
        (size_t)(b * NN + qb * AQR + w * 16) * (NQKV / 2) + h * (DD / 2);
#pragma unroll
    for (int t = 0; t < 4; t++) {
        aq[t][0] = scaleh2(Qw[(size_t)g * (NQKV / 2)       + t * 8 + q    ], QS);
        aq[t][1] = scaleh2(Qw[(size_t)(g + 8) * (NQKV / 2) + t * 8 + q    ], QS);
        aq[t][2] = scaleh2(Qw[(size_t)g * (NQKV / 2)       + t * 8 + q + 4], QS);
        aq[t][3] = scaleh2(Qw[(size_t)(g + 8) * (NQKV / 2) + t * 8 + q + 4], QS);
    }

    float o[8][4];
#pragma unroll
    for (int nt = 0; nt < 8; nt++)
#pragma unroll
        for (int k = 0; k < 4; k++) o[nt][k] = 0.0f;
    float m0 = -1e30f, m1 = -1e30f, l0 = 0.0f, l1 = 0.0f;

    const int prow0 = w * 16 + g;
    const int NT    = 2 * qb + 2;

    // ldmatrix lane-constant parts (words)
    const int kLane = ((lmat >> 1) * 8 + lrow) * SKW + (lmat & 1) * 4;
    const uint32_t pLane = smemBase +
        (PSOFF + (w * 16 + (lmat & 1) * 8 + lrow) * SKW + (lmat >> 1) * 4) * 4;
    const int vLane = ((lmat & 1) * 8 + lrow) * SKW + (lmat >> 1) * 4;

    auto issueKV = [&](int st, int kt) {
        const __half* base = QKV + (size_t)(b * NN + kt * 64) * NQKV;
        uint32_t sK = smemBase + (uint32_t)(st * KVSTG) * 4;
        uint32_t sV = sK + (64 * SKW) * 4;
#pragma unroll
        for (int i = 0; i < 2; i++) {
            int idx = tid + i * 256;
            int j = idx >> 3, cc = idx & 7;
            const __half* rowp = base + (size_t)j * NQKV + HD + cc * 8;
            cpa16(sK + (j * SKW + cc * 4) * 4, rowp);
            cpa16(sV + (j * SKW + cc * 4) * 4, rowp + DD);
        }
        asm volatile("cp.async.commit_group;");
    };

    issueKV(0, 0);
    if (NT > 1) issueKV(1, 1);

    for (int kt = 0; kt < NT; kt++) {
        if (kt + 1 < NT) asm volatile("cp.async.wait_group 1;");
        else             asm volatile("cp.async.wait_group 0;");
        __syncthreads();
        if (kt + 2 < NT) issueKV((kt + 2) % 3, kt + 2);

        const uint32_t sK = smemBase + (uint32_t)(((kt % 3) * KVSTG)) * 4;
        const uint32_t sV = sK + (64 * SKW) * 4;

        const bool active = (kt * 64) <= (qb * AQR + w * 16 + 15);
        if (active) {
            // --- S = Q K^T ---
            float s[8][4];
#pragma unroll
            for (int nt = 0; nt < 8; nt++)
                s[nt][0] = s[nt][1] = s[nt][2] = s[nt][3] = 0.0f;
#pragma unroll
            for (int t = 0; t < 4; t++) {
                uint32_t bf[8][2];
#pragma unroll
                for (int p = 0; p < 4; p++)
                    ldsm4(bf[2 * p][0], bf[2 * p][1], bf[2 * p + 1][0],
                          bf[2 * p + 1][1],
                          sK + (kLane + p * 16 * SKW + t * 8) * 4);
#pragma unroll
                for (int nt = 0; nt < 8; nt++)
                    mma_f16(s[nt], aq[t][0], aq[t][1], aq[t][2], aq[t][3],
                            bf[nt][0], bf[nt][1]);
            }

            // --- causal mask ---
            const int off = kt * 64 - qb * AQR;
            if (off + 63 > w * 16) {
                const int r0 = prow0, r1 = prow0 + 8;
#pragma unroll
                for (int nt = 0; nt < 8; nt++) {
                    int c0 = nt * 8 + 2 * q + off, c1 = c0 + 1;
                    if (c0 > r0) s[nt][0] = -1e30f;
                    if (c1 > r0) s[nt][1] = -1e30f;
                    if (c0 > r1) s[nt][2] = -1e30f;
                    if (c1 > r1) s[nt][3] = -1e30f;
                }
            }

            // --- online softmax (base-2) ---
            float ml0 = -1e30f, ml1 = -1e30f;
#pragma unroll
            for (int nt = 0; nt < 8; nt++) {
                ml0 = fmaxf(ml0, fmaxf(s[nt][0], s[nt][1]));
                ml1 = fmaxf(ml1, fmaxf(s[nt][2], s[nt][3]));
            }
            ml0 = fmaxf(ml0, __shfl_xor_sync(0xffffffffu, ml0, 1));
            ml0 = fmaxf(ml0, __shfl_xor_sync(0xffffffffu, ml0, 2));
            ml1 = fmaxf(ml1, __shfl_xor_sync(0xffffffffu, ml1, 1));
            ml1 = fmaxf(ml1, __shfl_xor_sync(0xffffffffu, ml1, 2));
            const float mn0 = fmaxf(m0, ml0), mn1 = fmaxf(m1, ml1);
            const float sc0 = ex2f(m0 - mn0), sc1 = ex2f(m1 - mn1);
            float ls0 = 0.0f, ls1 = 0.0f;
#pragma unroll
            for (int nt = 0; nt < 8; nt++) {
                s[nt][0] = ex2f(s[nt][0] - mn0);
                s[nt][1] = ex2f(s[nt][1] - mn0);
                s[nt][2] = ex2f(s[nt][2] - mn1);
                s[nt][3] = ex2f(s[nt][3] - mn1);
                ls0 += s[nt][0] + s[nt][1];
                ls1 += s[nt][2] + s[nt][3];
            }
            ls0 += __shfl_xor_sync(0xffffffffu, ls0, 1);
            ls0 += __shfl_xor_sync(0xffffffffu, ls0, 2);
            ls1 += __shfl_xor_sync(0xffffffffu, ls1, 1);
            ls1 += __shfl_xor_sync(0xffffffffu, ls1, 2);
            l0 = l0 * sc0 + ls0; m0 = mn0;
            l1 = l1 * sc1 + ls1; m1 = mn1;
#pragma unroll
            for (int nt = 0; nt < 8; nt++) {
                o[nt][0] *= sc0; o[nt][1] *= sc0;
                o[nt][2] *= sc1; o[nt][3] *= sc1;
            }

            // --- P to smem (half2 words), per-warp region ---
#pragma unroll
            for (int nt = 0; nt < 8; nt++) {
                Ps[prow0 * SKW + nt * 4 + q]       = packh2(s[nt][0], s[nt][1]);
                Ps[(prow0 + 8) * SKW + nt * 4 + q] = packh2(s[nt][2], s[nt][3]);
            }
            __syncwarp();

            // --- O += P V ---
#pragma unroll
            for (int t = 0; t < 4; t++) {
                uint32_t pa[4];
                ldsm4(pa[0], pa[1], pa[2], pa[3], pLane + (t * 8) * 4);
                uint32_t vf[8][2];
#pragma unroll
                for (int p = 0; p < 4; p++)
                    ldsm4t(vf[2 * p][0], vf[2 * p][1], vf[2 * p + 1][0],
                           vf[2 * p + 1][1],
                           sV + (vLane + t * 16 * SKW + p * 8) * 4);
#pragma unroll
                for (int nt = 0; nt < 8; nt++)
                    mma_f16(o[nt], pa[0], pa[1], pa[2], pa[3],
                            vf[nt][0], vf[nt][1]);
            }
        }
    }

    // --- normalize, write Z as fp16 ---
    const float i0 = 1.0f / l0, i1 = 1.0f / l1;
    uint32_t* Zw = (uint32_t*)Z +
        (size_t)(b * NN + qb * AQR + prow0) * (HD / 2) + h * (DD / 2);
#pragma unroll
    for (int nt = 0; nt < 8; nt++) {
        Zw[nt * 4 + q] = packh2(o[nt][0] * i0, o[nt][1] * i0);
        Zw[(size_t)8 * (HD / 2) + nt * 4 + q] = packh2(o[nt][2] * i1,
                                                       o[nt][3] * i1);
    }
}

// ---------------------------------------------------------------------------
// Launch
// ---------------------------------------------------------------------------
extern "C" void kernel_launch(void* const* d_in, const int* in_sizes, int n_in,
                              void* d_out, int out_size)
{
    const float* X  = (const float*)d_in[0];
    const float* Wq = (const float*)d_in[1];
    const float* Wk = (const float*)d_in[2];
    const float* Wv = (const float*)d_in[3];
    const float* Wo = (const float*)d_in[4];
    const float* bo = (const float*)d_in[5];
    float* out = (float*)d_out;

    __half *pQKV, *pZh, *pXh, *pWT, *pWoT;
    cudaGetSymbolAddress((void**)&pQKV, g_QKV);
    cudaGetSymbolAddress((void**)&pZh,  g_Zh);
    cudaGetSymbolAddress((void**)&pXh,  g_Xh);
    cudaGetSymbolAddress((void**)&pWT,  g_WT);
    cudaGetSymbolAddress((void**)&pWoT, g_WoT);

    cudaFuncSetAttribute(f16_gemm_kernel<false, true>,
                         cudaFuncAttributeMaxDynamicSharedMemorySize, GEMM_SMEM);
    cudaFuncSetAttribute(f16_gemm_kernel<true, false>,
                         cudaFuncAttributeMaxDynamicSharedMemorySize, GEMM_SMEM);
    cudaFuncSetAttribute(mqa_attn_tc_kernel,
                         cudaFuncAttributeMaxDynamicSharedMemorySize, ATTN_SMEM);

    // Fused prologue: X->half + all weight transpose-packs, ONE launch
    prep_kernel<<<PREP_X_BLOCKS + 544, 256>>>(X, Wq, Wk, Wv, Wo,
                                              pXh, pWT, pWoT);

    // Fused QKV projection: (4096,1024)@(1024,1152), fp16 out
    f16_gemm_kernel<false, true>
        <<<dim3(NQKV / GBN, MTOT / GBM), 256, GEMM_SMEM>>>(pXh, pWT, nullptr,
                                                           pQKV, MTOT, NQKV, EE);

    // Causal MQA attention, 128-row q-blocks, heavy-first (LPT)
    mqa_attn_tc_kernel<<<ANQB * BB * HH, 256, ATTN_SMEM>>>(pQKV, pZh);

    // Output projection + bias, fp32 out
    f16_gemm_kernel<true, false>
        <<<dim3(HD / GBN, MTOT / GBM), 256, GEMM_SMEM>>>(pZh, pWoT, bo, out,
                                                         MTOT, HD, HD);
}